// round 1
// baseline (speedup 1.0000x reference)
#include <cuda_runtime.h>
#include <math.h>

#define TSEQ 2048
#define BB 8
#define DH 64
#define DM 1024
#define NTOK (BB*TSEQ)

// scratch (device globals -- no allocation allowed)
__device__ float g_q[NTOK*DH];
__device__ float g_k[NTOK*DH];
__device__ float g_v[NTOK*DH];
__device__ float g_att[NTOK*DH];

// ---------------- f32x2 packed math helpers ----------------
__device__ __forceinline__ unsigned long long pack2(float lo, float hi){
    unsigned long long r;
    asm("mov.b64 %0, {%1,%2};" : "=l"(r) : "f"(lo), "f"(hi));
    return r;
}
__device__ __forceinline__ void unpack2(unsigned long long v, float &lo, float &hi){
    asm("mov.b64 {%0,%1}, %2;" : "=f"(lo), "=f"(hi) : "l"(v));
}
__device__ __forceinline__ void fma2(unsigned long long &d, unsigned long long a, unsigned long long b){
    asm("fma.rn.f32x2 %0, %1, %2, %3;" : "=l"(d) : "l"(a), "l"(b), "l"(d));
}
__device__ __forceinline__ void cp_async4(void* sptr, const void* gptr){
    unsigned s = (unsigned)__cvta_generic_to_shared(sptr);
    asm volatile("cp.async.ca.shared.global [%0], [%1], 4;" :: "r"(s), "l"(gptr));
}

// ---------------- QKV projection: x @ [Wq|Wk|Wv], elu1 on q,k ----------------
// BM=64 rows, BN=192 (all cols), BK=16, 256 threads, f32x2 accumulators.
__global__ __launch_bounds__(256) void qkv_kernel(const float* __restrict__ x,
                                                  const float* __restrict__ Wq,
                                                  const float* __restrict__ Wk,
                                                  const float* __restrict__ Wv){
    __shared__ float As[64][16];   // [row][kk], broadcast reads (ty uniform per warp)
    __shared__ float Bs[16][192];  // [kk][col]
    const int tid = threadIdx.x;
    const int rb  = blockIdx.x * 64;
    const int ty  = tid >> 5;      // 0..7 -> 8 rows each
    const int tx  = tid & 31;      // 0..31 -> 6 cols each

    unsigned long long acc[8][3];
#pragma unroll
    for(int i=0;i<8;i++)
#pragma unroll
        for(int j=0;j<3;j++) acc[i][j] = 0ULL;

    const int arow = tid >> 2, agrp = tid & 3;

    for(int k0=0;k0<DM;k0+=16){
        // load A tile (64x16)
        float4 av = *(const float4*)(x + (size_t)(rb+arow)*DM + k0 + agrp*4);
        *(float4*)&As[arow][agrp*4] = av;
        // load B tile (16x192) from the three weight matrices
#pragma unroll
        for(int i=0;i<3;i++){
            int idx = tid + i*256;          // 0..767
            int bk  = idx / 48;
            int c4  = (idx % 48) * 4;       // col, multiple of 4, never crosses a 64-boundary
            const float* W = (c4 < 64) ? Wq : (c4 < 128 ? Wk : Wv);
            float4 bv = *(const float4*)(W + (size_t)(k0+bk)*DH + (c4 & 63));
            *(float4*)&Bs[bk][c4] = bv;
        }
        __syncthreads();
#pragma unroll
        for(int kk=0;kk<16;kk++){
            float ar[8];
#pragma unroll
            for(int i=0;i<8;i++) ar[i] = As[ty*8+i][kk];   // warp-uniform broadcast
            const unsigned long long* bp = (const unsigned long long*)&Bs[kk][tx*6];
            unsigned long long b0 = bp[0], b1 = bp[1], b2 = bp[2];
#pragma unroll
            for(int i=0;i<8;i++){
                unsigned long long ap = pack2(ar[i], ar[i]);
                fma2(acc[i][0], ap, b0);
                fma2(acc[i][1], ap, b1);
                fma2(acc[i][2], ap, b2);
            }
        }
        __syncthreads();
    }

#pragma unroll
    for(int i=0;i<8;i++){
        int row = rb + ty*8 + i;
#pragma unroll
        for(int j=0;j<3;j++){
            float lo, hi; unpack2(acc[i][j], lo, hi);
            float vals[2] = {lo, hi};
#pragma unroll
            for(int u=0;u<2;u++){
                int cc = tx*6 + j*2 + u;
                float v = vals[u];
                if(cc < 128) v = (v > 0.f) ? (v + 1.f) : expf(v);   // elu(x)+1
                float* dst = (cc < 64) ? g_q : (cc < 128 ? g_k : g_v);
                dst[(size_t)row*DH + (cc & 63)] = v;
            }
        }
    }
}

// ---------------- HSS scan ----------------
// Constants describing the HSS structure
__constant__ int c_bs [4] = {4, 8, 16, 32};
__constant__ int c_r  [4] = {4, 8, 8, 8};
__constant__ int c_nro[4] = {0, 32, 64, 80};   // (node,rank) flat offsets, total 88
__constant__ int c_wso[4] = {0, 128, 384, 512};// Ws flat offsets, total 576
__constant__ int c_noff[4]= {0, 8, 12, 14};    // node offsets, total 15
__constant__ int c_bso[4] = {0, 16, 80, 208};  // basis offsets (bs*r cumsum), total 464

__device__ __forceinline__ int lvl88(int idx){ return (idx<32)?0:(idx<64)?1:(idx<80)?2:3; }

struct BasePtrs { const float* p[16]; }; // UL0-3, VR0-3, UR0-3, VL0-3

__global__ __launch_bounds__(128) void scan_kernel(BasePtrs bp){
    __shared__ float sUL[464], sVR[464], sUR[464], sVL[464];
    __shared__ float s_leaf[256], s_Ws[576], s_z[64];
    __shared__ float s_kvq[2][3][64];       // [buf][k,v,q][d]
    __shared__ float s_proj[4][88];         // uL, vR, vrx, vlx
    __shared__ float s_tmpT[88], s_tmpB[88];
    __shared__ float s_cleaf[16], s_sT[15], s_sB[15], s_yleaf[64];
    __shared__ float s_dpart[2];
    __shared__ float s_denom;

    const int tid = threadIdx.x;
    const int b   = blockIdx.x;
    const float* gk = g_k + (size_t)b*TSEQ*DH;
    const float* gv = g_v + (size_t)b*TSEQ*DH;
    const float* gq = g_q + (size_t)b*TSEQ*DH;
    float* gatt     = g_att + (size_t)b*TSEQ*DH;

    // load bases, zero state
    for(int i=tid;i<464;i+=128){
        int l = (i<16)?0:(i<80)?1:(i<208)?2:3;
        int off = i - c_bso[l];
        sUL[i] = bp.p[l   ][off];
        sVR[i] = bp.p[4+l ][off];
        sUR[i] = bp.p[8+l ][off];
        sVL[i] = bp.p[12+l][off];
    }
    for(int i=tid;i<256;i+=128) s_leaf[i]=0.f;
    for(int i=tid;i<576;i+=128) s_Ws[i]=0.f;
    if(tid<64) s_z[tid]=0.f;
    if(tid<64){
        cp_async4(&s_kvq[0][0][tid], gk+tid);
        cp_async4(&s_kvq[0][1][tid], gv+tid);
        cp_async4(&s_kvq[0][2][tid], gq+tid);
    }
    asm volatile("cp.async.commit_group;\n");
    asm volatile("cp.async.wait_group 0;\n");
    __syncthreads();

    for(int t=0;t<TSEQ;t++){
        const int cb = t & 1, nb = cb ^ 1;
        if(t+1 < TSEQ && tid < 64){
            cp_async4(&s_kvq[nb][0][tid], gk + (size_t)(t+1)*DH + tid);
            cp_async4(&s_kvq[nb][1][tid], gv + (size_t)(t+1)*DH + tid);
            cp_async4(&s_kvq[nb][2][tid], gq + (size_t)(t+1)*DH + tid);
        }
        asm volatile("cp.async.commit_group;\n");
        const float* sk = s_kvq[cb][0];
        const float* sv = s_kvq[cb][1];
        const float* sq = s_kvq[cb][2];

        // ---- S1: projections, leaf scalars, old-leaf matvec, z/denom ----
        for(int j=tid;j<432;j+=128){
            if(j<352){
                int arr = j/88, idx = j - arr*88;
                int l = lvl88(idx);
                int r = c_r[l], bs = c_bs[l];
                int rem = idx - c_nro[l];
                int n = rem / r, rr = rem - n*r;
                int base = 2*bs*n + ((arr==1 || arr==2) ? bs : 0);
                const float* vec = (arr==0) ? sk : (arr==1) ? sv : sq;
                const float* bas = (arr==0) ? sUL : (arr==3) ? sVL : sVR;
                const float* bc  = bas + c_bso[l] + rr;
                float a0=0.f, a1=0.f;
                for(int d=0; d<bs; d+=2){
                    a0 = fmaf(vec[base+d],   bc[d*r],     a0);
                    a1 = fmaf(vec[base+d+1], bc[(d+1)*r], a1);
                }
                s_proj[arr][idx] = a0 + a1;
            } else if(j<368){
                int n = j - 352;
                float c = 0.f;
#pragma unroll
                for(int u=0;u<4;u++) c = fmaf(sv[4*n+u], sq[4*n+u], c);
                s_cleaf[n] = c;
            } else {
                int d = j - 368; int n = d >> 2;
                const float* lr = s_leaf + d*4;
                float y = 0.f;
#pragma unroll
                for(int u=0;u<4;u++) y = fmaf(lr[u], sq[4*n+u], y);
                s_yleaf[d] = y;
            }
        }
        if(tid<64){
            float zz = s_z[tid] + sk[tid];
            s_z[tid] = zz;
            float dp = zz * sq[tid];
#pragma unroll
            for(int o=16;o>0;o>>=1) dp += __shfl_xor_sync(0xffffffffu, dp, o);
            if((tid & 31) == 0) s_dpart[tid>>5] = dp;
        }
        __syncthreads();

        // ---- S2: node scalars, old-state Ws matvecs, denom ----
        if(tid==0) s_denom = fmaxf(s_dpart[0] + s_dpart[1], 1e-6f);
        for(int j=tid;j<206;j+=128){
            if(j<30){
                int which = (j<15) ? 0 : 1;
                int m = j - which*15;
                int l = (m<8)?0:(m<12)?1:(m<14)?2:3;
                int n = m - c_noff[l]; int r = c_r[l];
                int base = c_nro[l] + n*r;
                float s = 0.f;
                if(which==0){
                    for(int i=0;i<r;i++) s = fmaf(s_proj[1][base+i], s_proj[2][base+i], s);
                    s_sT[m] = s;   // vR . vrx
                } else {
                    for(int i=0;i<r;i++) s = fmaf(s_proj[0][base+i], s_proj[3][base+i], s);
                    s_sB[m] = s;   // uL . vlx
                }
            } else {
                int jj = j - 30;
                int half = (jj < 88) ? 0 : 1;
                int idx = jj - half*88;
                int l = lvl88(idx); int r = c_r[l];
                int rem = idx - c_nro[l];
                int n = rem / r, i = rem - n*r;
                int wbase = c_wso[l] + n*r*r;
                int pbase = c_nro[l] + n*r;
                float s = 0.f;
                if(half==0){
                    const float* wrow = s_Ws + wbase + i*r;
                    for(int u=0;u<r;u++) s = fmaf(wrow[u], s_proj[2][pbase+u], s);
                    s_tmpT[idx] = s;                 // Ws_old @ vrx
                } else {
                    const float* wcol = s_Ws + wbase + i;
                    for(int u=0;u<r;u++) s = fmaf(wcol[u*r], s_proj[3][pbase+u], s);
                    s_tmpB[idx] = s;                 // Ws_old^T @ vlx
                }
            }
        }
        __syncthreads();

        // ---- S3: assemble y (new-state via rank-1 corrections), update state ----
        if(tid<64){
            const int d = tid;
            float y = s_yleaf[d] + sk[d]*s_cleaf[d>>2];  // leaf_new @ q
#pragma unroll
            for(int l=0;l<4;l++){
                int bs = c_bs[l], r = c_r[l];
                int n = d / (2*bs);
                int loc = d - n*2*bs;
                int pbase = c_nro[l] + n*r;
                int m = c_noff[l] + n;
                if(loc < bs){
                    const float* u = sUL + c_bso[l] + loc*r;
                    float st = s_sT[m];
                    for(int i=0;i<r;i++)
                        y = fmaf(u[i], s_tmpT[pbase+i] + s_proj[0][pbase+i]*st, y);
                } else {
                    loc -= bs;
                    const float* u = sUR + c_bso[l] + loc*r;
                    float sb2 = s_sB[m];
                    for(int i=0;i<r;i++)
                        y = fmaf(u[i], s_tmpB[pbase+i] + s_proj[1][pbase+i]*sb2, y);
                }
            }
            gatt[(size_t)t*DH + d] = y / s_denom;
        }
        for(int m=tid;m<256;m+=128){
            int n = m>>4, i = (m>>2)&3, jx = m&3;
            s_leaf[m] = fmaf(sk[4*n+i], sv[4*n+jx], s_leaf[m]);
        }
        for(int m=tid;m<576;m+=128){
            int l = (m<128)?0:(m<384)?1:(m<512)?2:3;
            int rem = m - c_wso[l]; int r = c_r[l]; int rr2 = r*r;
            int n = rem / rr2; int ij = rem - n*rr2;
            int i = ij / r, jx = ij - i*r;
            int pbase = c_nro[l] + n*r;
            s_Ws[m] = fmaf(s_proj[0][pbase+i], s_proj[1][pbase+jx], s_Ws[m]);
        }
        asm volatile("cp.async.wait_group 0;\n");
        __syncthreads();
    }
}

// ---------------- output GEMM: att(16384x64) @ Wo(64x1024) ----------------
__global__ __launch_bounds__(256) void wo_kernel(const float* __restrict__ Wo,
                                                 float* __restrict__ out){
    __shared__ float As[64][64];   // [row][kk]
    __shared__ float Bs[64][64];   // [kk][col]
    const int tid = threadIdx.x;
    const int rb = blockIdx.x*64, cbk = blockIdx.y*64;
#pragma unroll
    for(int i=0;i<4;i++){
        int idx = tid + i*256;              // 0..1023
        int row = idx >> 4, g = idx & 15;
        float4 av = *(const float4*)(g_att + (size_t)(rb+row)*DH + g*4);
        *(float4*)&As[row][g*4] = av;
        float4 bv = *(const float4*)(Wo + (size_t)row*DM + cbk + g*4);
        *(float4*)&Bs[row][g*4] = bv;
    }
    __syncthreads();
    const int ty = tid >> 4, tx = tid & 15;     // 4 rows x 4 cols per thread
    unsigned long long acc[4][2];
#pragma unroll
    for(int i=0;i<4;i++){ acc[i][0]=0ULL; acc[i][1]=0ULL; }
    for(int kk=0;kk<64;kk++){
        float a0 = As[ty*4+0][kk];
        float a1 = As[ty*4+1][kk];
        float a2 = As[ty*4+2][kk];
        float a3 = As[ty*4+3][kk];
        const unsigned long long* bpp = (const unsigned long long*)&Bs[kk][tx*4];
        unsigned long long b0 = bpp[0], b1 = bpp[1];
        unsigned long long ap;
        ap = pack2(a0,a0); fma2(acc[0][0],ap,b0); fma2(acc[0][1],ap,b1);
        ap = pack2(a1,a1); fma2(acc[1][0],ap,b0); fma2(acc[1][1],ap,b1);
        ap = pack2(a2,a2); fma2(acc[2][0],ap,b0); fma2(acc[2][1],ap,b1);
        ap = pack2(a3,a3); fma2(acc[3][0],ap,b0); fma2(acc[3][1],ap,b1);
    }
#pragma unroll
    for(int i=0;i<4;i++){
        float4 ov;
        unpack2(acc[i][0], ov.x, ov.y);
        unpack2(acc[i][1], ov.z, ov.w);
        *(float4*)(out + (size_t)(rb+ty*4+i)*DM + cbk + tx*4) = ov;
    }
}

extern "C" void kernel_launch(void* const* d_in, const int* in_sizes, int n_in,
                              void* d_out, int out_size){
    (void)in_sizes; (void)n_in; (void)out_size;
    const float* x  = (const float*)d_in[0];
    const float* Wq = (const float*)d_in[1];
    const float* Wk = (const float*)d_in[2];
    const float* Wv = (const float*)d_in[3];
    const float* Wo = (const float*)d_in[4];
    BasePtrs bp;
    for(int i=0;i<16;i++) bp.p[i] = (const float*)d_in[5+i];
    float* out = (float*)d_out;

    qkv_kernel<<<NTOK/64, 256>>>(x, Wq, Wk, Wv);
    scan_kernel<<<BB, 128>>>(bp);
    wo_kernel<<<dim3(NTOK/64, DM/64), 256>>>(Wo, out);
}

// round 2
// speedup vs baseline: 27.1905x; 27.1905x over previous
#include <cuda_runtime.h>
#include <math.h>

#define TSEQ 2048
#define BB 8
#define DH 64
#define DM 1024
#define NTOK (BB*TSEQ)
#define CCH 64
#define NCH (TSEQ/CCH)   /* 32 */
#define NST 896          /* leaf 256 + Ws 576 + z 64 */

// scratch (device globals -- no allocation allowed)
__device__ float g_q[NTOK*DH];
__device__ float g_k[NTOK*DH];
__device__ float g_v[NTOK*DH];
__device__ float g_att[NTOK*DH];
__device__ float g_state[BB*NCH*NST];
__device__ float g_prefix[BB*NCH*NST];

struct BasePtrs { const float* p[16]; }; // UL0-3, VR0-3, UR0-3, VL0-3

// ---------------- f32x2 packed math helpers ----------------
__device__ __forceinline__ unsigned long long pack2(float lo, float hi){
    unsigned long long r;
    asm("mov.b64 %0, {%1,%2};" : "=l"(r) : "f"(lo), "f"(hi));
    return r;
}
__device__ __forceinline__ void unpack2(unsigned long long v, float &lo, float &hi){
    asm("mov.b64 {%0,%1}, %2;" : "=f"(lo), "=f"(hi) : "l"(v));
}
__device__ __forceinline__ void fma2(unsigned long long &d, unsigned long long a, unsigned long long b){
    asm("fma.rn.f32x2 %0, %1, %2, %3;" : "=l"(d) : "l"(a), "l"(b), "l"(d));
}

__device__ __forceinline__ float dot4v(float4 a, float4 b){
    return fmaf(a.x,b.x, fmaf(a.y,b.y, fmaf(a.z,b.z, a.w*b.w)));
}

// level constant helpers (pure ALU, no memory)
__device__ __forceinline__ int Knro(int l){ return (l==0)?0:(l==1)?32:(l==2)?64:80; }
__device__ __forceinline__ int Kwso(int l){ return (l==0)?0:(l==1)?128:(l==2)?384:512; }
__device__ __forceinline__ int Kbso(int l){ return (l==0)?0:(l==1)?16:(l==2)?80:208; }
__device__ __forceinline__ int Knoff(int l){ return (l==0)?0:(l==1)?8:(l==2)?12:14; }

// ---------------- QKV projection: x @ [Wq|Wk|Wv], elu1 on q,k ----------------
__global__ __launch_bounds__(256) void qkv_kernel(const float* __restrict__ x,
                                                  const float* __restrict__ Wq,
                                                  const float* __restrict__ Wk,
                                                  const float* __restrict__ Wv){
    __shared__ float As[64][16];
    __shared__ float Bs[16][192];
    const int tid = threadIdx.x;
    const int rb  = blockIdx.x * 64;
    const int ty  = tid >> 5;
    const int tx  = tid & 31;

    unsigned long long acc[8][3];
#pragma unroll
    for(int i=0;i<8;i++)
#pragma unroll
        for(int j=0;j<3;j++) acc[i][j] = 0ULL;

    const int arow = tid >> 2, agrp = tid & 3;

    for(int k0=0;k0<DM;k0+=16){
        float4 av = *(const float4*)(x + (size_t)(rb+arow)*DM + k0 + agrp*4);
        *(float4*)&As[arow][agrp*4] = av;
#pragma unroll
        for(int i=0;i<3;i++){
            int idx = tid + i*256;
            int bk  = idx / 48;
            int c4  = (idx % 48) * 4;
            const float* W = (c4 < 64) ? Wq : (c4 < 128 ? Wk : Wv);
            float4 bv = *(const float4*)(W + (size_t)(k0+bk)*DH + (c4 & 63));
            *(float4*)&Bs[bk][c4] = bv;
        }
        __syncthreads();
#pragma unroll
        for(int kk=0;kk<16;kk++){
            float ar[8];
#pragma unroll
            for(int i=0;i<8;i++) ar[i] = As[ty*8+i][kk];
            const unsigned long long* bp = (const unsigned long long*)&Bs[kk][tx*6];
            unsigned long long b0 = bp[0], b1 = bp[1], b2 = bp[2];
#pragma unroll
            for(int i=0;i<8;i++){
                unsigned long long ap = pack2(ar[i], ar[i]);
                fma2(acc[i][0], ap, b0);
                fma2(acc[i][1], ap, b1);
                fma2(acc[i][2], ap, b2);
            }
        }
        __syncthreads();
    }

#pragma unroll
    for(int i=0;i<8;i++){
        int row = rb + ty*8 + i;
#pragma unroll
        for(int j=0;j<3;j++){
            float lo, hi; unpack2(acc[i][j], lo, hi);
            float vals[2] = {lo, hi};
#pragma unroll
            for(int u=0;u<2;u++){
                int cc = tx*6 + j*2 + u;
                float v = vals[u];
                if(cc < 128) v = (v > 0.f) ? (v + 1.f) : expf(v);
                float* dst = (cc < 64) ? g_q : (cc < 128 ? g_k : g_v);
                dst[(size_t)row*DH + (cc & 63)] = v;
            }
        }
    }
}

// =====================================================================
// shared LUT builders
// =====================================================================
__device__ __forceinline__ void build_node_lut(int* s_nd, int tid){
    if (tid < 15){
        int l = (tid<8)?0:(tid<12)?1:(tid<14)?2:3;
        int n = tid - Knoff(l);
        int bs = 4<<l, r = (l==0)?4:8;
        s_nd[tid*5+0]=bs; s_nd[tid*5+1]=r; s_nd[tid*5+2]=Knro(l)+n*r;
        s_nd[tid*5+3]=2*bs*n; s_nd[tid*5+4]=Kbso(l);
    }
}
__device__ __forceinline__ void build_ws_lut(int* s_lutAB, int* s_lutT, int tid, int nthr){
    for (int m = tid; m < 576; m += nthr){
        int l = (m<128)?0:(m<384)?1:(m<512)?2:3;
        int r = (l==0)?4:8;
        int rem = m - Kwso(l);
        int rr2 = r*r;
        int n = rem / rr2;
        int ij = rem - n*rr2;
        int i = ij / r, j = ij - i*r;
        int pb = Knro(l) + n*r;
        s_lutAB[m] = (pb+i) | ((pb+j)<<16);
        if (s_lutT) s_lutT[m] = Kwso(l) + n*rr2 + j*r + i;
    }
}

#define FMA4A(acc, sc, v4) do{ (acc)[0]=fmaf((sc),(v4).x,(acc)[0]); (acc)[1]=fmaf((sc),(v4).y,(acc)[1]); \
                               (acc)[2]=fmaf((sc),(v4).z,(acc)[2]); (acc)[3]=fmaf((sc),(v4).w,(acc)[3]); }while(0)

// =====================================================================
// Pass 1: per-chunk state sums (fully parallel)
// smem floats: k 4096 + v 4096 + prjUL 5632 + prjVR 5632 + sUL 464 + sVR 464
// =====================================================================
#define SMEM_P1 ((4096*2 + 5632*2 + 464*2)*4 + (80+576)*4)
__global__ __launch_bounds__(256) void chunk_sum_kernel(BasePtrs bp){
    extern __shared__ float sm[];
    float* s_k   = sm;
    float* s_v   = s_k + 4096;
    float* prjUL = s_v + 4096;
    float* prjVR = prjUL + 5632;
    float* sUL   = prjVR + 5632;
    float* sVR   = sUL + 464;
    int*   s_nd    = (int*)(sVR + 464);
    int*   s_lutAB = s_nd + 80;

    const int tid = threadIdx.x;
    const int blk = blockIdx.x;
    const int b = blk / NCH, c = blk % NCH;
    const float* gk = g_k + ((size_t)b*TSEQ + c*CCH)*DH;
    const float* gv = g_v + ((size_t)b*TSEQ + c*CCH)*DH;

    for (int i=tid;i<464;i+=256){
        int l = (i<16)?0:(i<80)?1:(i<208)?2:3;
        int off = i - Kbso(l);
        sUL[i] = bp.p[l][off];
        sVR[i] = bp.p[4+l][off];
    }
    for (int i=tid;i<1024;i+=256){
        ((float4*)s_k)[i] = ((const float4*)gk)[i];
        ((float4*)s_v)[i] = ((const float4*)gv)[i];
    }
    build_node_lut(s_nd, tid);
    build_ws_lut(s_lutAB, 0, tid, 256);
    __syncthreads();

    // projections uL (k top), vR (v bottom) for all s
    for (int j=tid; j<CCH*15; j+=256){
        int s = j/15, m = j - s*15;
        int bs = s_nd[m*5+0], r = s_nd[m*5+1], pb = s_nd[m*5+2];
        int topo = s_nd[m*5+3], bso = s_nd[m*5+4];
        const float* kt = s_k + s*64 + topo;
        const float* vb = s_v + s*64 + topo + bs;
        float aU[8], aV[8];
#pragma unroll
        for (int i=0;i<8;i++){ aU[i]=0.f; aV[i]=0.f; }
        if (r == 4){
            for (int d=0; d<bs; d++){
                float kd = kt[d], vd = vb[d];
                float4 u = *(const float4*)(sUL + bso + d*4);
                float4 w = *(const float4*)(sVR + bso + d*4);
                FMA4A(aU, kd, u);
                FMA4A(aV, vd, w);
            }
        } else {
            for (int d=0; d<bs; d++){
                float kd = kt[d], vd = vb[d];
                const float* U = sUL + bso + d*8;
                const float* W = sVR + bso + d*8;
                float4 u0 = *(const float4*)U, u1 = *(const float4*)(U+4);
                float4 w0 = *(const float4*)W, w1 = *(const float4*)(W+4);
                FMA4A(aU, kd, u0); FMA4A(aU+4, kd, u1);
                FMA4A(aV, vd, w0); FMA4A(aV+4, vd, w1);
            }
        }
        int o = s*88 + pb;
#pragma unroll
        for (int i=0;i<4;i++){ prjUL[o+i]=aU[i]; prjVR[o+i]=aV[i]; }
        if (r==8){
#pragma unroll
            for (int i=4;i<8;i++){ prjUL[o+i]=aU[i]; prjVR[o+i]=aV[i]; }
        }
    }
    __syncthreads();

    float* go = g_state + (size_t)blk*NST;
    for (int e=tid; e<NST; e+=256){
        float acc = 0.f;
        if (e < 256){
            int n=e>>4, i=(e>>2)&3, j2=e&3;
            int ki=4*n+i, vi=4*n+j2;
#pragma unroll 8
            for (int s=0;s<CCH;s++) acc = fmaf(s_k[s*64+ki], s_v[s*64+vi], acc);
        } else if (e < 832){
            int m = e-256;
            int ab = s_lutAB[m]; int a = ab & 0xffff, b3 = ab >> 16;
#pragma unroll 8
            for (int s=0;s<CCH;s++) acc = fmaf(prjUL[s*88+a], prjVR[s*88+b3], acc);
        } else {
            int d = e-832;
#pragma unroll 8
            for (int s=0;s<CCH;s++) acc += s_k[s*64+d];
        }
        go[e] = acc;
    }
}

// =====================================================================
// Pass 2: exclusive prefix over chunks (per batch)
// =====================================================================
__global__ __launch_bounds__(128) void prefix_kernel(){
    const int b = blockIdx.x, tid = threadIdx.x;
    for (int e=tid; e<NST; e+=128){
        float run = 0.f;
        for (int c=0;c<NCH;c++){
            size_t o = ((size_t)(b*NCH+c))*NST + e;
            float v2 = g_state[o];
            g_prefix[o] = run;
            run += v2;
        }
    }
}

// =====================================================================
// Pass 3: per-chunk sequential scan with precomputed projections
// =====================================================================
#define P3_FLOATS (4096*3 + 5632*4 + 464*4 + 256 + 576 + 576 + 64 + 88 + 88 + 16 + 16 + 16 + 64 + 4)
#define SMEM_P3 (P3_FLOATS*4 + (80+576+576)*4)
__global__ __launch_bounds__(256) void chunk_scan_kernel(BasePtrs bp){
    extern __shared__ float sm[];
    float* s_k   = sm;
    float* s_v   = s_k + 4096;
    float* s_q   = s_v + 4096;
    float* prjUL = s_q + 4096;
    float* prjVR = prjUL + 5632;
    float* prjX  = prjVR + 5632;   // vrx = VR^T q_bot
    float* prjL  = prjX  + 5632;   // vlx = VL^T q_top
    float* sUL   = prjL + 5632;
    float* sVR   = sUL + 464;
    float* sUR   = sVR + 464;
    float* sVL   = sUR + 464;
    float* s_leaf = sVL + 464;     // 256
    float* s_Ws   = s_leaf + 256;  // 576
    float* s_WsT  = s_Ws + 576;    // 576
    float* s_z    = s_WsT + 576;   // 64
    float* s_tmpT = s_z + 64;      // 88
    float* s_tmpB = s_tmpT + 88;   // 88
    float* s_sT   = s_tmpB + 88;   // 16
    float* s_sB   = s_sT + 16;     // 16
    float* s_cleaf= s_sB + 16;     // 16
    float* s_yleaf= s_cleaf + 16;  // 64
    float* s_dp   = s_yleaf + 64;  // 4
    int*   s_nd    = (int*)(s_dp + 4);
    int*   s_lutAB = s_nd + 80;
    int*   s_lutT  = s_lutAB + 576;

    const int tid = threadIdx.x;
    const int blk = blockIdx.x;
    const int b = blk / NCH, c = blk % NCH;
    const float* gk = g_k + ((size_t)b*TSEQ + c*CCH)*DH;
    const float* gv = g_v + ((size_t)b*TSEQ + c*CCH)*DH;
    const float* gq = g_q + ((size_t)b*TSEQ + c*CCH)*DH;
    float* g_o      = g_att + ((size_t)b*TSEQ + c*CCH)*DH;

    // --- one-time loads ---
    for (int i=tid;i<464;i+=256){
        int l = (i<16)?0:(i<80)?1:(i<208)?2:3;
        int off = i - Kbso(l);
        sUL[i] = bp.p[l   ][off];
        sVR[i] = bp.p[4+l ][off];
        sUR[i] = bp.p[8+l ][off];
        sVL[i] = bp.p[12+l][off];
    }
    for (int i=tid;i<1024;i+=256){
        ((float4*)s_k)[i] = ((const float4*)gk)[i];
        ((float4*)s_v)[i] = ((const float4*)gv)[i];
        ((float4*)s_q)[i] = ((const float4*)gq)[i];
    }
    build_node_lut(s_nd, tid);
    build_ws_lut(s_lutAB, s_lutT, tid, 256);
    {
        const float* gp = g_prefix + (size_t)blk*NST;
        for (int e=tid;e<NST;e+=256){
            float vle = gp[e];
            if (e<256) s_leaf[e]=vle;
            else if (e<832) s_Ws[e-256]=vle;
            else s_z[e-832]=vle;
        }
    }
    __syncthreads();

    // transposed Ws copy
    for (int m=tid;m<576;m+=256) s_WsT[m] = s_Ws[s_lutT[m]];

    // --- projections for every token in the chunk ---
    for (int j=tid; j<CCH*15; j+=256){
        int s = j/15, m = j - s*15;
        int bs = s_nd[m*5+0], r = s_nd[m*5+1], pb = s_nd[m*5+2];
        int topo = s_nd[m*5+3], bso = s_nd[m*5+4];
        const float* kt = s_k + s*64 + topo;
        const float* vb = s_v + s*64 + topo + bs;
        const float* qt = s_q + s*64 + topo;
        const float* qb = qt + bs;
        float aU[8], aV[8], aX[8], aL[8];
#pragma unroll
        for (int i=0;i<8;i++){ aU[i]=aV[i]=aX[i]=aL[i]=0.f; }
        if (r == 4){
            for (int d=0; d<bs; d++){
                float kd=kt[d], vd=vb[d], qbd=qb[d], qtd=qt[d];
                float4 u = *(const float4*)(sUL + bso + d*4);
                float4 w = *(const float4*)(sVR + bso + d*4);
                float4 x = *(const float4*)(sVL + bso + d*4);
                FMA4A(aU, kd, u);
                FMA4A(aV, vd, w);
                FMA4A(aX, qbd, w);
                FMA4A(aL, qtd, x);
            }
        } else {
            for (int d=0; d<bs; d++){
                float kd=kt[d], vd=vb[d], qbd=qb[d], qtd=qt[d];
                const float* U = sUL + bso + d*8;
                const float* W = sVR + bso + d*8;
                const float* X = sVL + bso + d*8;
                float4 u0=*(const float4*)U, u1=*(const float4*)(U+4);
                float4 w0=*(const float4*)W, w1=*(const float4*)(W+4);
                float4 x0=*(const float4*)X, x1=*(const float4*)(X+4);
                FMA4A(aU, kd, u0);  FMA4A(aU+4, kd, u1);
                FMA4A(aV, vd, w0);  FMA4A(aV+4, vd, w1);
                FMA4A(aX, qbd, w0); FMA4A(aX+4, qbd, w1);
                FMA4A(aL, qtd, x0); FMA4A(aL+4, qtd, x1);
            }
        }
        int o = s*88 + pb;
#pragma unroll
        for (int i=0;i<4;i++){ prjUL[o+i]=aU[i]; prjVR[o+i]=aV[i]; prjX[o+i]=aX[i]; prjL[o+i]=aL[i]; }
        if (r==8){
#pragma unroll
            for (int i=4;i<8;i++){ prjUL[o+i]=aU[i]; prjVR[o+i]=aV[i]; prjX[o+i]=aX[i]; prjL[o+i]=aL[i]; }
        }
    }
    __syncthreads();

    // --- per-thread descriptors (hoisted index math) ---
    int dT_wrow=0, dT_pb=0;
    if (tid < 88){
        int idx = tid;
        int l = (idx<32)?0:(idx<64)?1:(idx<80)?2:3;
        int r = (l==0)?4:8;
        int rem = idx - Knro(l);
        int n = rem / r, i = rem - n*r;
        dT_wrow = Kwso(l) + n*r*r + i*r;
        dT_pb   = Knro(l) + n*r;
    }
    int dB_wrow=0, dB_pb=0;
    if (tid >= 96 && tid < 184){
        int idx = tid - 96;
        int l = (idx<32)?0:(idx<64)?1:(idx<80)?2:3;
        int r = (l==0)?4:8;
        int rem = idx - Knro(l);
        int n = rem / r, i = rem - n*r;
        dB_wrow = Kwso(l) + n*r*r + i*r;
        dB_pb   = Knro(l) + n*r;
    }
    int sn_pb=0, sn_r=0;
    if (tid < 15){ sn_pb = s_nd[tid*5+2]; sn_r = s_nd[tid*5+1]; }
    int sb_pb=0, sb_r=0;
    if (tid >= 16 && tid < 31){ int m=tid-16; sb_pb = s_nd[m*5+2]; sb_r = s_nd[m*5+1]; }

    // phase-B state descriptors
    int le0=0, lk0=0, lv0=0, lk1=0, lv1=0;
    if (tid >= 64 && tid < 192){
        le0 = (tid-64)*2;
        int e = le0;
        lk0 = ((e>>4)<<2)|((e>>2)&3); lv0 = ((e>>4)<<2)|(e&3);
        e++;
        lk1 = ((e>>4)<<2)|((e>>2)&3); lv1 = ((e>>4)<<2)|(e&3);
    }
    int wm0=0; int wAB[6];
    float* wsTarget = s_Ws;
    if (tid >= 64){
        int e0 = (tid-64)*6;
        bool wT = (e0 >= 576);
        wm0 = wT ? (e0-576) : e0;
        wsTarget = wT ? s_WsT : s_Ws;
#pragma unroll
        for (int q2=0;q2<6;q2++){
            int ab = s_lutAB[wm0+q2];
            int a = ab & 0xffff, b3 = ab >> 16;
            wAB[q2] = wT ? (b3 | (a<<16)) : ab;
        }
    }

    // ===================== main sequential loop =====================
    for (int t=0; t<CCH; t++){
        const int s88 = t*88, s64 = t*64;

        // ---- phase A: old-state matvecs + per-token scalars ----
        if (tid < 88){
            const float* w = s_Ws + dT_wrow;
            const float* x = prjX + s88 + dT_pb;
            float4 w0 = *(const float4*)w, x0 = *(const float4*)x;
            float acc = dot4v(w0, x0);
            if (tid >= 32){
                float4 w1 = *(const float4*)(w+4), x1 = *(const float4*)(x+4);
                acc += dot4v(w1, x1);
            }
            s_tmpT[tid] = acc;
        }
        if (tid >= 96 && tid < 184){
            int idx = tid - 96;
            const float* w = s_WsT + dB_wrow;
            const float* x = prjL + s88 + dB_pb;
            float4 w0 = *(const float4*)w, x0 = *(const float4*)x;
            float acc = dot4v(w0, x0);
            if (idx >= 32){
                float4 w1 = *(const float4*)(w+4), x1 = *(const float4*)(x+4);
                acc += dot4v(w1, x1);
            }
            s_tmpB[idx] = acc;
        }
        if (tid < 15){
            const float* a2 = prjVR + s88 + sn_pb;
            const float* b2 = prjX  + s88 + sn_pb;
            float acc = dot4v(*(const float4*)a2, *(const float4*)b2);
            if (sn_r == 8) acc += dot4v(*(const float4*)(a2+4), *(const float4*)(b2+4));
            s_sT[tid] = acc;
        }
        if (tid >= 16 && tid < 31){
            const float* a2 = prjUL + s88 + sb_pb;
            const float* b2 = prjL  + s88 + sb_pb;
            float acc = dot4v(*(const float4*)a2, *(const float4*)b2);
            if (sb_r == 8) acc += dot4v(*(const float4*)(a2+4), *(const float4*)(b2+4));
            s_sB[tid-16] = acc;
        }
        if (tid >= 32 && tid < 48){
            int n = tid - 32;
            s_cleaf[n] = dot4v(*(const float4*)(s_v + s64 + 4*n),
                               *(const float4*)(s_q + s64 + 4*n));
        }
        if (tid >= 192){
            int d2 = tid - 192;
            float4 lr = *(const float4*)(s_leaf + 4*d2);
            float4 qr = *(const float4*)(s_q + s64 + (d2 & ~3));
            s_yleaf[d2] = dot4v(lr, qr);
            float p = (s_z[d2] + s_k[s64+d2]) * s_q[s64+d2];
#pragma unroll
            for (int o=16;o>0;o>>=1) p += __shfl_xor_sync(0xffffffffu, p, o);
            if ((tid & 31) == 0) s_dp[(tid>>5)-6] = p;
        }
        __syncthreads();

        // ---- phase B: assemble y, update state ----
        if (tid < 64){
            const int d2 = tid;
            float denom = fmaxf(s_dp[0] + s_dp[1], 1e-6f);
            float y = s_yleaf[d2] + s_k[s64+d2]*s_cleaf[d2>>2];
#pragma unroll
            for (int l=0;l<4;l++){
                const int bs = 4<<l;
                const int r  = (l==0)?4:8;
                const int nro = Knro(l), noff = Knoff(l), bso = Kbso(l);
                const int n = d2 >> (3+l);
                const int loc = d2 & (2*bs - 1);
                const int pb = nro + n*r;
                const int m = noff + n;
                if (loc < bs){
                    const float* u  = sUL + bso + loc*r;
                    const float st  = s_sT[m];
                    const float* tb = s_tmpT + pb;
                    const float* pr = prjUL + s88 + pb;
                    float4 u0=*(const float4*)u, t0=*(const float4*)tb, p0=*(const float4*)pr;
                    y = fmaf(u0.x, fmaf(p0.x,st,t0.x), y);
                    y = fmaf(u0.y, fmaf(p0.y,st,t0.y), y);
                    y = fmaf(u0.z, fmaf(p0.z,st,t0.z), y);
                    y = fmaf(u0.w, fmaf(p0.w,st,t0.w), y);
                    if (r == 8){
                        float4 u1=*(const float4*)(u+4), t1=*(const float4*)(tb+4), p1=*(const float4*)(pr+4);
                        y = fmaf(u1.x, fmaf(p1.x,st,t1.x), y);
                        y = fmaf(u1.y, fmaf(p1.y,st,t1.y), y);
                        y = fmaf(u1.z, fmaf(p1.z,st,t1.z), y);
                        y = fmaf(u1.w, fmaf(p1.w,st,t1.w), y);
                    }
                } else {
                    const float* u  = sUR + bso + (loc-bs)*r;
                    const float sb3 = s_sB[m];
                    const float* tb = s_tmpB + pb;
                    const float* pr = prjVR + s88 + pb;
                    float4 u0=*(const float4*)u, t0=*(const float4*)tb, p0=*(const float4*)pr;
                    y = fmaf(u0.x, fmaf(p0.x,sb3,t0.x), y);
                    y = fmaf(u0.y, fmaf(p0.y,sb3,t0.y), y);
                    y = fmaf(u0.z, fmaf(p0.z,sb3,t0.z), y);
                    y = fmaf(u0.w, fmaf(p0.w,sb3,t0.w), y);
                    if (r == 8){
                        float4 u1=*(const float4*)(u+4), t1=*(const float4*)(tb+4), p1=*(const float4*)(pr+4);
                        y = fmaf(u1.x, fmaf(p1.x,sb3,t1.x), y);
                        y = fmaf(u1.y, fmaf(p1.y,sb3,t1.y), y);
                        y = fmaf(u1.z, fmaf(p1.z,sb3,t1.z), y);
                        y = fmaf(u1.w, fmaf(p1.w,sb3,t1.w), y);
                    }
                }
            }
            g_o[(size_t)t*DH + d2] = y / denom;
        } else {
            if (tid < 192){
                s_leaf[le0]   = fmaf(s_k[s64+lk0], s_v[s64+lv0], s_leaf[le0]);
                s_leaf[le0+1] = fmaf(s_k[s64+lk1], s_v[s64+lv1], s_leaf[le0+1]);
            }
            const float* pu = prjUL + s88;
            const float* pv = prjVR + s88;
#pragma unroll
            for (int q2=0;q2<6;q2++){
                int ab = wAB[q2];
                int a = ab & 0xffff, b3 = ab >> 16;
                wsTarget[wm0+q2] = fmaf(pu[a], pv[b3], wsTarget[wm0+q2]);
            }
            if (tid >= 192){
                int d2 = tid - 192;
                s_z[d2] += s_k[s64+d2];
            }
        }
        __syncthreads();
    }
}

// ---------------- output GEMM: att(16384x64) @ Wo(64x1024) ----------------
__global__ __launch_bounds__(256) void wo_kernel(const float* __restrict__ Wo,
                                                 float* __restrict__ out){
    __shared__ float As[64][64];
    __shared__ float Bs[64][64];
    const int tid = threadIdx.x;
    const int rb = blockIdx.x*64, cbk = blockIdx.y*64;
#pragma unroll
    for(int i=0;i<4;i++){
        int idx = tid + i*256;
        int row = idx >> 4, g = idx & 15;
        float4 av = *(const float4*)(g_att + (size_t)(rb+row)*DH + g*4);
        *(float4*)&As[row][g*4] = av;
        float4 bv = *(const float4*)(Wo + (size_t)row*DM + cbk + g*4);
        *(float4*)&Bs[row][g*4] = bv;
    }
    __syncthreads();
    const int ty = tid >> 4, tx = tid & 15;
    unsigned long long acc[4][2];
#pragma unroll
    for(int i=0;i<4;i++){ acc[i][0]=0ULL; acc[i][1]=0ULL; }
    for(int kk=0;kk<64;kk++){
        float a0 = As[ty*4+0][kk];
        float a1 = As[ty*4+1][kk];
        float a2 = As[ty*4+2][kk];
        float a3 = As[ty*4+3][kk];
        const unsigned long long* bpp = (const unsigned long long*)&Bs[kk][tx*4];
        unsigned long long b0 = bpp[0], b1 = bpp[1];
        unsigned long long ap;
        ap = pack2(a0,a0); fma2(acc[0][0],ap,b0); fma2(acc[0][1],ap,b1);
        ap = pack2(a1,a1); fma2(acc[1][0],ap,b0); fma2(acc[1][1],ap,b1);
        ap = pack2(a2,a2); fma2(acc[2][0],ap,b0); fma2(acc[2][1],ap,b1);
        ap = pack2(a3,a3); fma2(acc[3][0],ap,b0); fma2(acc[3][1],ap,b1);
    }
#pragma unroll
    for(int i=0;i<4;i++){
        float4 ov;
        unpack2(acc[i][0], ov.x, ov.y);
        unpack2(acc[i][1], ov.z, ov.w);
        *(float4*)(out + (size_t)(rb+ty*4+i)*DM + cbk + tx*4) = ov;
    }
}

extern "C" void kernel_launch(void* const* d_in, const int* in_sizes, int n_in,
                              void* d_out, int out_size){
    (void)in_sizes; (void)n_in; (void)out_size;
    const float* x  = (const float*)d_in[0];
    const float* Wq = (const float*)d_in[1];
    const float* Wk = (const float*)d_in[2];
    const float* Wv = (const float*)d_in[3];
    const float* Wo = (const float*)d_in[4];
    BasePtrs bp;
    for(int i=0;i<16;i++) bp.p[i] = (const float*)d_in[5+i];
    float* out = (float*)d_out;

    cudaFuncSetAttribute(chunk_sum_kernel,  cudaFuncAttributeMaxDynamicSharedMemorySize, SMEM_P1);
    cudaFuncSetAttribute(chunk_scan_kernel, cudaFuncAttributeMaxDynamicSharedMemorySize, SMEM_P3);

    qkv_kernel<<<NTOK/64, 256>>>(x, Wq, Wk, Wv);
    chunk_sum_kernel<<<BB*NCH, 256, SMEM_P1>>>(bp);
    prefix_kernel<<<BB, 128>>>();
    chunk_scan_kernel<<<BB*NCH, 256, SMEM_P3>>>(bp);
    wo_kernel<<<dim3(NTOK/64, DM/64), 256>>>(Wo, out);
}

// round 3
// speedup vs baseline: 33.8173x; 1.2437x over previous
#include <cuda_runtime.h>
#include <math.h>

#define TSEQ 2048
#define BB 8
#define DH 64
#define DM 1024
#define NTOK (BB*TSEQ)
#define CCH 16
#define NCH (TSEQ/CCH)   /* 128 */
#define NST 896          /* leaf 256 + Ws 576 + z 64 */
#define KV4 (CCH*DH/4)   /* float4 per chunk tensor */

// scratch (device globals -- no allocation allowed)
__device__ float g_q[NTOK*DH];
__device__ float g_k[NTOK*DH];
__device__ float g_v[NTOK*DH];
__device__ float g_att[NTOK*DH];
__device__ float g_state[BB*NCH*NST];
__device__ float g_prefix[BB*NCH*NST];

struct BasePtrs { const float* p[16]; }; // UL0-3, VR0-3, UR0-3, VL0-3

// ---------------- f32x2 packed math helpers ----------------
__device__ __forceinline__ unsigned long long pack2(float lo, float hi){
    unsigned long long r;
    asm("mov.b64 %0, {%1,%2};" : "=l"(r) : "f"(lo), "f"(hi));
    return r;
}
__device__ __forceinline__ void unpack2(unsigned long long v, float &lo, float &hi){
    asm("mov.b64 {%0,%1}, %2;" : "=f"(lo), "=f"(hi) : "l"(v));
}
__device__ __forceinline__ void fma2(unsigned long long &d, unsigned long long a, unsigned long long b){
    asm("fma.rn.f32x2 %0, %1, %2, %3;" : "=l"(d) : "l"(a), "l"(b), "l"(d));
}
__device__ __forceinline__ void cp_async16(void* sptr, const void* gptr){
    unsigned s = (unsigned)__cvta_generic_to_shared(sptr);
    asm volatile("cp.async.ca.shared.global [%0], [%1], 16;" :: "r"(s), "l"(gptr));
}

__device__ __forceinline__ float dot4v(float4 a, float4 b){
    return fmaf(a.x,b.x, fmaf(a.y,b.y, fmaf(a.z,b.z, a.w*b.w)));
}

// level constant helpers (pure ALU, no memory)
__device__ __forceinline__ int Knro(int l){ return (l==0)?0:(l==1)?32:(l==2)?64:80; }
__device__ __forceinline__ int Kwso(int l){ return (l==0)?0:(l==1)?128:(l==2)?384:512; }
__device__ __forceinline__ int Kbso(int l){ return (l==0)?0:(l==1)?16:(l==2)?80:208; }
__device__ __forceinline__ int Knoff(int l){ return (l==0)?0:(l==1)?8:(l==2)?12:14; }

// ---------------- QKV projection: x @ [Wq|Wk|Wv], elu1 on q,k ----------------
// BM=64, BN=192, BK=16, 256 threads, double-buffered (cp.async B, reg-prefetch A),
// A stored pre-duplicated as float2 so f32x2 FMAs need no splat movs.
__global__ __launch_bounds__(256) void qkv_kernel(const float* __restrict__ x,
                                                  const float* __restrict__ Wq,
                                                  const float* __restrict__ Wk,
                                                  const float* __restrict__ Wv){
    __shared__ float2 As2[2][64][16];
    __shared__ float  Bs [2][16][192];
    const int tid = threadIdx.x;
    const int rb  = blockIdx.x * 64;
    const int ty  = tid >> 5;
    const int tx  = tid & 31;
    const int arow = tid >> 2, agrp = tid & 3;

    unsigned long long acc[8][3];
#pragma unroll
    for(int i=0;i<8;i++)
#pragma unroll
        for(int j=0;j<3;j++) acc[i][j] = 0ULL;

    // B-load descriptors (3 float4 per thread)
    int bk_[3], c4_[3]; const float* wsrc[3];
#pragma unroll
    for(int i=0;i<3;i++){
        int idx = tid + i*256;
        bk_[i] = idx / 48;
        int c4 = (idx % 48) * 4;
        c4_[i] = c4;
        wsrc[i] = (c4 < 64) ? Wq : (c4 < 128 ? Wk : Wv);
    }

    // preload tile 0
    float4 av = *(const float4*)(x + (size_t)(rb+arow)*DM + agrp*4);
#pragma unroll
    for(int i=0;i<3;i++)
        cp_async16(&Bs[0][bk_[i]][c4_[i]], wsrc[i] + (size_t)bk_[i]*DH + (c4_[i] & 63));
    asm volatile("cp.async.commit_group;\n");
    {
        float2* d = &As2[0][arow][agrp*4];
        d[0] = make_float2(av.x, av.x);
        d[1] = make_float2(av.y, av.y);
        d[2] = make_float2(av.z, av.z);
        d[3] = make_float2(av.w, av.w);
    }
    asm volatile("cp.async.wait_group 0;\n");
    __syncthreads();

    for(int kt=0; kt<64; kt++){
        const int buf = kt & 1;
        if (kt < 63){
            int k0 = (kt+1)*16;
            av = *(const float4*)(x + (size_t)(rb+arow)*DM + k0 + agrp*4);
#pragma unroll
            for(int i=0;i<3;i++)
                cp_async16(&Bs[buf^1][bk_[i]][c4_[i]], wsrc[i] + (size_t)(k0+bk_[i])*DH + (c4_[i] & 63));
            asm volatile("cp.async.commit_group;\n");
        }
#pragma unroll
        for(int kk=0;kk<16;kk++){
            unsigned long long a2[8];
#pragma unroll
            for(int i=0;i<8;i++) a2[i] = *(const unsigned long long*)&As2[buf][ty*8+i][kk];
            const unsigned long long* bp = (const unsigned long long*)&Bs[buf][kk][tx*6];
            unsigned long long b0 = bp[0], b1 = bp[1], b2 = bp[2];
#pragma unroll
            for(int i=0;i<8;i++){
                fma2(acc[i][0], a2[i], b0);
                fma2(acc[i][1], a2[i], b1);
                fma2(acc[i][2], a2[i], b2);
            }
        }
        __syncthreads();
        if (kt < 63){
            float2* d = &As2[buf^1][arow][agrp*4];
            d[0] = make_float2(av.x, av.x);
            d[1] = make_float2(av.y, av.y);
            d[2] = make_float2(av.z, av.z);
            d[3] = make_float2(av.w, av.w);
            asm volatile("cp.async.wait_group 0;\n");
            __syncthreads();
        }
    }

#pragma unroll
    for(int i=0;i<8;i++){
        int row = rb + ty*8 + i;
#pragma unroll
        for(int j=0;j<3;j++){
            float lo, hi; unpack2(acc[i][j], lo, hi);
            float vals[2] = {lo, hi};
#pragma unroll
            for(int u=0;u<2;u++){
                int cc = tx*6 + j*2 + u;
                float v = vals[u];
                if(cc < 128) v = (v > 0.f) ? (v + 1.f) : expf(v);
                float* dst = (cc < 64) ? g_q : (cc < 128 ? g_k : g_v);
                dst[(size_t)row*DH + (cc & 63)] = v;
            }
        }
    }
}

// =====================================================================
// shared LUT builders
// =====================================================================
__device__ __forceinline__ void build_node_lut(int* s_nd, int tid){
    if (tid < 15){
        int l = (tid<8)?0:(tid<12)?1:(tid<14)?2:3;
        int n = tid - Knoff(l);
        int bs = 4<<l, r = (l==0)?4:8;
        s_nd[tid*5+0]=bs; s_nd[tid*5+1]=r; s_nd[tid*5+2]=Knro(l)+n*r;
        s_nd[tid*5+3]=2*bs*n; s_nd[tid*5+4]=Kbso(l);
    }
}
__device__ __forceinline__ void build_ws_lut(int* s_lutAB, int* s_lutT, int tid, int nthr){
    for (int m = tid; m < 576; m += nthr){
        int l = (m<128)?0:(m<384)?1:(m<512)?2:3;
        int r = (l==0)?4:8;
        int rem = m - Kwso(l);
        int rr2 = r*r;
        int n = rem / rr2;
        int ij = rem - n*rr2;
        int i = ij / r, j = ij - i*r;
        int pb = Knro(l) + n*r;
        s_lutAB[m] = (pb+i) | ((pb+j)<<16);
        if (s_lutT) s_lutT[m] = Kwso(l) + n*rr2 + j*r + i;
    }
}

#define FMA4A(acc, sc, v4) do{ (acc)[0]=fmaf((sc),(v4).x,(acc)[0]); (acc)[1]=fmaf((sc),(v4).y,(acc)[1]); \
                               (acc)[2]=fmaf((sc),(v4).z,(acc)[2]); (acc)[3]=fmaf((sc),(v4).w,(acc)[3]); }while(0)

// =====================================================================
// Pass 1: per-chunk state sums (fully parallel)
// =====================================================================
#define SMEM_P1 ((CCH*64*2 + CCH*88*2 + 464*2)*4 + (80+576)*4)
__global__ __launch_bounds__(256) void chunk_sum_kernel(BasePtrs bp){
    extern __shared__ float sm[];
    float* s_k   = sm;
    float* s_v   = s_k + CCH*64;
    float* prjUL = s_v + CCH*64;
    float* prjVR = prjUL + CCH*88;
    float* sUL   = prjVR + CCH*88;
    float* sVR   = sUL + 464;
    int*   s_nd    = (int*)(sVR + 464);
    int*   s_lutAB = s_nd + 80;

    const int tid = threadIdx.x;
    const int blk = blockIdx.x;
    const int b = blk / NCH, c = blk % NCH;
    const float* gk = g_k + ((size_t)b*TSEQ + c*CCH)*DH;
    const float* gv = g_v + ((size_t)b*TSEQ + c*CCH)*DH;

    for (int i=tid;i<464;i+=256){
        int l = (i<16)?0:(i<80)?1:(i<208)?2:3;
        int off = i - Kbso(l);
        sUL[i] = bp.p[l][off];
        sVR[i] = bp.p[4+l][off];
    }
    for (int i=tid;i<KV4;i+=256){
        ((float4*)s_k)[i] = ((const float4*)gk)[i];
        ((float4*)s_v)[i] = ((const float4*)gv)[i];
    }
    build_node_lut(s_nd, tid);
    build_ws_lut(s_lutAB, 0, tid, 256);
    __syncthreads();

    // projections uL (k top), vR (v bottom) for all s
    for (int j=tid; j<CCH*15; j+=256){
        int s = j/15, m = j - s*15;
        int bs = s_nd[m*5+0], r = s_nd[m*5+1], pb = s_nd[m*5+2];
        int topo = s_nd[m*5+3], bso = s_nd[m*5+4];
        const float* kt = s_k + s*64 + topo;
        const float* vb = s_v + s*64 + topo + bs;
        float aU[8], aV[8];
#pragma unroll
        for (int i=0;i<8;i++){ aU[i]=0.f; aV[i]=0.f; }
        if (r == 4){
            for (int d=0; d<bs; d++){
                float kd = kt[d], vd = vb[d];
                float4 u = *(const float4*)(sUL + bso + d*4);
                float4 w = *(const float4*)(sVR + bso + d*4);
                FMA4A(aU, kd, u);
                FMA4A(aV, vd, w);
            }
        } else {
            for (int d=0; d<bs; d++){
                float kd = kt[d], vd = vb[d];
                const float* U = sUL + bso + d*8;
                const float* W = sVR + bso + d*8;
                float4 u0 = *(const float4*)U, u1 = *(const float4*)(U+4);
                float4 w0 = *(const float4*)W, w1 = *(const float4*)(W+4);
                FMA4A(aU, kd, u0); FMA4A(aU+4, kd, u1);
                FMA4A(aV, vd, w0); FMA4A(aV+4, vd, w1);
            }
        }
        int o = s*88 + pb;
#pragma unroll
        for (int i=0;i<4;i++){ prjUL[o+i]=aU[i]; prjVR[o+i]=aV[i]; }
        if (r==8){
#pragma unroll
            for (int i=4;i<8;i++){ prjUL[o+i]=aU[i]; prjVR[o+i]=aV[i]; }
        }
    }
    __syncthreads();

    float* go = g_state + (size_t)blk*NST;
    for (int e=tid; e<NST; e+=256){
        float acc = 0.f;
        if (e < 256){
            int n=e>>4, i=(e>>2)&3, j2=e&3;
            int ki=4*n+i, vi=4*n+j2;
#pragma unroll
            for (int s=0;s<CCH;s++) acc = fmaf(s_k[s*64+ki], s_v[s*64+vi], acc);
        } else if (e < 832){
            int m = e-256;
            int ab = s_lutAB[m]; int a = ab & 0xffff, b3 = ab >> 16;
#pragma unroll
            for (int s=0;s<CCH;s++) acc = fmaf(prjUL[s*88+a], prjVR[s*88+b3], acc);
        } else {
            int d = e-832;
#pragma unroll
            for (int s=0;s<CCH;s++) acc += s_k[s*64+d];
        }
        go[e] = acc;
    }
}

// =====================================================================
// Pass 2: exclusive prefix over chunks (per batch, element-parallel, MLP=8)
// grid (NST/128=7, BB), 128 threads
// =====================================================================
__global__ __launch_bounds__(128) void prefix_kernel(){
    const int b = blockIdx.y;
    const int e = blockIdx.x*128 + threadIdx.x;
    const float* gs = g_state  + (size_t)b*NCH*NST + e;
    float*       gp = g_prefix + (size_t)b*NCH*NST + e;
    float run = 0.f;
    for (int c0=0;c0<NCH;c0+=8){
        float v[8];
#pragma unroll
        for (int j=0;j<8;j++) v[j] = gs[(size_t)(c0+j)*NST];
#pragma unroll
        for (int j=0;j<8;j++){ gp[(size_t)(c0+j)*NST] = run; run += v[j]; }
    }
}

// =====================================================================
// Pass 3: per-chunk sequential scan with precomputed projections
// =====================================================================
#define P3_FLOATS (CCH*64*3 + CCH*88*4 + 464*4 + 256 + 576 + 576 + 64 + 88 + 88 + 16 + 16 + 16 + 64 + 4)
#define SMEM_P3 (P3_FLOATS*4 + (80+576+576)*4)
__global__ __launch_bounds__(256) void chunk_scan_kernel(BasePtrs bp){
    extern __shared__ float sm[];
    float* s_k   = sm;
    float* s_v   = s_k + CCH*64;
    float* s_q   = s_v + CCH*64;
    float* prjUL = s_q + CCH*64;
    float* prjVR = prjUL + CCH*88;
    float* prjX  = prjVR + CCH*88;   // vrx = VR^T q_bot
    float* prjL  = prjX  + CCH*88;   // vlx = VL^T q_top
    float* sUL   = prjL + CCH*88;
    float* sVR   = sUL + 464;
    float* sUR   = sVR + 464;
    float* sVL   = sUR + 464;
    float* s_leaf = sVL + 464;     // 256
    float* s_Ws   = s_leaf + 256;  // 576
    float* s_WsT  = s_Ws + 576;    // 576
    float* s_z    = s_WsT + 576;   // 64
    float* s_tmpT = s_z + 64;      // 88
    float* s_tmpB = s_tmpT + 88;   // 88
    float* s_sT   = s_tmpB + 88;   // 16
    float* s_sB   = s_sT + 16;     // 16
    float* s_cleaf= s_sB + 16;     // 16
    float* s_yleaf= s_cleaf + 16;  // 64
    float* s_dp   = s_yleaf + 64;  // 4
    int*   s_nd    = (int*)(s_dp + 4);
    int*   s_lutAB = s_nd + 80;
    int*   s_lutT  = s_lutAB + 576;

    const int tid = threadIdx.x;
    const int blk = blockIdx.x;
    const int b = blk / NCH, c = blk % NCH;
    const float* gk = g_k + ((size_t)b*TSEQ + c*CCH)*DH;
    const float* gv = g_v + ((size_t)b*TSEQ + c*CCH)*DH;
    const float* gq = g_q + ((size_t)b*TSEQ + c*CCH)*DH;
    float* g_o      = g_att + ((size_t)b*TSEQ + c*CCH)*DH;

    // --- one-time loads ---
    for (int i=tid;i<464;i+=256){
        int l = (i<16)?0:(i<80)?1:(i<208)?2:3;
        int off = i - Kbso(l);
        sUL[i] = bp.p[l   ][off];
        sVR[i] = bp.p[4+l ][off];
        sUR[i] = bp.p[8+l ][off];
        sVL[i] = bp.p[12+l][off];
    }
    for (int i=tid;i<KV4;i+=256){
        ((float4*)s_k)[i] = ((const float4*)gk)[i];
        ((float4*)s_v)[i] = ((const float4*)gv)[i];
        ((float4*)s_q)[i] = ((const float4*)gq)[i];
    }
    build_node_lut(s_nd, tid);
    build_ws_lut(s_lutAB, s_lutT, tid, 256);
    {
        const float* gp = g_prefix + (size_t)blk*NST;
        for (int e=tid;e<NST;e+=256){
            float vle = gp[e];
            if (e<256) s_leaf[e]=vle;
            else if (e<832) s_Ws[e-256]=vle;
            else s_z[e-832]=vle;
        }
    }
    __syncthreads();

    // transposed Ws copy
    for (int m=tid;m<576;m+=256) s_WsT[m] = s_Ws[s_lutT[m]];

    // --- projections for every token in the chunk ---
    for (int j=tid; j<CCH*15; j+=256){
        int s = j/15, m = j - s*15;
        int bs = s_nd[m*5+0], r = s_nd[m*5+1], pb = s_nd[m*5+2];
        int topo = s_nd[m*5+3], bso = s_nd[m*5+4];
        const float* kt = s_k + s*64 + topo;
        const float* vb = s_v + s*64 + topo + bs;
        const float* qt = s_q + s*64 + topo;
        const float* qb = qt + bs;
        float aU[8], aV[8], aX[8], aL[8];
#pragma unroll
        for (int i=0;i<8;i++){ aU[i]=aV[i]=aX[i]=aL[i]=0.f; }
        if (r == 4){
            for (int d=0; d<bs; d++){
                float kd=kt[d], vd=vb[d], qbd=qb[d], qtd=qt[d];
                float4 u = *(const float4*)(sUL + bso + d*4);
                float4 w = *(const float4*)(sVR + bso + d*4);
                float4 x = *(const float4*)(sVL + bso + d*4);
                FMA4A(aU, kd, u);
                FMA4A(aV, vd, w);
                FMA4A(aX, qbd, w);
                FMA4A(aL, qtd, x);
            }
        } else {
            for (int d=0; d<bs; d++){
                float kd=kt[d], vd=vb[d], qbd=qb[d], qtd=qt[d];
                const float* U = sUL + bso + d*8;
                const float* W = sVR + bso + d*8;
                const float* X = sVL + bso + d*8;
                float4 u0=*(const float4*)U, u1=*(const float4*)(U+4);
                float4 w0=*(const float4*)W, w1=*(const float4*)(W+4);
                float4 x0=*(const float4*)X, x1=*(const float4*)(X+4);
                FMA4A(aU, kd, u0);  FMA4A(aU+4, kd, u1);
                FMA4A(aV, vd, w0);  FMA4A(aV+4, vd, w1);
                FMA4A(aX, qbd, w0); FMA4A(aX+4, qbd, w1);
                FMA4A(aL, qtd, x0); FMA4A(aL+4, qtd, x1);
            }
        }
        int o = s*88 + pb;
#pragma unroll
        for (int i=0;i<4;i++){ prjUL[o+i]=aU[i]; prjVR[o+i]=aV[i]; prjX[o+i]=aX[i]; prjL[o+i]=aL[i]; }
        if (r==8){
#pragma unroll
            for (int i=4;i<8;i++){ prjUL[o+i]=aU[i]; prjVR[o+i]=aV[i]; prjX[o+i]=aX[i]; prjL[o+i]=aL[i]; }
        }
    }
    __syncthreads();

    // --- per-thread descriptors (hoisted index math) ---
    int dT_wrow=0, dT_pb=0;
    if (tid < 88){
        int idx = tid;
        int l = (idx<32)?0:(idx<64)?1:(idx<80)?2:3;
        int r = (l==0)?4:8;
        int rem = idx - Knro(l);
        int n = rem / r, i = rem - n*r;
        dT_wrow = Kwso(l) + n*r*r + i*r;
        dT_pb   = Knro(l) + n*r;
    }
    int dB_wrow=0, dB_pb=0;
    if (tid >= 96 && tid < 184){
        int idx = tid - 96;
        int l = (idx<32)?0:(idx<64)?1:(idx<80)?2:3;
        int r = (l==0)?4:8;
        int rem = idx - Knro(l);
        int n = rem / r, i = rem - n*r;
        dB_wrow = Kwso(l) + n*r*r + i*r;
        dB_pb   = Knro(l) + n*r;
    }
    int sn_pb=0, sn_r=0;
    if (tid < 15){ sn_pb = s_nd[tid*5+2]; sn_r = s_nd[tid*5+1]; }
    int sb_pb=0, sb_r=0;
    if (tid >= 16 && tid < 31){ int m=tid-16; sb_pb = s_nd[m*5+2]; sb_r = s_nd[m*5+1]; }

    // phase-B state descriptors
    int le0=0, lk0=0, lv0=0, lk1=0, lv1=0;
    if (tid >= 64 && tid < 192){
        le0 = (tid-64)*2;
        int e = le0;
        lk0 = ((e>>4)<<2)|((e>>2)&3); lv0 = ((e>>4)<<2)|(e&3);
        e++;
        lk1 = ((e>>4)<<2)|((e>>2)&3); lv1 = ((e>>4)<<2)|(e&3);
    }
    int wm0=0; int wAB[6];
    float* wsTarget = s_Ws;
    if (tid >= 64){
        int e0 = (tid-64)*6;
        bool wT = (e0 >= 576);
        wm0 = wT ? (e0-576) : e0;
        wsTarget = wT ? s_WsT : s_Ws;
#pragma unroll
        for (int q2=0;q2<6;q2++){
            int ab = s_lutAB[wm0+q2];
            int a = ab & 0xffff, b3 = ab >> 16;
            wAB[q2] = wT ? (b3 | (a<<16)) : ab;
        }
    }

    // ===================== main sequential loop =====================
    for (int t=0; t<CCH; t++){
        const int s88 = t*88, s64 = t*64;

        // ---- phase A: old-state matvecs + per-token scalars ----
        if (tid < 88){
            const float* w = s_Ws + dT_wrow;
            const float* x = prjX + s88 + dT_pb;
            float4 w0 = *(const float4*)w, x0 = *(const float4*)x;
            float acc = dot4v(w0, x0);
            if (tid >= 32){
                float4 w1 = *(const float4*)(w+4), x1 = *(const float4*)(x+4);
                acc += dot4v(w1, x1);
            }
            s_tmpT[tid] = acc;
        }
        if (tid >= 96 && tid < 184){
            int idx = tid - 96;
            const float* w = s_WsT + dB_wrow;
            const float* x = prjL + s88 + dB_pb;
            float4 w0 = *(const float4*)w, x0 = *(const float4*)x;
            float acc = dot4v(w0, x0);
            if (idx >= 32){
                float4 w1 = *(const float4*)(w+4), x1 = *(const float4*)(x+4);
                acc += dot4v(w1, x1);
            }
            s_tmpB[idx] = acc;
        }
        if (tid < 15){
            const float* a2 = prjVR + s88 + sn_pb;
            const float* b2 = prjX  + s88 + sn_pb;
            float acc = dot4v(*(const float4*)a2, *(const float4*)b2);
            if (sn_r == 8) acc += dot4v(*(const float4*)(a2+4), *(const float4*)(b2+4));
            s_sT[tid] = acc;
        }
        if (tid >= 16 && tid < 31){
            const float* a2 = prjUL + s88 + sb_pb;
            const float* b2 = prjL  + s88 + sb_pb;
            float acc = dot4v(*(const float4*)a2, *(const float4*)b2);
            if (sb_r == 8) acc += dot4v(*(const float4*)(a2+4), *(const float4*)(b2+4));
            s_sB[tid-16] = acc;
        }
        if (tid >= 32 && tid < 48){
            int n = tid - 32;
            s_cleaf[n] = dot4v(*(const float4*)(s_v + s64 + 4*n),
                               *(const float4*)(s_q + s64 + 4*n));
        }
        if (tid >= 192){
            int d2 = tid - 192;
            float4 lr = *(const float4*)(s_leaf + 4*d2);
            float4 qr = *(const float4*)(s_q + s64 + (d2 & ~3));
            s_yleaf[d2] = dot4v(lr, qr);
            float p = (s_z[d2] + s_k[s64+d2]) * s_q[s64+d2];
#pragma unroll
            for (int o=16;o>0;o>>=1) p += __shfl_xor_sync(0xffffffffu, p, o);
            if ((tid & 31) == 0) s_dp[(tid>>5)-6] = p;
        }
        __syncthreads();

        // ---- phase B: assemble y, update state ----
        if (tid < 64){
            const int d2 = tid;
            float denom = fmaxf(s_dp[0] + s_dp[1], 1e-6f);
            float y = s_yleaf[d2] + s_k[s64+d2]*s_cleaf[d2>>2];
#pragma unroll
            for (int l=0;l<4;l++){
                const int bs = 4<<l;
                const int r  = (l==0)?4:8;
                const int nro = Knro(l), noff = Knoff(l), bso = Kbso(l);
                const int n = d2 >> (3+l);
                const int loc = d2 & (2*bs - 1);
                const int pb = nro + n*r;
                const int m = noff + n;
                if (loc < bs){
                    const float* u  = sUL + bso + loc*r;
                    const float st  = s_sT[m];
                    const float* tb = s_tmpT + pb;
                    const float* pr = prjUL + s88 + pb;
                    float4 u0=*(const float4*)u, t0=*(const float4*)tb, p0=*(const float4*)pr;
                    y = fmaf(u0.x, fmaf(p0.x,st,t0.x), y);
                    y = fmaf(u0.y, fmaf(p0.y,st,t0.y), y);
                    y = fmaf(u0.z, fmaf(p0.z,st,t0.z), y);
                    y = fmaf(u0.w, fmaf(p0.w,st,t0.w), y);
                    if (r == 8){
                        float4 u1=*(const float4*)(u+4), t1=*(const float4*)(tb+4), p1=*(const float4*)(pr+4);
                        y = fmaf(u1.x, fmaf(p1.x,st,t1.x), y);
                        y = fmaf(u1.y, fmaf(p1.y,st,t1.y), y);
                        y = fmaf(u1.z, fmaf(p1.z,st,t1.z), y);
                        y = fmaf(u1.w, fmaf(p1.w,st,t1.w), y);
                    }
                } else {
                    const float* u  = sUR + bso + (loc-bs)*r;
                    const float sb3 = s_sB[m];
                    const float* tb = s_tmpB + pb;
                    const float* pr = prjVR + s88 + pb;
                    float4 u0=*(const float4*)u, t0=*(const float4*)tb, p0=*(const float4*)pr;
                    y = fmaf(u0.x, fmaf(p0.x,sb3,t0.x), y);
                    y = fmaf(u0.y, fmaf(p0.y,sb3,t0.y), y);
                    y = fmaf(u0.z, fmaf(p0.z,sb3,t0.z), y);
                    y = fmaf(u0.w, fmaf(p0.w,sb3,t0.w), y);
                    if (r == 8){
                        float4 u1=*(const float4*)(u+4), t1=*(const float4*)(tb+4), p1=*(const float4*)(pr+4);
                        y = fmaf(u1.x, fmaf(p1.x,sb3,t1.x), y);
                        y = fmaf(u1.y, fmaf(p1.y,sb3,t1.y), y);
                        y = fmaf(u1.z, fmaf(p1.z,sb3,t1.z), y);
                        y = fmaf(u1.w, fmaf(p1.w,sb3,t1.w), y);
                    }
                }
            }
            g_o[(size_t)t*DH + d2] = y / denom;
        } else {
            if (tid < 192){
                s_leaf[le0]   = fmaf(s_k[s64+lk0], s_v[s64+lv0], s_leaf[le0]);
                s_leaf[le0+1] = fmaf(s_k[s64+lk1], s_v[s64+lv1], s_leaf[le0+1]);
            }
            const float* pu = prjUL + s88;
            const float* pv = prjVR + s88;
#pragma unroll
            for (int q2=0;q2<6;q2++){
                int ab = wAB[q2];
                int a = ab & 0xffff, b3 = ab >> 16;
                wsTarget[wm0+q2] = fmaf(pu[a], pv[b3], wsTarget[wm0+q2]);
            }
            if (tid >= 192){
                int d2 = tid - 192;
                s_z[d2] += s_k[s64+d2];
            }
        }
        __syncthreads();
    }
}

// ---------------- output GEMM: att(16384x64) @ Wo(64x1024) ----------------
// block = 64 rows x 256 cols (A tile loaded once, 4 B sub-tiles)
__global__ __launch_bounds__(256) void wo_kernel(const float* __restrict__ Wo,
                                                 float* __restrict__ out){
    __shared__ float As[64][64];
    __shared__ float Bs[64][64];
    const int tid = threadIdx.x;
    const int rb = blockIdx.x*64, cbase = blockIdx.y*256;
#pragma unroll
    for(int i=0;i<4;i++){
        int idx = tid + i*256;
        int row = idx >> 4, g = idx & 15;
        float4 av = *(const float4*)(g_att + (size_t)(rb+row)*DH + g*4);
        *(float4*)&As[row][g*4] = av;
    }
    const int ty = tid >> 4, tx = tid & 15;
    for(int sub=0; sub<4; sub++){
        const int cbk = cbase + sub*64;
        __syncthreads();   // As ready (first iter) / previous Bs reads done
#pragma unroll
        for(int i=0;i<4;i++){
            int idx = tid + i*256;
            int row = idx >> 4, g = idx & 15;
            float4 bv = *(const float4*)(Wo + (size_t)row*DM + cbk + g*4);
            *(float4*)&Bs[row][g*4] = bv;
        }
        __syncthreads();
        unsigned long long acc[4][2];
#pragma unroll
        for(int i=0;i<4;i++){ acc[i][0]=0ULL; acc[i][1]=0ULL; }
        for(int kk=0;kk<64;kk++){
            float a0 = As[ty*4+0][kk];
            float a1 = As[ty*4+1][kk];
            float a2 = As[ty*4+2][kk];
            float a3 = As[ty*4+3][kk];
            const unsigned long long* bpp = (const unsigned long long*)&Bs[kk][tx*4];
            unsigned long long b0 = bpp[0], b1 = bpp[1];
            unsigned long long ap;
            ap = pack2(a0,a0); fma2(acc[0][0],ap,b0); fma2(acc[0][1],ap,b1);
            ap = pack2(a1,a1); fma2(acc[1][0],ap,b0); fma2(acc[1][1],ap,b1);
            ap = pack2(a2,a2); fma2(acc[2][0],ap,b0); fma2(acc[2][1],ap,b1);
            ap = pack2(a3,a3); fma2(acc[3][0],ap,b0); fma2(acc[3][1],ap,b1);
        }
#pragma unroll
        for(int i=0;i<4;i++){
            float4 ov;
            unpack2(acc[i][0], ov.x, ov.y);
            unpack2(acc[i][1], ov.z, ov.w);
            *(float4*)(out + (size_t)(rb+ty*4+i)*DM + cbk + tx*4) = ov;
        }
    }
}

extern "C" void kernel_launch(void* const* d_in, const int* in_sizes, int n_in,
                              void* d_out, int out_size){
    (void)in_sizes; (void)n_in; (void)out_size;
    const float* x  = (const float*)d_in[0];
    const float* Wq = (const float*)d_in[1];
    const float* Wk = (const float*)d_in[2];
    const float* Wv = (const float*)d_in[3];
    const float* Wo = (const float*)d_in[4];
    BasePtrs bp;
    for(int i=0;i<16;i++) bp.p[i] = (const float*)d_in[5+i];
    float* out = (float*)d_out;

    cudaFuncSetAttribute(chunk_sum_kernel,  cudaFuncAttributeMaxDynamicSharedMemorySize, SMEM_P1);
    cudaFuncSetAttribute(chunk_scan_kernel, cudaFuncAttributeMaxDynamicSharedMemorySize, SMEM_P3);

    qkv_kernel<<<NTOK/64, 256>>>(x, Wq, Wk, Wv);
    chunk_sum_kernel<<<BB*NCH, 256, SMEM_P1>>>(bp);
    prefix_kernel<<<dim3(NST/128, BB), 128>>>();
    chunk_scan_kernel<<<BB*NCH, 256, SMEM_P3>>>(bp);
    wo_kernel<<<dim3(NTOK/64, DM/256), 256>>>(Wo, out);
}

// round 4
// speedup vs baseline: 34.0261x; 1.0062x over previous
#include <cuda_runtime.h>
#include <math.h>

#define TSEQ 2048
#define BB 8
#define DH 64
#define DM 1024
#define NTOK (BB*TSEQ)
#define CCH 16
#define NCH (TSEQ/CCH)   /* 128 */
#define NST 896          /* leaf 256 + Ws 576 + z 64 */
#define KPAD 68          /* padded row stride for k/v/q in smem */

// scratch (device globals -- no allocation allowed)
__device__ float g_q[NTOK*DH];
__device__ float g_k[NTOK*DH];
__device__ float g_v[NTOK*DH];
__device__ float g_att[NTOK*DH];
__device__ float g_state[BB*NCH*NST];
__device__ float g_prefix[BB*NCH*NST];

struct BasePtrs { const float* p[16]; }; // UL0-3, VR0-3, UR0-3, VL0-3

// ---------------- f32x2 packed math helpers ----------------
__device__ __forceinline__ unsigned long long pack2(float lo, float hi){
    unsigned long long r;
    asm("mov.b64 %0, {%1,%2};" : "=l"(r) : "f"(lo), "f"(hi));
    return r;
}
__device__ __forceinline__ void unpack2(unsigned long long v, float &lo, float &hi){
    asm("mov.b64 {%0,%1}, %2;" : "=f"(lo), "=f"(hi) : "l"(v));
}
__device__ __forceinline__ void fma2(unsigned long long &d, unsigned long long a, unsigned long long b){
    asm("fma.rn.f32x2 %0, %1, %2, %3;" : "=l"(d) : "l"(a), "l"(b), "l"(d));
}
__device__ __forceinline__ void cp_async16(void* sptr, const void* gptr){
    unsigned s = (unsigned)__cvta_generic_to_shared(sptr);
    asm volatile("cp.async.ca.shared.global [%0], [%1], 16;" :: "r"(s), "l"(gptr));
}

__device__ __forceinline__ float dot4v(float4 a, float4 b){
    return fmaf(a.x,b.x, fmaf(a.y,b.y, fmaf(a.z,b.z, a.w*b.w)));
}
__device__ __forceinline__ void fma4(float4 &acc, float s, float4 v){
    acc.x = fmaf(s, v.x, acc.x); acc.y = fmaf(s, v.y, acc.y);
    acc.z = fmaf(s, v.z, acc.z); acc.w = fmaf(s, v.w, acc.w);
}

// level constant helpers (pure ALU, no memory)
__device__ __forceinline__ int Knro(int l){ return (l==0)?0:(l==1)?32:(l==2)?64:80; }
__device__ __forceinline__ int Kwso(int l){ return (l==0)?0:(l==1)?128:(l==2)?384:512; }
__device__ __forceinline__ int Kbso(int l){ return (l==0)?0:(l==1)?16:(l==2)?80:208; }
__device__ __forceinline__ int Knoff(int l){ return (l==0)?0:(l==1)?8:(l==2)?12:14; }

// ---------------- QKV projection: x @ [Wq|Wk|Wv], elu1 on q,k ----------------
__global__ __launch_bounds__(256) void qkv_kernel(const float* __restrict__ x,
                                                  const float* __restrict__ Wq,
                                                  const float* __restrict__ Wk,
                                                  const float* __restrict__ Wv){
    __shared__ float2 As2[2][64][16];
    __shared__ float  Bs [2][16][192];
    const int tid = threadIdx.x;
    const int rb  = blockIdx.x * 64;
    const int ty  = tid >> 5;
    const int tx  = tid & 31;
    const int arow = tid >> 2, agrp = tid & 3;

    unsigned long long acc[8][3];
#pragma unroll
    for(int i=0;i<8;i++)
#pragma unroll
        for(int j=0;j<3;j++) acc[i][j] = 0ULL;

    int bk_[3], c4_[3]; const float* wsrc[3];
#pragma unroll
    for(int i=0;i<3;i++){
        int idx = tid + i*256;
        bk_[i] = idx / 48;
        int c4 = (idx % 48) * 4;
        c4_[i] = c4;
        wsrc[i] = (c4 < 64) ? Wq : (c4 < 128 ? Wk : Wv);
    }

    float4 av = *(const float4*)(x + (size_t)(rb+arow)*DM + agrp*4);
#pragma unroll
    for(int i=0;i<3;i++)
        cp_async16(&Bs[0][bk_[i]][c4_[i]], wsrc[i] + (size_t)bk_[i]*DH + (c4_[i] & 63));
    asm volatile("cp.async.commit_group;\n");
    {
        float2* d = &As2[0][arow][agrp*4];
        d[0] = make_float2(av.x, av.x);
        d[1] = make_float2(av.y, av.y);
        d[2] = make_float2(av.z, av.z);
        d[3] = make_float2(av.w, av.w);
    }
    asm volatile("cp.async.wait_group 0;\n");
    __syncthreads();

    for(int kt=0; kt<64; kt++){
        const int buf = kt & 1;
        if (kt < 63){
            int k0 = (kt+1)*16;
            av = *(const float4*)(x + (size_t)(rb+arow)*DM + k0 + agrp*4);
#pragma unroll
            for(int i=0;i<3;i++)
                cp_async16(&Bs[buf^1][bk_[i]][c4_[i]], wsrc[i] + (size_t)(k0+bk_[i])*DH + (c4_[i] & 63));
            asm volatile("cp.async.commit_group;\n");
        }
#pragma unroll
        for(int kk=0;kk<16;kk++){
            unsigned long long a2[8];
#pragma unroll
            for(int i=0;i<8;i++) a2[i] = *(const unsigned long long*)&As2[buf][ty*8+i][kk];
            const unsigned long long* bp = (const unsigned long long*)&Bs[buf][kk][tx*6];
            unsigned long long b0 = bp[0], b1 = bp[1], b2 = bp[2];
#pragma unroll
            for(int i=0;i<8;i++){
                fma2(acc[i][0], a2[i], b0);
                fma2(acc[i][1], a2[i], b1);
                fma2(acc[i][2], a2[i], b2);
            }
        }
        __syncthreads();
        if (kt < 63){
            float2* d = &As2[buf^1][arow][agrp*4];
            d[0] = make_float2(av.x, av.x);
            d[1] = make_float2(av.y, av.y);
            d[2] = make_float2(av.z, av.z);
            d[3] = make_float2(av.w, av.w);
            asm volatile("cp.async.wait_group 0;\n");
            __syncthreads();
        }
    }

#pragma unroll
    for(int i=0;i<8;i++){
        int row = rb + ty*8 + i;
#pragma unroll
        for(int j=0;j<3;j++){
            float lo, hi; unpack2(acc[i][j], lo, hi);
            float vals[2] = {lo, hi};
#pragma unroll
            for(int u=0;u<2;u++){
                int cc = tx*6 + j*2 + u;
                float v = vals[u];
                if(cc < 128) v = (v > 0.f) ? (v + 1.f) : expf(v);
                float* dst = (cc < 64) ? g_q : (cc < 128 ? g_k : g_v);
                dst[(size_t)row*DH + (cc & 63)] = v;
            }
        }
    }
}

// =====================================================================
// shared LUT builders
// =====================================================================
__device__ __forceinline__ void build_node_lut(int* s_nd, int tid){
    if (tid < 15){
        int l = (tid<8)?0:(tid<12)?1:(tid<14)?2:3;
        int n = tid - Knoff(l);
        int bs = 4<<l, r = (l==0)?4:8;
        s_nd[tid*5+0]=bs; s_nd[tid*5+1]=r; s_nd[tid*5+2]=Knro(l)+n*r;
        s_nd[tid*5+3]=2*bs*n; s_nd[tid*5+4]=Kbso(l);
    }
}
__device__ __forceinline__ void build_ws_lut(int* s_lutAB, int tid, int nthr){
    for (int m = tid; m < 576; m += nthr){
        int l = (m<128)?0:(m<384)?1:(m<512)?2:3;
        int r = (l==0)?4:8;
        int rem = m - Kwso(l);
        int rr2 = r*r;
        int n = rem / rr2;
        int ij = rem - n*rr2;
        int i = ij / r, j = ij - i*r;
        int pb = Knro(l) + n*r;
        s_lutAB[m] = (pb+i) | ((pb+j)<<16);
    }
}

// projection phase job (m = node 0..14, s = token): computes transposed projections
// prjT layout: [88 rows][16 cols=s]

// =====================================================================
// Pass 1: per-chunk state sums (fully parallel, transposed projections)
// =====================================================================
#define P1_BYTES ((1088*2 + 1408*2 + 464*2)*4 + (75+576)*4)
__global__ __launch_bounds__(256) void chunk_sum_kernel(BasePtrs bp){
    extern __shared__ float sm[];
    float* s_k    = sm;              // [16][KPAD]
    float* s_v    = s_k + 16*KPAD;
    float* prjULT = s_v + 16*KPAD;   // [88][16]
    float* prjVRT = prjULT + 1408;
    float* sUL    = prjVRT + 1408;
    float* sVR    = sUL + 464;
    int*   s_nd   = (int*)(sVR + 464);
    int*   lutAB  = s_nd + 75;

    const int tid = threadIdx.x;
    const int blk = blockIdx.x;
    const int b = blk / NCH, c = blk % NCH;
    const float* gk = g_k + ((size_t)b*TSEQ + c*CCH)*DH;
    const float* gv = g_v + ((size_t)b*TSEQ + c*CCH)*DH;

    for (int i=tid;i<464;i+=256){
        int l = (i<16)?0:(i<80)?1:(i<208)?2:3;
        int off = i - Kbso(l);
        sUL[i] = bp.p[l][off];
        sVR[i] = bp.p[4+l][off];
    }
    for (int i=tid;i<512;i+=256){
        int arr = i>>8;
        int rem = i & 255; int row = rem>>4, g = rem&15;
        const float* src = (arr==0?gk:gv) + row*64 + g*4;
        float* dst = (arr==0?s_k:s_v) + row*KPAD + g*4;
        *(float4*)dst = *(const float4*)src;
    }
    build_node_lut(s_nd, tid);
    build_ws_lut(lutAB, tid, 256);
    __syncthreads();

    // projections (transposed stores)
    if (tid < 240){
        int m = tid>>4, s = tid&15;
        int bs=s_nd[m*5], r=s_nd[m*5+1], pb=s_nd[m*5+2], topo=s_nd[m*5+3], bso=s_nd[m*5+4];
        const float* kt = s_k + s*KPAD + topo;
        const float* vb = s_v + s*KPAD + topo + bs;
        float aU[8], aV[8];
#pragma unroll
        for (int i=0;i<8;i++){ aU[i]=0.f; aV[i]=0.f; }
        if (r == 4){
            for (int d=0; d<bs; d++){
                float kd = kt[d], vd = vb[d];
                float4 u = *(const float4*)(sUL + bso + d*4);
                float4 w = *(const float4*)(sVR + bso + d*4);
                aU[0]=fmaf(kd,u.x,aU[0]); aU[1]=fmaf(kd,u.y,aU[1]); aU[2]=fmaf(kd,u.z,aU[2]); aU[3]=fmaf(kd,u.w,aU[3]);
                aV[0]=fmaf(vd,w.x,aV[0]); aV[1]=fmaf(vd,w.y,aV[1]); aV[2]=fmaf(vd,w.z,aV[2]); aV[3]=fmaf(vd,w.w,aV[3]);
            }
        } else {
            for (int d=0; d<bs; d++){
                float kd = kt[d], vd = vb[d];
                const float* U = sUL + bso + d*8;
                const float* W = sVR + bso + d*8;
#pragma unroll
                for (int i=0;i<8;i++){
                    aU[i]=fmaf(kd,U[i],aU[i]);
                    aV[i]=fmaf(vd,W[i],aV[i]);
                }
            }
        }
        for (int i=0;i<r;i++){
            prjULT[(pb+i)*16+s]=aU[i];
            prjVRT[(pb+i)*16+s]=aV[i];
        }
    }
    __syncthreads();

    float* go = g_state + (size_t)blk*NST;
    for (int e=tid; e<NST; e+=256){
        float acc = 0.f;
        if (e < 256){
            int n=e>>4, i=(e>>2)&3, j2=e&3;
            int ki=4*n+i, vi=4*n+j2;
#pragma unroll
            for (int s=0;s<CCH;s++) acc = fmaf(s_k[s*KPAD+ki], s_v[s*KPAD+vi], acc);
        } else if (e < 832){
            int m = e-256;
            int ab = lutAB[m]; int a = ab & 0xffff, b3 = ab >> 16;
            const float4* pa = (const float4*)&prjULT[a*16];
            const float4* pb4 = (const float4*)&prjVRT[b3*16];
#pragma unroll
            for (int g=0;g<4;g++) acc += dot4v(pa[g], pb4[g]);
        } else {
            int d = e-832;
#pragma unroll
            for (int s=0;s<CCH;s++) acc += s_k[s*KPAD+d];
        }
        go[e] = acc;
    }
}

// =====================================================================
// Pass 2: exclusive prefix over chunks (per batch, element-parallel)
// =====================================================================
__global__ __launch_bounds__(128) void prefix_kernel(){
    const int b = blockIdx.y;
    const int e = blockIdx.x*128 + threadIdx.x;
    const float* gs = g_state  + (size_t)b*NCH*NST + e;
    float*       gp = g_prefix + (size_t)b*NCH*NST + e;
    float run = 0.f;
    for (int c0=0;c0<NCH;c0+=8){
        float v[8];
#pragma unroll
        for (int j=0;j<8;j++) v[j] = gs[(size_t)(c0+j)*NST];
#pragma unroll
        for (int j=0;j<8;j++){ gp[(size_t)(c0+j)*NST] = run; run += v[j]; }
    }
}

// =====================================================================
// Pass 3: fully parallel intra-chunk "attention" formulation
// =====================================================================
#define P3_BYTES (27776*4 + 339*4)
__global__ __launch_bounds__(256) void chunk_scan_kernel(BasePtrs bp){
    extern __shared__ float sm[];
    float* s_k    = sm;                 // [16][KPAD]
    float* s_v    = s_k + 16*KPAD;
    float* s_q    = s_v + 16*KPAD;
    float* prjULT = s_q + 16*KPAD;      // [88][16] each
    float* prjVRT = prjULT + 1408;
    float* prjXT  = prjVRT + 1408;      // VR^T q_bot
    float* prjLT  = prjXT + 1408;       // VL^T q_top
    float* sUL    = prjLT + 1408;       // 464 each
    float* sVR    = sUL + 464;
    float* sUR    = sVR + 464;
    float* sVL    = sUR + 464;
    float* s_leaf = sVL + 464;          // 256
    float* s_Ws   = s_leaf + 256;       // 576
    float* s_z    = s_Ws + 576;         // 64
    float* Asc    = s_z + 64;           // [15][16 t][16 s] = 3840
    float* Bsc    = Asc + 3840;
    float* Cle    = Bsc + 3840;         // [16][16 t][16 s] = 4096
    float* Dsc    = Cle + 4096;         // [16 t][16 s]
    float* s_den  = Dsc + 256;          // 16
    float* TT     = s_den + 16;         // [88][17] = 1496
    float* TBB    = TT + 1496;
    float* yl     = TBB + 1496;         // [64][17] = 1088
    int*   s_nd   = (int*)(yl + 1088);  // 75
    int*   lutP   = s_nd + 75;          // 88
    int*   lutWT  = lutP + 88;          // 88
    int*   lutWB  = lutWT + 88;         // 88

    const int tid = threadIdx.x;
    const int blk = blockIdx.x;
    const int b = blk / NCH, c = blk % NCH;
    const float* gk = g_k + ((size_t)b*TSEQ + c*CCH)*DH;
    const float* gv = g_v + ((size_t)b*TSEQ + c*CCH)*DH;
    const float* gq = g_q + ((size_t)b*TSEQ + c*CCH)*DH;
    float* g_o      = g_att + ((size_t)b*TSEQ + c*CCH)*DH;

    // ---- init loads ----
    for (int i=tid;i<464;i+=256){
        int l = (i<16)?0:(i<80)?1:(i<208)?2:3;
        int off = i - Kbso(l);
        sUL[i] = bp.p[l   ][off];
        sVR[i] = bp.p[4+l ][off];
        sUR[i] = bp.p[8+l ][off];
        sVL[i] = bp.p[12+l][off];
    }
    for (int i=tid;i<768;i+=256){
        int arr = i>>8;
        int rem = i & 255; int row = rem>>4, g = rem&15;
        const float* src = (arr==0?gk:(arr==1?gv:gq)) + row*64 + g*4;
        float* dst = (arr==0?s_k:(arr==1?s_v:s_q)) + row*KPAD + g*4;
        *(float4*)dst = *(const float4*)src;
    }
    {
        const float* gp = g_prefix + (size_t)blk*NST;
        for (int e=tid;e<NST;e+=256){
            float vle = gp[e];
            if (e<256) s_leaf[e]=vle;
            else if (e<832) s_Ws[e-256]=vle;
            else s_z[e-832]=vle;
        }
    }
    build_node_lut(s_nd, tid);
    if (tid < 88){
        int i88 = tid;
        int l = (i88<32)?0:(i88<64)?1:(i88<80)?2:3;
        int r = (l==0)?4:8;
        int rem = i88 - Knro(l);
        int n = rem / r, i = rem - n*r;
        int pb = Knro(l) + n*r;
        int ng = Knoff(l) + n;
        lutP[i88]  = pb | (ng<<8) | (r<<16);
        lutWT[i88] = Kwso(l) + n*r*r + i*r;
        lutWB[i88] = Kwso(l) + n*r*r + i;
    }
    __syncthreads();

    // ---- phase P: transposed projections for all tokens ----
    if (tid < 240){
        int m = tid>>4, s = tid&15;
        int bs=s_nd[m*5], r=s_nd[m*5+1], pb=s_nd[m*5+2], topo=s_nd[m*5+3], bso=s_nd[m*5+4];
        const float* kt = s_k + s*KPAD + topo;
        const float* vb = s_v + s*KPAD + topo + bs;
        const float* qt = s_q + s*KPAD + topo;
        const float* qb = qt + bs;
        float aU[8], aV[8], aX[8], aL[8];
#pragma unroll
        for (int i=0;i<8;i++){ aU[i]=aV[i]=aX[i]=aL[i]=0.f; }
        if (r == 4){
            for (int d=0; d<bs; d++){
                float kd=kt[d], vd=vb[d], qbd=qb[d], qtd=qt[d];
                const float* U = sUL + bso + d*4;
                const float* W = sVR + bso + d*4;
                const float* X = sVL + bso + d*4;
#pragma unroll
                for (int i=0;i<4;i++){
                    aU[i]=fmaf(kd,U[i],aU[i]);
                    aV[i]=fmaf(vd,W[i],aV[i]);
                    aX[i]=fmaf(qbd,W[i],aX[i]);
                    aL[i]=fmaf(qtd,X[i],aL[i]);
                }
            }
        } else {
            for (int d=0; d<bs; d++){
                float kd=kt[d], vd=vb[d], qbd=qb[d], qtd=qt[d];
                const float* U = sUL + bso + d*8;
                const float* W = sVR + bso + d*8;
                const float* X = sVL + bso + d*8;
#pragma unroll
                for (int i=0;i<8;i++){
                    aU[i]=fmaf(kd,U[i],aU[i]);
                    aV[i]=fmaf(vd,W[i],aV[i]);
                    aX[i]=fmaf(qbd,W[i],aX[i]);
                    aL[i]=fmaf(qtd,X[i],aL[i]);
                }
            }
        }
        for (int i=0;i<r;i++){
            prjULT[(pb+i)*16+s]=aU[i];
            prjVRT[(pb+i)*16+s]=aV[i];
            prjXT [(pb+i)*16+s]=aX[i];
            prjLT [(pb+i)*16+s]=aL[i];
        }
    }
    __syncthreads();

    // ---- phase 2: score matrices (causally masked, s<=t) ----
    if (tid < 240){   // A[n][t][s] = vR_s . vrx_t
        int ng = tid>>4, t = tid&15;
        int r = s_nd[ng*5+1], pb = s_nd[ng*5+2];
        float4 a0=make_float4(0,0,0,0), a1=a0, a2=a0, a3=a0;
        for (int i=0;i<r;i++){
            float w = prjXT[(pb+i)*16+t];
            const float4* vr = (const float4*)&prjVRT[(pb+i)*16];
            fma4(a0,w,vr[0]); fma4(a1,w,vr[1]); fma4(a2,w,vr[2]); fma4(a3,w,vr[3]);
        }
        float* dst = &Asc[tid*16];
        dst[0]=a0.x; dst[1]=(1<=t)?a0.y:0.f; dst[2]=(2<=t)?a0.z:0.f; dst[3]=(3<=t)?a0.w:0.f;
        dst[4]=(4<=t)?a1.x:0.f; dst[5]=(5<=t)?a1.y:0.f; dst[6]=(6<=t)?a1.z:0.f; dst[7]=(7<=t)?a1.w:0.f;
        dst[8]=(8<=t)?a2.x:0.f; dst[9]=(9<=t)?a2.y:0.f; dst[10]=(10<=t)?a2.z:0.f; dst[11]=(11<=t)?a2.w:0.f;
        dst[12]=(12<=t)?a3.x:0.f; dst[13]=(13<=t)?a3.y:0.f; dst[14]=(14<=t)?a3.z:0.f; dst[15]=(15<=t)?a3.w:0.f;
    }
    if (tid < 240){   // B[n][t][s] = uL_s . vlx_t
        int ng = tid>>4, t = tid&15;
        int r = s_nd[ng*5+1], pb = s_nd[ng*5+2];
        float4 a0=make_float4(0,0,0,0), a1=a0, a2=a0, a3=a0;
        for (int i=0;i<r;i++){
            float w = prjLT[(pb+i)*16+t];
            const float4* ul = (const float4*)&prjULT[(pb+i)*16];
            fma4(a0,w,ul[0]); fma4(a1,w,ul[1]); fma4(a2,w,ul[2]); fma4(a3,w,ul[3]);
        }
        float* dst = &Bsc[tid*16];
        dst[0]=a0.x; dst[1]=(1<=t)?a0.y:0.f; dst[2]=(2<=t)?a0.z:0.f; dst[3]=(3<=t)?a0.w:0.f;
        dst[4]=(4<=t)?a1.x:0.f; dst[5]=(5<=t)?a1.y:0.f; dst[6]=(6<=t)?a1.z:0.f; dst[7]=(7<=t)?a1.w:0.f;
        dst[8]=(8<=t)?a2.x:0.f; dst[9]=(9<=t)?a2.y:0.f; dst[10]=(10<=t)?a2.z:0.f; dst[11]=(11<=t)?a2.w:0.f;
        dst[12]=(12<=t)?a3.x:0.f; dst[13]=(13<=t)?a3.y:0.f; dst[14]=(14<=t)?a3.z:0.f; dst[15]=(15<=t)?a3.w:0.f;
    }
    {   // Cleaf[n][t][s] = (v_s . q_t) over leaf n, masked
        int n = tid>>4, t = tid&15;
        float4 qv = *(const float4*)&s_q[t*KPAD+4*n];
        float* dst = &Cle[tid*16];
#pragma unroll
        for (int s=0;s<16;s++){
            float val = dot4v(*(const float4*)&s_v[s*KPAD+4*n], qv);
            dst[s] = (s<=t)? val : 0.f;
        }
    }
    {   // D[t][s] = k_s . q_t (unmasked)
        int t = tid>>4, s = tid&15;
        float acc = 0.f;
#pragma unroll
        for (int g=0;g<16;g++)
            acc += dot4v(*(const float4*)&s_k[s*KPAD+4*g], *(const float4*)&s_q[t*KPAD+4*g]);
        Dsc[tid] = acc;
    }
    __syncthreads();

    // ---- phase 3: weighted accumulations ----
    for (int j=tid; j<1408; j+=256){   // TT[i88][t] = Ws_pref@vrx + sum_s uL_s[i]*A
        int i88 = j>>4, t = j&15;
        int info = lutP[i88]; int pb = info&255, ng=(info>>8)&255, r=info>>16;
        float acc = 0.f;
        int wr = lutWT[i88];
        for (int u=0;u<r;u++) acc = fmaf(s_Ws[wr+u], prjXT[(pb+u)*16+t], acc);
        const float4* uu = (const float4*)&prjULT[i88*16];
        const float4* aa = (const float4*)&Asc[(ng*16+t)*16];
        acc += dot4v(uu[0],aa[0]) + dot4v(uu[1],aa[1]) + dot4v(uu[2],aa[2]) + dot4v(uu[3],aa[3]);
        TT[i88*17+t] = acc;
    }
    for (int j=tid; j<1408; j+=256){   // TB[i88][t] = Ws_pref^T@vlx + sum_s vR_s[i]*B
        int i88 = j>>4, t = j&15;
        int info = lutP[i88]; int pb = info&255, ng=(info>>8)&255, r=info>>16;
        float acc = 0.f;
        int wc = lutWB[i88];
        for (int u=0;u<r;u++) acc = fmaf(s_Ws[wc+u*r], prjLT[(pb+u)*16+t], acc);
        const float4* vv = (const float4*)&prjVRT[i88*16];
        const float4* bb = (const float4*)&Bsc[(ng*16+t)*16];
        acc += dot4v(vv[0],bb[0]) + dot4v(vv[1],bb[1]) + dot4v(vv[2],bb[2]) + dot4v(vv[3],bb[3]);
        TBB[i88*17+t] = acc;
    }
    for (int j=tid; j<1024; j+=256){   // yl[d][t] = leaf_pref@q + sum_s k_s[d]*Cleaf
        int d = j>>4, t = j&15, n = d>>2;
        float4 lf = *(const float4*)&s_leaf[d*4];
        float4 qv = *(const float4*)&s_q[t*KPAD+4*n];
        float acc = dot4v(lf, qv);
        const float* cl = &Cle[(n*16+t)*16];
#pragma unroll
        for (int s=0;s<16;s++) acc = fmaf(s_k[s*KPAD+d], cl[s], acc);
        yl[d*17+t] = acc;
    }
    if (tid < 16){   // denominators
        int t = tid;
        float acc = 0.f;
#pragma unroll
        for (int g=0;g<16;g++)
            acc += dot4v(*(const float4*)&s_z[4*g], *(const float4*)&s_q[t*KPAD+4*g]);
        for (int s=0;s<=t;s++) acc += Dsc[t*16+s];
        s_den[t] = fmaxf(acc, 1e-6f);
    }
    __syncthreads();

    // ---- phase 4: final assembly ----
    for (int j=tid; j<1024; j+=256){
        int d = j&63, t = j>>6;
        float y = yl[d*17+t];
#pragma unroll
        for (int l=0;l<4;l++){
            const int bs = 4<<l;
            const int r  = (l==0)?4:8;
            const int n = d >> (3+l);
            const int loc = d & (2*bs - 1);
            const int pb = Knro(l) + n*r;
            const int bso = Kbso(l);
            if (loc < bs){
                const float* u = sUL + bso + loc*r;
                for (int i=0;i<r;i++) y = fmaf(u[i], TT[(pb+i)*17+t], y);
            } else {
                const float* u = sUR + bso + (loc-bs)*r;
                for (int i=0;i<r;i++) y = fmaf(u[i], TBB[(pb+i)*17+t], y);
            }
        }
        g_o[(size_t)t*DH + d] = y / s_den[t];
    }
}

// ---------------- output GEMM: att(16384x64) @ Wo(64x1024) ----------------
__global__ __launch_bounds__(256) void wo_kernel(const float* __restrict__ Wo,
                                                 float* __restrict__ out){
    __shared__ float As[64][64];
    __shared__ float Bs[64][64];
    const int tid = threadIdx.x;
    const int rb = blockIdx.x*64, cbase = blockIdx.y*256;
#pragma unroll
    for(int i=0;i<4;i++){
        int idx = tid + i*256;
        int row = idx >> 4, g = idx & 15;
        float4 av = *(const float4*)(g_att + (size_t)(rb+row)*DH + g*4);
        *(float4*)&As[row][g*4] = av;
    }
    const int ty = tid >> 4, tx = tid & 15;
    for(int sub=0; sub<4; sub++){
        const int cbk = cbase + sub*64;
        __syncthreads();
#pragma unroll
        for(int i=0;i<4;i++){
            int idx = tid + i*256;
            int row = idx >> 4, g = idx & 15;
            float4 bv = *(const float4*)(Wo + (size_t)row*DM + cbk + g*4);
            *(float4*)&Bs[row][g*4] = bv;
        }
        __syncthreads();
        unsigned long long acc[4][2];
#pragma unroll
        for(int i=0;i<4;i++){ acc[i][0]=0ULL; acc[i][1]=0ULL; }
        for(int kk=0;kk<64;kk++){
            float a0 = As[ty*4+0][kk];
            float a1 = As[ty*4+1][kk];
            float a2 = As[ty*4+2][kk];
            float a3 = As[ty*4+3][kk];
            const unsigned long long* bpp = (const unsigned long long*)&Bs[kk][tx*4];
            unsigned long long b0 = bpp[0], b1 = bpp[1];
            unsigned long long ap;
            ap = pack2(a0,a0); fma2(acc[0][0],ap,b0); fma2(acc[0][1],ap,b1);
            ap = pack2(a1,a1); fma2(acc[1][0],ap,b0); fma2(acc[1][1],ap,b1);
            ap = pack2(a2,a2); fma2(acc[2][0],ap,b0); fma2(acc[2][1],ap,b1);
            ap = pack2(a3,a3); fma2(acc[3][0],ap,b0); fma2(acc[3][1],ap,b1);
        }
#pragma unroll
        for(int i=0;i<4;i++){
            float4 ov;
            unpack2(acc[i][0], ov.x, ov.y);
            unpack2(acc[i][1], ov.z, ov.w);
            *(float4*)(out + (size_t)(rb+ty*4+i)*DM + cbk + tx*4) = ov;
        }
    }
}

extern "C" void kernel_launch(void* const* d_in, const int* in_sizes, int n_in,
                              void* d_out, int out_size){
    (void)in_sizes; (void)n_in; (void)out_size;
    const float* x  = (const float*)d_in[0];
    const float* Wq = (const float*)d_in[1];
    const float* Wk = (const float*)d_in[2];
    const float* Wv = (const float*)d_in[3];
    const float* Wo = (const float*)d_in[4];
    BasePtrs bp;
    for(int i=0;i<16;i++) bp.p[i] = (const float*)d_in[5+i];
    float* out = (float*)d_out;

    cudaFuncSetAttribute(chunk_sum_kernel,  cudaFuncAttributeMaxDynamicSharedMemorySize, P1_BYTES);
    cudaFuncSetAttribute(chunk_scan_kernel, cudaFuncAttributeMaxDynamicSharedMemorySize, P3_BYTES);

    qkv_kernel<<<NTOK/64, 256>>>(x, Wq, Wk, Wv);
    chunk_sum_kernel<<<BB*NCH, 256, P1_BYTES>>>(bp);
    prefix_kernel<<<dim3(NST/128, BB), 128>>>();
    chunk_scan_kernel<<<BB*NCH, 256, P3_BYTES>>>(bp);
    wo_kernel<<<dim3(NTOK/64, DM/256), 256>>>(Wo, out);
}

// round 5
// speedup vs baseline: 36.2483x; 1.0653x over previous
#include <cuda_runtime.h>
#include <math.h>

#define TSEQ 2048
#define BB 8
#define DH 64
#define DM 1024
#define NTOK (BB*TSEQ)
#define CCH 16
#define NCH (TSEQ/CCH)   /* 128 */
#define NST 896          /* leaf 256 + Ws 576 + z 64 */
#define KPAD 68
#define NT 512

// scratch (device globals -- no allocation allowed)
__device__ float g_q[NTOK*DH];
__device__ float g_k[NTOK*DH];
__device__ float g_v[NTOK*DH];
__device__ float g_att[NTOK*DH];
__device__ float g_state[BB*NCH*NST];
__device__ float g_prefix[BB*NCH*NST];

struct BasePtrs { const float* p[16]; }; // UL0-3, VR0-3, UR0-3, VL0-3

// ---------------- f32x2 packed math helpers ----------------
__device__ __forceinline__ unsigned long long pack2(float lo, float hi){
    unsigned long long r;
    asm("mov.b64 %0, {%1,%2};" : "=l"(r) : "f"(lo), "f"(hi));
    return r;
}
__device__ __forceinline__ void unpack2(unsigned long long v, float &lo, float &hi){
    asm("mov.b64 {%0,%1}, %2;" : "=f"(lo), "=f"(hi) : "l"(v));
}
__device__ __forceinline__ void fma2(unsigned long long &d, unsigned long long a, unsigned long long b){
    asm("fma.rn.f32x2 %0, %1, %2, %3;" : "=l"(d) : "l"(a), "l"(b), "l"(d));
}
__device__ __forceinline__ void cp_async16(void* sptr, const void* gptr){
    unsigned s = (unsigned)__cvta_generic_to_shared(sptr);
    asm volatile("cp.async.ca.shared.global [%0], [%1], 16;" :: "r"(s), "l"(gptr));
}
__device__ __forceinline__ float dot4v(float4 a, float4 b){
    return fmaf(a.x,b.x, fmaf(a.y,b.y, fmaf(a.z,b.z, a.w*b.w)));
}
__device__ __forceinline__ void fma4(float4 &acc, float s, float4 v){
    acc.x = fmaf(s, v.x, acc.x); acc.y = fmaf(s, v.y, acc.y);
    acc.z = fmaf(s, v.z, acc.z); acc.w = fmaf(s, v.w, acc.w);
}

__device__ __forceinline__ int Knro(int l){ return (l==0)?0:(l==1)?32:(l==2)?64:80; }
__device__ __forceinline__ int Kwso(int l){ return (l==0)?0:(l==1)?128:(l==2)?384:512; }
__device__ __forceinline__ int Kbso(int l){ return (l==0)?0:(l==1)?16:(l==2)?80:208; }
__device__ __forceinline__ int Knoff(int l){ return (l==0)?0:(l==1)?8:(l==2)?12:14; }

// ---------------- QKV projection (unchanged; f32x2 floor) ----------------
__global__ __launch_bounds__(256) void qkv_kernel(const float* __restrict__ x,
                                                  const float* __restrict__ Wq,
                                                  const float* __restrict__ Wk,
                                                  const float* __restrict__ Wv){
    __shared__ float2 As2[2][64][16];
    __shared__ float  Bs [2][16][192];
    const int tid = threadIdx.x;
    const int rb  = blockIdx.x * 64;
    const int ty  = tid >> 5;
    const int tx  = tid & 31;
    const int arow = tid >> 2, agrp = tid & 3;

    unsigned long long acc[8][3];
#pragma unroll
    for(int i=0;i<8;i++)
#pragma unroll
        for(int j=0;j<3;j++) acc[i][j] = 0ULL;

    int bk_[3], c4_[3]; const float* wsrc[3];
#pragma unroll
    for(int i=0;i<3;i++){
        int idx = tid + i*256;
        bk_[i] = idx / 48;
        int c4 = (idx % 48) * 4;
        c4_[i] = c4;
        wsrc[i] = (c4 < 64) ? Wq : (c4 < 128 ? Wk : Wv);
    }

    float4 av = *(const float4*)(x + (size_t)(rb+arow)*DM + agrp*4);
#pragma unroll
    for(int i=0;i<3;i++)
        cp_async16(&Bs[0][bk_[i]][c4_[i]], wsrc[i] + (size_t)bk_[i]*DH + (c4_[i] & 63));
    asm volatile("cp.async.commit_group;\n");
    {
        float2* d = &As2[0][arow][agrp*4];
        d[0] = make_float2(av.x, av.x);
        d[1] = make_float2(av.y, av.y);
        d[2] = make_float2(av.z, av.z);
        d[3] = make_float2(av.w, av.w);
    }
    asm volatile("cp.async.wait_group 0;\n");
    __syncthreads();

    for(int kt=0; kt<64; kt++){
        const int buf = kt & 1;
        if (kt < 63){
            int k0 = (kt+1)*16;
            av = *(const float4*)(x + (size_t)(rb+arow)*DM + k0 + agrp*4);
#pragma unroll
            for(int i=0;i<3;i++)
                cp_async16(&Bs[buf^1][bk_[i]][c4_[i]], wsrc[i] + (size_t)(k0+bk_[i])*DH + (c4_[i] & 63));
            asm volatile("cp.async.commit_group;\n");
        }
#pragma unroll
        for(int kk=0;kk<16;kk++){
            unsigned long long a2[8];
#pragma unroll
            for(int i=0;i<8;i++) a2[i] = *(const unsigned long long*)&As2[buf][ty*8+i][kk];
            const unsigned long long* bp = (const unsigned long long*)&Bs[buf][kk][tx*6];
            unsigned long long b0 = bp[0], b1 = bp[1], b2 = bp[2];
#pragma unroll
            for(int i=0;i<8;i++){
                fma2(acc[i][0], a2[i], b0);
                fma2(acc[i][1], a2[i], b1);
                fma2(acc[i][2], a2[i], b2);
            }
        }
        __syncthreads();
        if (kt < 63){
            float2* d = &As2[buf^1][arow][agrp*4];
            d[0] = make_float2(av.x, av.x);
            d[1] = make_float2(av.y, av.y);
            d[2] = make_float2(av.z, av.z);
            d[3] = make_float2(av.w, av.w);
            asm volatile("cp.async.wait_group 0;\n");
            __syncthreads();
        }
    }

#pragma unroll
    for(int i=0;i<8;i++){
        int row = rb + ty*8 + i;
#pragma unroll
        for(int j=0;j<3;j++){
            float lo, hi; unpack2(acc[i][j], lo, hi);
            float vals[2] = {lo, hi};
#pragma unroll
            for(int u=0;u<2;u++){
                int cc = tx*6 + j*2 + u;
                float v = vals[u];
                if(cc < 128) v = (v > 0.f) ? (v + 1.f) : expf(v);
                float* dst = (cc < 64) ? g_q : (cc < 128 ? g_k : g_v);
                dst[(size_t)row*DH + (cc & 63)] = v;
            }
        }
    }
}

// =====================================================================
// shared LUT builders
// =====================================================================
__device__ __forceinline__ void build_node_lut(int* s_nd, int tid){
    if (tid < 15){
        int l = (tid<8)?0:(tid<12)?1:(tid<14)?2:3;
        int n = tid - Knoff(l);
        int bs = 4<<l, r = (l==0)?4:8;
        s_nd[tid*5+0]=bs; s_nd[tid*5+1]=r; s_nd[tid*5+2]=Knro(l)+n*r;
        s_nd[tid*5+3]=2*bs*n; s_nd[tid*5+4]=Kbso(l);
    }
}
__device__ __forceinline__ void build_ws_lut(int* s_lutAB, int tid, int nthr){
    for (int m = tid; m < 576; m += nthr){
        int l = (m<128)?0:(m<384)?1:(m<512)?2:3;
        int r = (l==0)?4:8;
        int rem = m - Kwso(l);
        int rr2 = r*r;
        int n = rem / rr2;
        int ij = rem - n*rr2;
        int i = ij / r, j = ij - i*r;
        int pb = Knro(l) + n*r;
        s_lutAB[m] = (pb+i) | ((pb+j)<<16);
    }
}
// projection d-chunk table: 20 chunks; pack m | dd0<<8 | ext<<16 | ec<<20
__device__ __forceinline__ void build_chunk_lut(int* s_ck, int tid){
    if (tid < 20){
        int c = tid, m, dd0=0, ext=0, ec=0;
        if (c < 13){ m = c; }
        else if (c == 13){ m=12; dd0=8; ext=1; ec=0; }
        else if (c == 14){ m=13; }
        else if (c == 15){ m=13; dd0=8; ext=1; ec=1; }
        else if (c == 16){ m=14; }
        else { m=14; dd0=8*(c-16); ext=1; ec=c-15; }
        s_ck[c] = m | (dd0<<8) | (ext<<16) | (ec<<20);
    }
}

// =====================================================================
// Pass 1: per-chunk state sums (512 threads, chunked projections)
// =====================================================================
#define P1_FLOATS (2176 + 2816 + 928 + 1280)
#define P1_BYTES (P1_FLOATS*4 + (75+576+20)*4)
__global__ __launch_bounds__(512,2) void chunk_sum_kernel(BasePtrs bp){
    extern __shared__ float sm[];
    float* s_k    = sm;              // [16][KPAD]
    float* s_v    = s_k + 16*KPAD;
    float* prjULT = s_v + 16*KPAD;   // [88][16]
    float* prjVRT = prjULT + 1408;
    float* sUL    = prjVRT + 1408;
    float* sVR    = sUL + 464;
    float* extP   = sVR + 464;       // [2][5][8][16] = 1280
    int*   s_nd   = (int*)(extP + 1280);
    int*   lutAB  = s_nd + 75;
    int*   s_ck   = lutAB + 576;

    const int tid = threadIdx.x;
    const int blk = blockIdx.x;
    const int b = blk / NCH, c = blk % NCH;
    const float* gk = g_k + ((size_t)b*TSEQ + c*CCH)*DH;
    const float* gv = g_v + ((size_t)b*TSEQ + c*CCH)*DH;

    for (int i=tid;i<464;i+=NT){
        int l = (i<16)?0:(i<80)?1:(i<208)?2:3;
        int off = i - Kbso(l);
        sUL[i] = bp.p[l][off];
        sVR[i] = bp.p[4+l][off];
    }
    for (int i=tid;i<512;i+=NT){
        int arr = i>>8;
        int rem = i & 255; int row = rem>>4, g = rem&15;
        const float* src = (arr==0?gk:gv) + row*64 + g*4;
        float* dst = (arr==0?s_k:s_v) + row*KPAD + g*4;
        *(float4*)dst = *(const float4*)src;
    }
    build_node_lut(s_nd, tid);
    build_ws_lut(lutAB, tid, NT);
    build_chunk_lut(s_ck, tid);
    __syncthreads();

    // projections (chunked, transposed stores)
    if (tid < 320){
        int cd = s_ck[tid>>4]; int s = tid&15;
        int m = cd & 31, dd0 = (cd>>8)&63, isext=(cd>>16)&1, ec=(cd>>20)&7;
        int bs=s_nd[m*5], r=s_nd[m*5+1], pb=s_nd[m*5+2], topo=s_nd[m*5+3], bso=s_nd[m*5+4];
        const float* kt = s_k + s*KPAD + topo + dd0;
        const float* vb = s_v + s*KPAD + topo + bs + dd0;
        const float* Ub = sUL + bso + dd0*r;
        const float* Wb = sVR + bso + dd0*r;
        if (r == 4){
            float4 aU=make_float4(0,0,0,0), aV=aU;
#pragma unroll
            for (int d=0; d<4; d++){
                float kd=kt[d], vd=vb[d];
                float4 u=*(const float4*)(Ub+d*4), w=*(const float4*)(Wb+d*4);
                fma4(aU,kd,u); fma4(aV,vd,w);
            }
            float au[4]={aU.x,aU.y,aU.z,aU.w}, avv[4]={aV.x,aV.y,aV.z,aV.w};
#pragma unroll
            for (int i=0;i<4;i++){
                prjULT[(pb+i)*16+s]=au[i];
                prjVRT[(pb+i)*16+s]=avv[i];
            }
        } else {
            float aU[8], aV[8];
#pragma unroll
            for (int i=0;i<8;i++){ aU[i]=0.f; aV[i]=0.f; }
#pragma unroll
            for (int d=0; d<8; d++){
                float kd=kt[d], vd=vb[d];
                float4 u0=*(const float4*)(Ub+d*8), u1=*(const float4*)(Ub+d*8+4);
                float4 w0=*(const float4*)(Wb+d*8), w1=*(const float4*)(Wb+d*8+4);
                aU[0]=fmaf(kd,u0.x,aU[0]); aU[1]=fmaf(kd,u0.y,aU[1]); aU[2]=fmaf(kd,u0.z,aU[2]); aU[3]=fmaf(kd,u0.w,aU[3]);
                aU[4]=fmaf(kd,u1.x,aU[4]); aU[5]=fmaf(kd,u1.y,aU[5]); aU[6]=fmaf(kd,u1.z,aU[6]); aU[7]=fmaf(kd,u1.w,aU[7]);
                aV[0]=fmaf(vd,w0.x,aV[0]); aV[1]=fmaf(vd,w0.y,aV[1]); aV[2]=fmaf(vd,w0.z,aV[2]); aV[3]=fmaf(vd,w0.w,aV[3]);
                aV[4]=fmaf(vd,w1.x,aV[4]); aV[5]=fmaf(vd,w1.y,aV[5]); aV[6]=fmaf(vd,w1.z,aV[6]); aV[7]=fmaf(vd,w1.w,aV[7]);
            }
            if (!isext){
#pragma unroll
                for (int i=0;i<8;i++){
                    prjULT[(pb+i)*16+s]=aU[i];
                    prjVRT[(pb+i)*16+s]=aV[i];
                }
            } else {
#pragma unroll
                for (int i=0;i<8;i++){
                    extP[((0*5+ec)*8+i)*16+s]=aU[i];
                    extP[((1*5+ec)*8+i)*16+s]=aV[i];
                }
            }
        }
    }
    __syncthreads();
    // combine ext partials into main rows
    if (tid < 256){
        int a=tid>>7, i=(tid>>4)&7, s=tid&15;
        float* base = prjULT + a*1408;
        base[(64+i)*16+s] += extP[((a*5+0)*8+i)*16+s];
        base[(72+i)*16+s] += extP[((a*5+1)*8+i)*16+s];
        base[(80+i)*16+s] += extP[((a*5+2)*8+i)*16+s] + extP[((a*5+3)*8+i)*16+s] + extP[((a*5+4)*8+i)*16+s];
    }
    __syncthreads();

    float* go = g_state + (size_t)blk*NST;
    for (int e=tid; e<NST; e+=NT){
        float acc = 0.f;
        if (e < 256){
            int n=e>>4, i=(e>>2)&3, j2=e&3;
            int ki=4*n+i, vi=4*n+j2;
#pragma unroll
            for (int s=0;s<CCH;s++) acc = fmaf(s_k[s*KPAD+ki], s_v[s*KPAD+vi], acc);
        } else if (e < 832){
            int m = e-256;
            int ab = lutAB[m]; int a = ab & 0xffff, b3 = ab >> 16;
            const float4* pa = (const float4*)&prjULT[a*16];
            const float4* pb4 = (const float4*)&prjVRT[b3*16];
#pragma unroll
            for (int g=0;g<4;g++) acc += dot4v(pa[g], pb4[g]);
        } else {
            int d = e-832;
#pragma unroll
            for (int s=0;s<CCH;s++) acc += s_k[s*KPAD+d];
        }
        go[e] = acc;
    }
}

// =====================================================================
// Pass 2: exclusive prefix over chunks
// =====================================================================
__global__ __launch_bounds__(128) void prefix_kernel(){
    const int b = blockIdx.y;
    const int e = blockIdx.x*128 + threadIdx.x;
    const float* gs = g_state  + (size_t)b*NCH*NST + e;
    float*       gp = g_prefix + (size_t)b*NCH*NST + e;
    float run = 0.f;
    for (int c0=0;c0<NCH;c0+=8){
        float v[8];
#pragma unroll
        for (int j=0;j<8;j++) v[j] = gs[(size_t)(c0+j)*NST];
#pragma unroll
        for (int j=0;j<8;j++){ gp[(size_t)(c0+j)*NST] = run; run += v[j]; }
    }
}

// =====================================================================
// Pass 3: fully parallel intra-chunk attention, 512 threads
// =====================================================================
#define P3_FLOATS (3264 + 5632 + 1856 + 896 + 3840 + 3840 + 2560 + 256 + 16 + 1496 + 1496 + 1088)
#define P3_BYTES (P3_FLOATS*4 + (75 + 88*3 + 20)*4)
__global__ __launch_bounds__(512,2) void chunk_scan_kernel(BasePtrs bp){
    extern __shared__ float sm[];
    float* s_k    = sm;                 // [16][KPAD]
    float* s_v    = s_k + 16*KPAD;
    float* s_q    = s_v + 16*KPAD;
    float* prjULT = s_q + 16*KPAD;      // [88][16] x4 contiguous
    float* prjVRT = prjULT + 1408;
    float* prjXT  = prjVRT + 1408;
    float* prjLT  = prjXT + 1408;
    float* sUL    = prjLT + 1408;       // 464 x4
    float* sVR    = sUL + 464;
    float* sUR    = sVR + 464;
    float* sVL    = sUR + 464;
    float* s_leaf = sVL + 464;          // 256
    float* s_Ws   = s_leaf + 256;       // 576
    float* s_z    = s_Ws + 576;         // 64
    float* Asc    = s_z + 64;           // [240][16]
    float* Bsc    = Asc + 3840;         // [240][16]
    float* extP   = Bsc + 3840;         // [4][5][8][16] = 2560
    float* Dsc    = extP + 2560;        // [16][16]
    float* s_den  = Dsc + 256;          // 16
    float* TT     = s_den + 16;         // [88][17]
    float* TBB    = TT + 1496;
    float* yl     = TBB + 1496;         // [64][17]
    int*   s_nd   = (int*)(yl + 1088);
    int*   lutP   = s_nd + 75;
    int*   lutWT  = lutP + 88;
    int*   lutWB  = lutWT + 88;
    int*   s_ck   = lutWB + 88;

    const int tid = threadIdx.x;
    const int blk = blockIdx.x;
    const int b = blk / NCH, c = blk % NCH;
    const float* gk = g_k + ((size_t)b*TSEQ + c*CCH)*DH;
    const float* gv = g_v + ((size_t)b*TSEQ + c*CCH)*DH;
    const float* gq = g_q + ((size_t)b*TSEQ + c*CCH)*DH;
    float* g_o      = g_att + ((size_t)b*TSEQ + c*CCH)*DH;

    // ---- init ----
    for (int i=tid;i<464;i+=NT){
        int l = (i<16)?0:(i<80)?1:(i<208)?2:3;
        int off = i - Kbso(l);
        sUL[i] = bp.p[l   ][off];
        sVR[i] = bp.p[4+l ][off];
        sUR[i] = bp.p[8+l ][off];
        sVL[i] = bp.p[12+l][off];
    }
    for (int i=tid;i<768;i+=NT){
        int arr = i>>8;
        int rem = i & 255; int row = rem>>4, g = rem&15;
        const float* src = (arr==0?gk:(arr==1?gv:gq)) + row*64 + g*4;
        float* dst = (arr==0?s_k:(arr==1?s_v:s_q)) + row*KPAD + g*4;
        *(float4*)dst = *(const float4*)src;
    }
    {
        const float* gp = g_prefix + (size_t)blk*NST;
        for (int e=tid;e<NST;e+=NT){
            float vle = gp[e];
            if (e<256) s_leaf[e]=vle;
            else if (e<832) s_Ws[e-256]=vle;
            else s_z[e-832]=vle;
        }
    }
    build_node_lut(s_nd, tid);
    build_chunk_lut(s_ck, tid);
    if (tid < 88){
        int i88 = tid;
        int l = (i88<32)?0:(i88<64)?1:(i88<80)?2:3;
        int r = (l==0)?4:8;
        int rem = i88 - Knro(l);
        int n = rem / r, i = rem - n*r;
        int pb = Knro(l) + n*r;
        int ng = Knoff(l) + n;
        lutP[i88]  = pb | (ng<<8) | (r<<16);
        lutWT[i88] = Kwso(l) + n*r*r + i*r;
        lutWB[i88] = Kwso(l) + n*r*r + i;
    }
    __syncthreads();

    // ---- phase P: chunked projections + D scores ----
    if (tid < 320){
        int cd = s_ck[tid>>4]; int s = tid&15;
        int m = cd & 31, dd0 = (cd>>8)&63, isext=(cd>>16)&1, ec=(cd>>20)&7;
        int bs=s_nd[m*5], r=s_nd[m*5+1], pb=s_nd[m*5+2], topo=s_nd[m*5+3], bso=s_nd[m*5+4];
        const float* kt = s_k + s*KPAD + topo + dd0;
        const float* vb = s_v + s*KPAD + topo + bs + dd0;
        const float* qt = s_q + s*KPAD + topo + dd0;
        const float* qb = s_q + s*KPAD + topo + bs + dd0;
        const float* Ub = sUL + bso + dd0*r;
        const float* Wb = sVR + bso + dd0*r;
        const float* Xb = sVL + bso + dd0*r;
        if (r == 4){
            float4 aU=make_float4(0,0,0,0), aV=aU, aX=aU, aL=aU;
#pragma unroll
            for (int d=0; d<4; d++){
                float kd=kt[d], vd=vb[d], qtd=qt[d], qbd=qb[d];
                float4 u=*(const float4*)(Ub+d*4), w=*(const float4*)(Wb+d*4), x=*(const float4*)(Xb+d*4);
                fma4(aU,kd,u); fma4(aV,vd,w); fma4(aX,qbd,w); fma4(aL,qtd,x);
            }
            float t0[4]={aU.x,aU.y,aU.z,aU.w}, t1[4]={aV.x,aV.y,aV.z,aV.w};
            float t2[4]={aX.x,aX.y,aX.z,aX.w}, t3[4]={aL.x,aL.y,aL.z,aL.w};
#pragma unroll
            for (int i=0;i<4;i++){
                prjULT[(pb+i)*16+s]=t0[i];
                prjVRT[(pb+i)*16+s]=t1[i];
                prjXT [(pb+i)*16+s]=t2[i];
                prjLT [(pb+i)*16+s]=t3[i];
            }
        } else {
            // pass A: U (with k), V (with v)
            {
                float aU[8], aV[8];
#pragma unroll
                for (int i=0;i<8;i++){ aU[i]=0.f; aV[i]=0.f; }
#pragma unroll
                for (int d=0; d<8; d++){
                    float kd=kt[d], vd=vb[d];
                    float4 u0=*(const float4*)(Ub+d*8), u1=*(const float4*)(Ub+d*8+4);
                    float4 w0=*(const float4*)(Wb+d*8), w1=*(const float4*)(Wb+d*8+4);
                    aU[0]=fmaf(kd,u0.x,aU[0]); aU[1]=fmaf(kd,u0.y,aU[1]); aU[2]=fmaf(kd,u0.z,aU[2]); aU[3]=fmaf(kd,u0.w,aU[3]);
                    aU[4]=fmaf(kd,u1.x,aU[4]); aU[5]=fmaf(kd,u1.y,aU[5]); aU[6]=fmaf(kd,u1.z,aU[6]); aU[7]=fmaf(kd,u1.w,aU[7]);
                    aV[0]=fmaf(vd,w0.x,aV[0]); aV[1]=fmaf(vd,w0.y,aV[1]); aV[2]=fmaf(vd,w0.z,aV[2]); aV[3]=fmaf(vd,w0.w,aV[3]);
                    aV[4]=fmaf(vd,w1.x,aV[4]); aV[5]=fmaf(vd,w1.y,aV[5]); aV[6]=fmaf(vd,w1.z,aV[6]); aV[7]=fmaf(vd,w1.w,aV[7]);
                }
                if (!isext){
#pragma unroll
                    for (int i=0;i<8;i++){ prjULT[(pb+i)*16+s]=aU[i]; prjVRT[(pb+i)*16+s]=aV[i]; }
                } else {
#pragma unroll
                    for (int i=0;i<8;i++){
                        extP[((0*5+ec)*8+i)*16+s]=aU[i];
                        extP[((1*5+ec)*8+i)*16+s]=aV[i];
                    }
                }
            }
            // pass B: X (qb with W), L (qt with X)
            {
                float aX[8], aL[8];
#pragma unroll
                for (int i=0;i<8;i++){ aX[i]=0.f; aL[i]=0.f; }
#pragma unroll
                for (int d=0; d<8; d++){
                    float qbd=qb[d], qtd=qt[d];
                    float4 w0=*(const float4*)(Wb+d*8), w1=*(const float4*)(Wb+d*8+4);
                    float4 x0=*(const float4*)(Xb+d*8), x1=*(const float4*)(Xb+d*8+4);
                    aX[0]=fmaf(qbd,w0.x,aX[0]); aX[1]=fmaf(qbd,w0.y,aX[1]); aX[2]=fmaf(qbd,w0.z,aX[2]); aX[3]=fmaf(qbd,w0.w,aX[3]);
                    aX[4]=fmaf(qbd,w1.x,aX[4]); aX[5]=fmaf(qbd,w1.y,aX[5]); aX[6]=fmaf(qbd,w1.z,aX[6]); aX[7]=fmaf(qbd,w1.w,aX[7]);
                    aL[0]=fmaf(qtd,x0.x,aL[0]); aL[1]=fmaf(qtd,x0.y,aL[1]); aL[2]=fmaf(qtd,x0.z,aL[2]); aL[3]=fmaf(qtd,x0.w,aL[3]);
                    aL[4]=fmaf(qtd,x1.x,aL[4]); aL[5]=fmaf(qtd,x1.y,aL[5]); aL[6]=fmaf(qtd,x1.z,aL[6]); aL[7]=fmaf(qtd,x1.w,aL[7]);
                }
                if (!isext){
#pragma unroll
                    for (int i=0;i<8;i++){ prjXT[(pb+i)*16+s]=aX[i]; prjLT[(pb+i)*16+s]=aL[i]; }
                } else {
#pragma unroll
                    for (int i=0;i<8;i++){
                        extP[((2*5+ec)*8+i)*16+s]=aX[i];
                        extP[((3*5+ec)*8+i)*16+s]=aL[i];
                    }
                }
            }
        }
    } else {
        // D scores: D[t][s] = k_s . q_t
        int j = tid - 320;
#pragma unroll
        for (int rep=0; rep<2; rep++){
            if (j < 256){
                int t = j>>4, s = j&15;
                float acc = 0.f;
#pragma unroll
                for (int g=0;g<16;g++)
                    acc += dot4v(*(const float4*)&s_k[s*KPAD+4*g], *(const float4*)&s_q[t*KPAD+4*g]);
                Dsc[j] = acc;
            }
            j += 192;
        }
    }
    __syncthreads();
    // combine ext partials
    if (tid < 512){
        int a=tid>>7, i=(tid>>4)&7, s=tid&15;
        float* base = prjULT + a*1408;
        base[(64+i)*16+s] += extP[((a*5+0)*8+i)*16+s];
        base[(72+i)*16+s] += extP[((a*5+1)*8+i)*16+s];
        base[(80+i)*16+s] += extP[((a*5+2)*8+i)*16+s] + extP[((a*5+3)*8+i)*16+s] + extP[((a*5+4)*8+i)*16+s];
    }
    __syncthreads();

    // ---- phase 2: score matrices + yl + den ----
    for (int j=tid; j<752; j+=NT){
        if (j < 240){
            // Asc[ng][t][s] = vR_s . vrx_t (masked)
            int ng = j>>4, t = j&15;
            int pb = s_nd[ng*5+2];
            float4 a0=make_float4(0,0,0,0), a1=a0, a2=a0, a3=a0;
            if (ng < 8){
#pragma unroll
                for (int i=0;i<4;i++){
                    float w = prjXT[(pb+i)*16+t];
                    const float4* vr = (const float4*)&prjVRT[(pb+i)*16];
                    fma4(a0,w,vr[0]); fma4(a1,w,vr[1]); fma4(a2,w,vr[2]); fma4(a3,w,vr[3]);
                }
            } else {
#pragma unroll
                for (int i=0;i<8;i++){
                    float w = prjXT[(pb+i)*16+t];
                    const float4* vr = (const float4*)&prjVRT[(pb+i)*16];
                    fma4(a0,w,vr[0]); fma4(a1,w,vr[1]); fma4(a2,w,vr[2]); fma4(a3,w,vr[3]);
                }
            }
            float* dst = &Asc[(ng*16+t)*16];
            dst[0]=a0.x; dst[1]=(1<=t)?a0.y:0.f; dst[2]=(2<=t)?a0.z:0.f; dst[3]=(3<=t)?a0.w:0.f;
            dst[4]=(4<=t)?a1.x:0.f; dst[5]=(5<=t)?a1.y:0.f; dst[6]=(6<=t)?a1.z:0.f; dst[7]=(7<=t)?a1.w:0.f;
            dst[8]=(8<=t)?a2.x:0.f; dst[9]=(9<=t)?a2.y:0.f; dst[10]=(10<=t)?a2.z:0.f; dst[11]=(11<=t)?a2.w:0.f;
            dst[12]=(12<=t)?a3.x:0.f; dst[13]=(13<=t)?a3.y:0.f; dst[14]=(14<=t)?a3.z:0.f; dst[15]=(15<=t)?a3.w:0.f;
        } else if (j < 480){
            // Bsc[ng][t][s] = uL_s . vlx_t (masked)
            int jj = j-240;
            int ng = jj>>4, t = jj&15;
            int pb = s_nd[ng*5+2];
            float4 a0=make_float4(0,0,0,0), a1=a0, a2=a0, a3=a0;
            if (ng < 8){
#pragma unroll
                for (int i=0;i<4;i++){
                    float w = prjLT[(pb+i)*16+t];
                    const float4* ul = (const float4*)&prjULT[(pb+i)*16];
                    fma4(a0,w,ul[0]); fma4(a1,w,ul[1]); fma4(a2,w,ul[2]); fma4(a3,w,ul[3]);
                }
            } else {
#pragma unroll
                for (int i=0;i<8;i++){
                    float w = prjLT[(pb+i)*16+t];
                    const float4* ul = (const float4*)&prjULT[(pb+i)*16];
                    fma4(a0,w,ul[0]); fma4(a1,w,ul[1]); fma4(a2,w,ul[2]); fma4(a3,w,ul[3]);
                }
            }
            float* dst = &Bsc[(ng*16+t)*16];
            dst[0]=a0.x; dst[1]=(1<=t)?a0.y:0.f; dst[2]=(2<=t)?a0.z:0.f; dst[3]=(3<=t)?a0.w:0.f;
            dst[4]=(4<=t)?a1.x:0.f; dst[5]=(5<=t)?a1.y:0.f; dst[6]=(6<=t)?a1.z:0.f; dst[7]=(7<=t)?a1.w:0.f;
            dst[8]=(8<=t)?a2.x:0.f; dst[9]=(9<=t)?a2.y:0.f; dst[10]=(10<=t)?a2.z:0.f; dst[11]=(11<=t)?a2.w:0.f;
            dst[12]=(12<=t)?a3.x:0.f; dst[13]=(13<=t)?a3.y:0.f; dst[14]=(14<=t)?a3.z:0.f; dst[15]=(15<=t)?a3.w:0.f;
        } else if (j < 736){
            // fused leaf scores + yl: yl[4n+i][t]
            int jj = j-480;
            int n = jj>>4, t = jj&15;
            float4 qv = *(const float4*)&s_q[t*KPAD+4*n];
            float cvals[16];
#pragma unroll
            for (int s=0;s<16;s++){
                float val = dot4v(*(const float4*)&s_v[s*KPAD+4*n], qv);
                cvals[s] = (s<=t)? val : 0.f;
            }
            float acc0 = dot4v(*(const float4*)&s_leaf[(4*n+0)*4], qv);
            float acc1 = dot4v(*(const float4*)&s_leaf[(4*n+1)*4], qv);
            float acc2 = dot4v(*(const float4*)&s_leaf[(4*n+2)*4], qv);
            float acc3 = dot4v(*(const float4*)&s_leaf[(4*n+3)*4], qv);
#pragma unroll
            for (int s=0;s<16;s++){
                float4 kv = *(const float4*)&s_k[s*KPAD+4*n];
                float cs = cvals[s];
                acc0 = fmaf(kv.x, cs, acc0);
                acc1 = fmaf(kv.y, cs, acc1);
                acc2 = fmaf(kv.z, cs, acc2);
                acc3 = fmaf(kv.w, cs, acc3);
            }
            yl[(4*n+0)*17+t] = acc0;
            yl[(4*n+1)*17+t] = acc1;
            yl[(4*n+2)*17+t] = acc2;
            yl[(4*n+3)*17+t] = acc3;
        } else {
            // denominator
            int t = j-736;
            float acc = 0.f;
#pragma unroll
            for (int g=0;g<16;g++)
                acc += dot4v(*(const float4*)&s_z[4*g], *(const float4*)&s_q[t*KPAD+4*g]);
            for (int s=0;s<=t;s++) acc += Dsc[t*16+s];
            s_den[t] = fmaxf(acc, 1e-6f);
        }
    }
    __syncthreads();

    // ---- phase 3: TT / TBB ----
    for (int j=tid; j<2816; j+=NT){
        if (j < 1408){
            int i88 = j>>4, t = j&15;
            int info = lutP[i88]; int pb = info&255, ng=(info>>8)&255;
            float acc = 0.f;
            int wr = lutWT[i88];
            if (i88 < 32){
#pragma unroll
                for (int u=0;u<4;u++) acc = fmaf(s_Ws[wr+u], prjXT[(pb+u)*16+t], acc);
            } else {
#pragma unroll
                for (int u=0;u<8;u++) acc = fmaf(s_Ws[wr+u], prjXT[(pb+u)*16+t], acc);
            }
            const float4* uu = (const float4*)&prjULT[i88*16];
            const float4* aa = (const float4*)&Asc[(ng*16+t)*16];
            acc += dot4v(uu[0],aa[0]) + dot4v(uu[1],aa[1]) + dot4v(uu[2],aa[2]) + dot4v(uu[3],aa[3]);
            TT[i88*17+t] = acc;
        } else {
            int jj = j-1408;
            int i88 = jj>>4, t = jj&15;
            int info = lutP[i88]; int pb = info&255, ng=(info>>8)&255;
            float acc = 0.f;
            int wc = lutWB[i88];
            if (i88 < 32){
#pragma unroll
                for (int u=0;u<4;u++) acc = fmaf(s_Ws[wc+u*4], prjLT[(pb+u)*16+t], acc);
            } else {
#pragma unroll
                for (int u=0;u<8;u++) acc = fmaf(s_Ws[wc+u*8], prjLT[(pb+u)*16+t], acc);
            }
            const float4* vv = (const float4*)&prjVRT[i88*16];
            const float4* bb = (const float4*)&Bsc[(ng*16+t)*16];
            acc += dot4v(vv[0],bb[0]) + dot4v(vv[1],bb[1]) + dot4v(vv[2],bb[2]) + dot4v(vv[3],bb[3]);
            TBB[i88*17+t] = acc;
        }
    }
    __syncthreads();

    // ---- phase 4: final assembly ----
    for (int j=tid; j<1024; j+=NT){
        int d = j&63, t = j>>6;
        float y = yl[d*17+t];
#pragma unroll
        for (int l=0;l<4;l++){
            const int bs = 4<<l;
            const int r  = (l==0)?4:8;
            const int n = d >> (3+l);
            const int loc = d & (2*bs - 1);
            const int pb = Knro(l) + n*r;
            const int bso = Kbso(l);
            if (loc < bs){
                const float* u = sUL + bso + loc*r;
#pragma unroll
                for (int i=0;i<8;i++){
                    if (i < r) y = fmaf(u[i], TT[(pb+i)*17+t], y);
                }
            } else {
                const float* u = sUR + bso + (loc-bs)*r;
#pragma unroll
                for (int i=0;i<8;i++){
                    if (i < r) y = fmaf(u[i], TBB[(pb+i)*17+t], y);
                }
            }
        }
        g_o[(size_t)t*DH + d] = y / s_den[t];
    }
}

// ---------------- output GEMM: att(16384x64) @ Wo(64x1024) ----------------
__global__ __launch_bounds__(256) void wo_kernel(const float* __restrict__ Wo,
                                                 float* __restrict__ out){
    __shared__ float As[64][64];
    __shared__ float Bs[64][64];
    const int tid = threadIdx.x;
    const int rb = blockIdx.x*64, cbase = blockIdx.y*256;
#pragma unroll
    for(int i=0;i<4;i++){
        int idx = tid + i*256;
        int row = idx >> 4, g = idx & 15;
        float4 av = *(const float4*)(g_att + (size_t)(rb+row)*DH + g*4);
        *(float4*)&As[row][g*4] = av;
    }
    const int ty = tid >> 4, tx = tid & 15;
    for(int sub=0; sub<4; sub++){
        const int cbk = cbase + sub*64;
        __syncthreads();
#pragma unroll
        for(int i=0;i<4;i++){
            int idx = tid + i*256;
            int row = idx >> 4, g = idx & 15;
            float4 bv = *(const float4*)(Wo + (size_t)row*DM + cbk + g*4);
            *(float4*)&Bs[row][g*4] = bv;
        }
        __syncthreads();
        unsigned long long acc[4][2];
#pragma unroll
        for(int i=0;i<4;i++){ acc[i][0]=0ULL; acc[i][1]=0ULL; }
        for(int kk=0;kk<64;kk++){
            float a0 = As[ty*4+0][kk];
            float a1 = As[ty*4+1][kk];
            float a2 = As[ty*4+2][kk];
            float a3 = As[ty*4+3][kk];
            const unsigned long long* bpp = (const unsigned long long*)&Bs[kk][tx*4];
            unsigned long long b0 = bpp[0], b1 = bpp[1];
            unsigned long long ap;
            ap = pack2(a0,a0); fma2(acc[0][0],ap,b0); fma2(acc[0][1],ap,b1);
            ap = pack2(a1,a1); fma2(acc[1][0],ap,b0); fma2(acc[1][1],ap,b1);
            ap = pack2(a2,a2); fma2(acc[2][0],ap,b0); fma2(acc[2][1],ap,b1);
            ap = pack2(a3,a3); fma2(acc[3][0],ap,b0); fma2(acc[3][1],ap,b1);
        }
#pragma unroll
        for(int i=0;i<4;i++){
            float4 ov;
            unpack2(acc[i][0], ov.x, ov.y);
            unpack2(acc[i][1], ov.z, ov.w);
            *(float4*)(out + (size_t)(rb+ty*4+i)*DM + cbk + tx*4) = ov;
        }
    }
}

extern "C" void kernel_launch(void* const* d_in, const int* in_sizes, int n_in,
                              void* d_out, int out_size){
    (void)in_sizes; (void)n_in; (void)out_size;
    const float* x  = (const float*)d_in[0];
    const float* Wq = (const float*)d_in[1];
    const float* Wk = (const float*)d_in[2];
    const float* Wv = (const float*)d_in[3];
    const float* Wo = (const float*)d_in[4];
    BasePtrs bp;
    for(int i=0;i<16;i++) bp.p[i] = (const float*)d_in[5+i];
    float* out = (float*)d_out;

    cudaFuncSetAttribute(chunk_sum_kernel,  cudaFuncAttributeMaxDynamicSharedMemorySize, P1_BYTES);
    cudaFuncSetAttribute(chunk_scan_kernel, cudaFuncAttributeMaxDynamicSharedMemorySize, P3_BYTES);

    qkv_kernel<<<NTOK/64, 256>>>(x, Wq, Wk, Wv);
    chunk_sum_kernel<<<BB*NCH, NT, P1_BYTES>>>(bp);
    prefix_kernel<<<dim3(NST/128, BB), 128>>>();
    chunk_scan_kernel<<<BB*NCH, NT, P3_BYTES>>>(bp);
    wo_kernel<<<dim3(NTOK/64, DM/256), 256>>>(Wo, out);
}

// round 6
// speedup vs baseline: 52.0590x; 1.4362x over previous
#include <cuda_runtime.h>
#include <cuda_bf16.h>
#include <math.h>

#define TSEQ 2048
#define BB 8
#define DH 64
#define DM 1024
#define NTOK (BB*TSEQ)
#define CCH 16
#define NCH (TSEQ/CCH)   /* 128 */
#define NST 896
#define KPAD 68
#define NT 512
#define NW 192           /* qkv output cols */

// scratch (device globals -- no allocation allowed)
__device__ float g_q[NTOK*DH];
__device__ float g_k[NTOK*DH];
__device__ float g_v[NTOK*DH];
__device__ float g_att[NTOK*DH];
__device__ float g_state[BB*NCH*NST];
__device__ float g_prefix[BB*NCH*NST];
__device__ __nv_bfloat16 g_wh[DM*NW];
__device__ __nv_bfloat16 g_wl[DM*NW];

struct BasePtrs { const float* p[16]; }; // UL0-3, VR0-3, UR0-3, VL0-3

// ---------------- helpers ----------------
__device__ __forceinline__ unsigned long long pack2(float lo, float hi){
    unsigned long long r;
    asm("mov.b64 %0, {%1,%2};" : "=l"(r) : "f"(lo), "f"(hi));
    return r;
}
__device__ __forceinline__ void unpack2(unsigned long long v, float &lo, float &hi){
    asm("mov.b64 {%0,%1}, %2;" : "=f"(lo), "=f"(hi) : "l"(v));
}
__device__ __forceinline__ void fma2(unsigned long long &d, unsigned long long a, unsigned long long b){
    asm("fma.rn.f32x2 %0, %1, %2, %3;" : "=l"(d) : "l"(a), "l"(b), "l"(d));
}
__device__ __forceinline__ void cp_async16(void* sptr, const void* gptr){
    unsigned s = (unsigned)__cvta_generic_to_shared(sptr);
    asm volatile("cp.async.ca.shared.global [%0], [%1], 16;" :: "r"(s), "l"(gptr));
}
__device__ __forceinline__ float dot4v(float4 a, float4 b){
    return fmaf(a.x,b.x, fmaf(a.y,b.y, fmaf(a.z,b.z, a.w*b.w)));
}
__device__ __forceinline__ void fma4(float4 &acc, float s, float4 v){
    acc.x = fmaf(s, v.x, acc.x); acc.y = fmaf(s, v.y, acc.y);
    acc.z = fmaf(s, v.z, acc.z); acc.w = fmaf(s, v.w, acc.w);
}
__device__ __forceinline__ unsigned smem_u32(const void* p){
    return (unsigned)__cvta_generic_to_shared(p);
}
__device__ __forceinline__ void ldmx4(unsigned &r0, unsigned &r1, unsigned &r2, unsigned &r3, const void* p){
    asm volatile("ldmatrix.sync.aligned.m8n8.x4.shared.b16 {%0,%1,%2,%3}, [%4];"
        : "=r"(r0),"=r"(r1),"=r"(r2),"=r"(r3) : "r"(smem_u32(p)));
}
__device__ __forceinline__ void ldmx4t(unsigned &r0, unsigned &r1, unsigned &r2, unsigned &r3, const void* p){
    asm volatile("ldmatrix.sync.aligned.m8n8.x4.trans.shared.b16 {%0,%1,%2,%3}, [%4];"
        : "=r"(r0),"=r"(r1),"=r"(r2),"=r"(r3) : "r"(smem_u32(p)));
}
__device__ __forceinline__ void mma16816(float* c, unsigned a0,unsigned a1,unsigned a2,unsigned a3,
                                         unsigned b0, unsigned b1){
    asm volatile("mma.sync.aligned.m16n8k16.row.col.f32.bf16.bf16.f32 "
        "{%0,%1,%2,%3}, {%4,%5,%6,%7}, {%8,%9}, {%0,%1,%2,%3};"
        : "+f"(c[0]),"+f"(c[1]),"+f"(c[2]),"+f"(c[3])
        : "r"(a0),"r"(a1),"r"(a2),"r"(a3),"r"(b0),"r"(b1));
}

__device__ __forceinline__ int Knro(int l){ return (l==0)?0:(l==1)?32:(l==2)?64:80; }
__device__ __forceinline__ int Kwso(int l){ return (l==0)?0:(l==1)?128:(l==2)?384:512; }
__device__ __forceinline__ int Kbso(int l){ return (l==0)?0:(l==1)?16:(l==2)?80:208; }
__device__ __forceinline__ int Knoff(int l){ return (l==0)?0:(l==1)?8:(l==2)?12:14; }

// ---------------- weight split prep: [Wq|Wk|Wv] -> bf16 hi/lo ----------------
__global__ __launch_bounds__(256) void wprep_kernel(const float* __restrict__ Wq,
                                                    const float* __restrict__ Wk,
                                                    const float* __restrict__ Wv){
    int idx = blockIdx.x*256 + threadIdx.x;        // 0 .. 196607
    int k = idx / NW, n = idx - k*NW;
    const float* W = (n<64)?Wq:(n<128?Wk:Wv);
    float w = W[(size_t)k*DH + (n&63)];
    __nv_bfloat16 hi = __float2bfloat16(w);
    float lo = w - __bfloat162float(hi);
    g_wh[idx] = hi;
    g_wl[idx] = __float2bfloat16(lo);
}

// ---------------- QKV via mma.sync bf16x3 ----------------
// block: 64 rows x 192 cols, 256 threads (8 warps, 4x2), K=1024 in 16-steps.
#define ASTR 24
#define BSTR 200
__global__ __launch_bounds__(256) void qkv_mma_kernel(const float* __restrict__ x){
    __shared__ __nv_bfloat16 sAh[2][64*ASTR];
    __shared__ __nv_bfloat16 sAl[2][64*ASTR];
    __shared__ __nv_bfloat16 sBh[2][16*BSTR];
    __shared__ __nv_bfloat16 sBl[2][16*BSTR];

    const int tid = threadIdx.x;
    const int wid = tid >> 5, lane = tid & 31;
    const int wy = wid & 3, wx = wid >> 2;
    const int rb = blockIdx.x * 64;
    const int arow = tid >> 2, akg = tid & 3;

    float acc[12][4];
#pragma unroll
    for (int i=0;i<12;i++){ acc[i][0]=acc[i][1]=acc[i][2]=acc[i][3]=0.f; }

    // ---- stage loaders ----
    auto loadB = [&](int k0, int buf){
#pragma unroll
        for (int i=0;i<3;i++){
            int idx = tid + i*256;                  // 0..767
            int m2 = (idx >= 384);
            int id2 = idx - m2*384;
            int r = id2 / 24, c8 = id2 - r*24;
            const __nv_bfloat16* src = (m2 ? g_wl : g_wh) + (size_t)(k0+r)*NW + c8*8;
            __nv_bfloat16* dst = (m2 ? sBl[buf] : sBh[buf]) + r*BSTR + c8*8;
            cp_async16(dst, src);
        }
    };
    auto storeA = [&](float4 v, int buf){
        __nv_bfloat16 h0=__float2bfloat16(v.x), h1=__float2bfloat16(v.y),
                      h2=__float2bfloat16(v.z), h3=__float2bfloat16(v.w);
        float l0 = v.x-__bfloat162float(h0), l1 = v.y-__bfloat162float(h1),
              l2 = v.z-__bfloat162float(h2), l3 = v.w-__bfloat162float(h3);
        __nv_bfloat162 hh0 = __halves2bfloat162(h0,h1), hh1 = __halves2bfloat162(h2,h3);
        __nv_bfloat162 ll0 = __floats2bfloat162_rn(l0,l1), ll1 = __floats2bfloat162_rn(l2,l3);
        uint2 hu = make_uint2(*(unsigned*)&hh0, *(unsigned*)&hh1);
        uint2 lu = make_uint2(*(unsigned*)&ll0, *(unsigned*)&ll1);
        *(uint2*)&sAh[buf][arow*ASTR + akg*4] = hu;
        *(uint2*)&sAl[buf][arow*ASTR + akg*4] = lu;
    };

    // preload stage 0
    float4 av = *(const float4*)(x + (size_t)(rb+arow)*DM + akg*4);
    loadB(0, 0);
    asm volatile("cp.async.commit_group;\n");
    storeA(av, 0);
    asm volatile("cp.async.wait_group 0;\n");
    __syncthreads();

    const int a_off = (wy*16 + (lane&15))*ASTR + (lane>>4)*8;
    const int b_off = (lane&15)*BSTR + wx*96 + (lane>>4)*8;

    for (int kt=0; kt<64; kt++){
        const int buf = kt & 1;
        if (kt < 63){
            int k0 = (kt+1)*16;
            av = *(const float4*)(x + (size_t)(rb+arow)*DM + k0 + akg*4);
            loadB(k0, buf^1);
            asm volatile("cp.async.commit_group;\n");
        }
        unsigned ah0,ah1,ah2,ah3, al0,al1,al2,al3;
        ldmx4(ah0,ah1,ah2,ah3, sAh[buf] + a_off);
        ldmx4(al0,al1,al2,al3, sAl[buf] + a_off);
#pragma unroll
        for (int nb=0; nb<6; nb++){
            unsigned bh0,bh1,bh2,bh3, bl0,bl1,bl2,bl3;
            ldmx4t(bh0,bh1,bh2,bh3, sBh[buf] + b_off + nb*16);
            ldmx4t(bl0,bl1,bl2,bl3, sBl[buf] + b_off + nb*16);
            mma16816(acc[2*nb],   ah0,ah1,ah2,ah3, bh0,bh1);
            mma16816(acc[2*nb],   ah0,ah1,ah2,ah3, bl0,bl1);
            mma16816(acc[2*nb],   al0,al1,al2,al3, bh0,bh1);
            mma16816(acc[2*nb+1], ah0,ah1,ah2,ah3, bh2,bh3);
            mma16816(acc[2*nb+1], ah0,ah1,ah2,ah3, bl2,bl3);
            mma16816(acc[2*nb+1], al0,al1,al2,al3, bh2,bh3);
        }
        __syncthreads();
        if (kt < 63){
            storeA(av, buf^1);
            asm volatile("cp.async.wait_group 0;\n");
            __syncthreads();
        }
    }

    // epilogue: elu1 on cols<128, scatter to g_q/g_k/g_v
    const int row0 = rb + wy*16 + (lane>>2);
#pragma unroll
    for (int t=0; t<12; t++){
        int col = wx*96 + t*8 + (lane&3)*2;
        bool act = (col < 128);
        float* base = (col < 64) ? g_q : (col < 128 ? g_k : g_v);
        int cc = col & 63;
        float v0 = acc[t][0], v1 = acc[t][1], v2 = acc[t][2], v3 = acc[t][3];
        if (act){
            v0 = (v0>0.f)? v0+1.f : expf(v0);
            v1 = (v1>0.f)? v1+1.f : expf(v1);
            v2 = (v2>0.f)? v2+1.f : expf(v2);
            v3 = (v3>0.f)? v3+1.f : expf(v3);
        }
        base[(size_t)row0*DH + cc]       = v0;
        base[(size_t)row0*DH + cc + 1]   = v1;
        base[(size_t)(row0+8)*DH + cc]   = v2;
        base[(size_t)(row0+8)*DH + cc+1] = v3;
    }
}

// =====================================================================
// shared LUT builders
// =====================================================================
__device__ __forceinline__ void build_node_lut(int* s_nd, int tid){
    if (tid < 15){
        int l = (tid<8)?0:(tid<12)?1:(tid<14)?2:3;
        int n = tid - Knoff(l);
        int bs = 4<<l, r = (l==0)?4:8;
        s_nd[tid*5+0]=bs; s_nd[tid*5+1]=r; s_nd[tid*5+2]=Knro(l)+n*r;
        s_nd[tid*5+3]=2*bs*n; s_nd[tid*5+4]=Kbso(l);
    }
}
__device__ __forceinline__ void build_ws_lut(int* s_lutAB, int tid, int nthr){
    for (int m = tid; m < 576; m += nthr){
        int l = (m<128)?0:(m<384)?1:(m<512)?2:3;
        int r = (l==0)?4:8;
        int rem = m - Kwso(l);
        int rr2 = r*r;
        int n = rem / rr2;
        int ij = rem - n*rr2;
        int i = ij / r, j = ij - i*r;
        int pb = Knro(l) + n*r;
        s_lutAB[m] = (pb+i) | ((pb+j)<<16);
    }
}
__device__ __forceinline__ void build_chunk_lut(int* s_ck, int tid){
    if (tid < 20){
        int c = tid, m, dd0=0, ext=0, ec=0;
        if (c < 13){ m = c; }
        else if (c == 13){ m=12; dd0=8; ext=1; ec=0; }
        else if (c == 14){ m=13; }
        else if (c == 15){ m=13; dd0=8; ext=1; ec=1; }
        else if (c == 16){ m=14; }
        else { m=14; dd0=8*(c-16); ext=1; ec=c-15; }
        s_ck[c] = m | (dd0<<8) | (ext<<16) | (ec<<20);
    }
}

// =====================================================================
// Pass 1: per-chunk state sums
// =====================================================================
#define P1_FLOATS (2176 + 2816 + 928 + 1280)
#define P1_BYTES (P1_FLOATS*4 + (75+576+20)*4)
__global__ __launch_bounds__(512,2) void chunk_sum_kernel(BasePtrs bp){
    extern __shared__ float sm[];
    float* s_k    = sm;
    float* s_v    = s_k + 16*KPAD;
    float* prjULT = s_v + 16*KPAD;
    float* prjVRT = prjULT + 1408;
    float* sUL    = prjVRT + 1408;
    float* sVR    = sUL + 464;
    float* extP   = sVR + 464;
    int*   s_nd   = (int*)(extP + 1280);
    int*   lutAB  = s_nd + 75;
    int*   s_ck   = lutAB + 576;

    const int tid = threadIdx.x;
    const int blk = blockIdx.x;
    const int b = blk / NCH, c = blk % NCH;
    const float* gk = g_k + ((size_t)b*TSEQ + c*CCH)*DH;
    const float* gv = g_v + ((size_t)b*TSEQ + c*CCH)*DH;

    for (int i=tid;i<464;i+=NT){
        int l = (i<16)?0:(i<80)?1:(i<208)?2:3;
        int off = i - Kbso(l);
        sUL[i] = bp.p[l][off];
        sVR[i] = bp.p[4+l][off];
    }
    for (int i=tid;i<512;i+=NT){
        int arr = i>>8;
        int rem = i & 255; int row = rem>>4, g = rem&15;
        const float* src = (arr==0?gk:gv) + row*64 + g*4;
        float* dst = (arr==0?s_k:s_v) + row*KPAD + g*4;
        *(float4*)dst = *(const float4*)src;
    }
    build_node_lut(s_nd, tid);
    build_ws_lut(lutAB, tid, NT);
    build_chunk_lut(s_ck, tid);
    __syncthreads();

    if (tid < 320){
        int cd = s_ck[tid>>4]; int s = tid&15;
        int m = cd & 31, dd0 = (cd>>8)&63, isext=(cd>>16)&1, ec=(cd>>20)&7;
        int bs=s_nd[m*5], r=s_nd[m*5+1], pb=s_nd[m*5+2], topo=s_nd[m*5+3], bso=s_nd[m*5+4];
        const float* kt = s_k + s*KPAD + topo + dd0;
        const float* vb = s_v + s*KPAD + topo + bs + dd0;
        const float* Ub = sUL + bso + dd0*r;
        const float* Wb = sVR + bso + dd0*r;
        if (r == 4){
            float4 aU=make_float4(0,0,0,0), aV=aU;
#pragma unroll
            for (int d=0; d<4; d++){
                float kd=kt[d], vd=vb[d];
                float4 u=*(const float4*)(Ub+d*4), w=*(const float4*)(Wb+d*4);
                fma4(aU,kd,u); fma4(aV,vd,w);
            }
            float au[4]={aU.x,aU.y,aU.z,aU.w}, avv[4]={aV.x,aV.y,aV.z,aV.w};
#pragma unroll
            for (int i=0;i<4;i++){
                prjULT[(pb+i)*16+s]=au[i];
                prjVRT[(pb+i)*16+s]=avv[i];
            }
        } else {
            float aU[8], aV[8];
#pragma unroll
            for (int i=0;i<8;i++){ aU[i]=0.f; aV[i]=0.f; }
#pragma unroll
            for (int d=0; d<8; d++){
                float kd=kt[d], vd=vb[d];
                float4 u0=*(const float4*)(Ub+d*8), u1=*(const float4*)(Ub+d*8+4);
                float4 w0=*(const float4*)(Wb+d*8), w1=*(const float4*)(Wb+d*8+4);
                aU[0]=fmaf(kd,u0.x,aU[0]); aU[1]=fmaf(kd,u0.y,aU[1]); aU[2]=fmaf(kd,u0.z,aU[2]); aU[3]=fmaf(kd,u0.w,aU[3]);
                aU[4]=fmaf(kd,u1.x,aU[4]); aU[5]=fmaf(kd,u1.y,aU[5]); aU[6]=fmaf(kd,u1.z,aU[6]); aU[7]=fmaf(kd,u1.w,aU[7]);
                aV[0]=fmaf(vd,w0.x,aV[0]); aV[1]=fmaf(vd,w0.y,aV[1]); aV[2]=fmaf(vd,w0.z,aV[2]); aV[3]=fmaf(vd,w0.w,aV[3]);
                aV[4]=fmaf(vd,w1.x,aV[4]); aV[5]=fmaf(vd,w1.y,aV[5]); aV[6]=fmaf(vd,w1.z,aV[6]); aV[7]=fmaf(vd,w1.w,aV[7]);
            }
            if (!isext){
#pragma unroll
                for (int i=0;i<8;i++){
                    prjULT[(pb+i)*16+s]=aU[i];
                    prjVRT[(pb+i)*16+s]=aV[i];
                }
            } else {
#pragma unroll
                for (int i=0;i<8;i++){
                    extP[((0*5+ec)*8+i)*16+s]=aU[i];
                    extP[((1*5+ec)*8+i)*16+s]=aV[i];
                }
            }
        }
    }
    __syncthreads();
    if (tid < 256){
        int a=tid>>7, i=(tid>>4)&7, s=tid&15;
        float* base = prjULT + a*1408;
        base[(64+i)*16+s] += extP[((a*5+0)*8+i)*16+s];
        base[(72+i)*16+s] += extP[((a*5+1)*8+i)*16+s];
        base[(80+i)*16+s] += extP[((a*5+2)*8+i)*16+s] + extP[((a*5+3)*8+i)*16+s] + extP[((a*5+4)*8+i)*16+s];
    }
    __syncthreads();

    float* go = g_state + (size_t)blk*NST;
    for (int e=tid; e<NST; e+=NT){
        float acc = 0.f;
        if (e < 256){
            int n=e>>4, i=(e>>2)&3, j2=e&3;
            int ki=4*n+i, vi=4*n+j2;
#pragma unroll
            for (int s=0;s<CCH;s++) acc = fmaf(s_k[s*KPAD+ki], s_v[s*KPAD+vi], acc);
        } else if (e < 832){
            int m = e-256;
            int ab = lutAB[m]; int a = ab & 0xffff, b3 = ab >> 16;
            const float4* pa = (const float4*)&prjULT[a*16];
            const float4* pb4 = (const float4*)&prjVRT[b3*16];
#pragma unroll
            for (int g=0;g<4;g++) acc += dot4v(pa[g], pb4[g]);
        } else {
            int d = e-832;
#pragma unroll
            for (int s=0;s<CCH;s++) acc += s_k[s*KPAD+d];
        }
        go[e] = acc;
    }
}

// =====================================================================
// Pass 2: exclusive prefix over chunks
// =====================================================================
__global__ __launch_bounds__(128) void prefix_kernel(){
    const int b = blockIdx.y;
    const int e = blockIdx.x*128 + threadIdx.x;
    const float* gs = g_state  + (size_t)b*NCH*NST + e;
    float*       gp = g_prefix + (size_t)b*NCH*NST + e;
    float run = 0.f;
    for (int c0=0;c0<NCH;c0+=8){
        float v[8];
#pragma unroll
        for (int j=0;j<8;j++) v[j] = gs[(size_t)(c0+j)*NST];
#pragma unroll
        for (int j=0;j<8;j++){ gp[(size_t)(c0+j)*NST] = run; run += v[j]; }
    }
}

// =====================================================================
// Pass 3: fully parallel intra-chunk attention, 512 threads
// =====================================================================
#define P3_FLOATS (3264 + 5632 + 1856 + 896 + 3840 + 3840 + 2560 + 256 + 16 + 1496 + 1496 + 1088)
#define P3_BYTES (P3_FLOATS*4 + (75 + 88*3 + 20)*4)
__global__ __launch_bounds__(512,2) void chunk_scan_kernel(BasePtrs bp){
    extern __shared__ float sm[];
    float* s_k    = sm;
    float* s_v    = s_k + 16*KPAD;
    float* s_q    = s_v + 16*KPAD;
    float* prjULT = s_q + 16*KPAD;
    float* prjVRT = prjULT + 1408;
    float* prjXT  = prjVRT + 1408;
    float* prjLT  = prjXT + 1408;
    float* sUL    = prjLT + 1408;
    float* sVR    = sUL + 464;
    float* sUR    = sVR + 464;
    float* sVL    = sUR + 464;
    float* s_leaf = sVL + 464;
    float* s_Ws   = s_leaf + 256;
    float* s_z    = s_Ws + 576;
    float* Asc    = s_z + 64;
    float* Bsc    = Asc + 3840;
    float* extP   = Bsc + 3840;
    float* Dsc    = extP + 2560;
    float* s_den  = Dsc + 256;
    float* TT     = s_den + 16;
    float* TBB    = TT + 1496;
    float* yl     = TBB + 1496;
    int*   s_nd   = (int*)(yl + 1088);
    int*   lutP   = s_nd + 75;
    int*   lutWT  = lutP + 88;
    int*   lutWB  = lutWT + 88;
    int*   s_ck   = lutWB + 88;

    const int tid = threadIdx.x;
    const int blk = blockIdx.x;
    const int b = blk / NCH, c = blk % NCH;
    const float* gk = g_k + ((size_t)b*TSEQ + c*CCH)*DH;
    const float* gv = g_v + ((size_t)b*TSEQ + c*CCH)*DH;
    const float* gq = g_q + ((size_t)b*TSEQ + c*CCH)*DH;
    float* g_o      = g_att + ((size_t)b*TSEQ + c*CCH)*DH;

    for (int i=tid;i<464;i+=NT){
        int l = (i<16)?0:(i<80)?1:(i<208)?2:3;
        int off = i - Kbso(l);
        sUL[i] = bp.p[l   ][off];
        sVR[i] = bp.p[4+l ][off];
        sUR[i] = bp.p[8+l ][off];
        sVL[i] = bp.p[12+l][off];
    }
    for (int i=tid;i<768;i+=NT){
        int arr = i>>8;
        int rem = i & 255; int row = rem>>4, g = rem&15;
        const float* src = (arr==0?gk:(arr==1?gv:gq)) + row*64 + g*4;
        float* dst = (arr==0?s_k:(arr==1?s_v:s_q)) + row*KPAD + g*4;
        *(float4*)dst = *(const float4*)src;
    }
    {
        const float* gp = g_prefix + (size_t)blk*NST;
        for (int e=tid;e<NST;e+=NT){
            float vle = gp[e];
            if (e<256) s_leaf[e]=vle;
            else if (e<832) s_Ws[e-256]=vle;
            else s_z[e-832]=vle;
        }
    }
    build_node_lut(s_nd, tid);
    build_chunk_lut(s_ck, tid);
    if (tid < 88){
        int i88 = tid;
        int l = (i88<32)?0:(i88<64)?1:(i88<80)?2:3;
        int r = (l==0)?4:8;
        int rem = i88 - Knro(l);
        int n = rem / r, i = rem - n*r;
        int pb = Knro(l) + n*r;
        int ng = Knoff(l) + n;
        lutP[i88]  = pb | (ng<<8) | (r<<16);
        lutWT[i88] = Kwso(l) + n*r*r + i*r;
        lutWB[i88] = Kwso(l) + n*r*r + i;
    }
    __syncthreads();

    if (tid < 320){
        int cd = s_ck[tid>>4]; int s = tid&15;
        int m = cd & 31, dd0 = (cd>>8)&63, isext=(cd>>16)&1, ec=(cd>>20)&7;
        int bs=s_nd[m*5], r=s_nd[m*5+1], pb=s_nd[m*5+2], topo=s_nd[m*5+3], bso=s_nd[m*5+4];
        const float* kt = s_k + s*KPAD + topo + dd0;
        const float* vb = s_v + s*KPAD + topo + bs + dd0;
        const float* qt = s_q + s*KPAD + topo + dd0;
        const float* qb = s_q + s*KPAD + topo + bs + dd0;
        const float* Ub = sUL + bso + dd0*r;
        const float* Wb = sVR + bso + dd0*r;
        const float* Xb = sVL + bso + dd0*r;
        if (r == 4){
            float4 aU=make_float4(0,0,0,0), aV=aU, aX=aU, aL=aU;
#pragma unroll
            for (int d=0; d<4; d++){
                float kd=kt[d], vd=vb[d], qtd=qt[d], qbd=qb[d];
                float4 u=*(const float4*)(Ub+d*4), w=*(const float4*)(Wb+d*4), x=*(const float4*)(Xb+d*4);
                fma4(aU,kd,u); fma4(aV,vd,w); fma4(aX,qbd,w); fma4(aL,qtd,x);
            }
            float t0[4]={aU.x,aU.y,aU.z,aU.w}, t1[4]={aV.x,aV.y,aV.z,aV.w};
            float t2[4]={aX.x,aX.y,aX.z,aX.w}, t3[4]={aL.x,aL.y,aL.z,aL.w};
#pragma unroll
            for (int i=0;i<4;i++){
                prjULT[(pb+i)*16+s]=t0[i];
                prjVRT[(pb+i)*16+s]=t1[i];
                prjXT [(pb+i)*16+s]=t2[i];
                prjLT [(pb+i)*16+s]=t3[i];
            }
        } else {
            {
                float aU[8], aV[8];
#pragma unroll
                for (int i=0;i<8;i++){ aU[i]=0.f; aV[i]=0.f; }
#pragma unroll
                for (int d=0; d<8; d++){
                    float kd=kt[d], vd=vb[d];
                    float4 u0=*(const float4*)(Ub+d*8), u1=*(const float4*)(Ub+d*8+4);
                    float4 w0=*(const float4*)(Wb+d*8), w1=*(const float4*)(Wb+d*8+4);
                    aU[0]=fmaf(kd,u0.x,aU[0]); aU[1]=fmaf(kd,u0.y,aU[1]); aU[2]=fmaf(kd,u0.z,aU[2]); aU[3]=fmaf(kd,u0.w,aU[3]);
                    aU[4]=fmaf(kd,u1.x,aU[4]); aU[5]=fmaf(kd,u1.y,aU[5]); aU[6]=fmaf(kd,u1.z,aU[6]); aU[7]=fmaf(kd,u1.w,aU[7]);
                    aV[0]=fmaf(vd,w0.x,aV[0]); aV[1]=fmaf(vd,w0.y,aV[1]); aV[2]=fmaf(vd,w0.z,aV[2]); aV[3]=fmaf(vd,w0.w,aV[3]);
                    aV[4]=fmaf(vd,w1.x,aV[4]); aV[5]=fmaf(vd,w1.y,aV[5]); aV[6]=fmaf(vd,w1.z,aV[6]); aV[7]=fmaf(vd,w1.w,aV[7]);
                }
                if (!isext){
#pragma unroll
                    for (int i=0;i<8;i++){ prjULT[(pb+i)*16+s]=aU[i]; prjVRT[(pb+i)*16+s]=aV[i]; }
                } else {
#pragma unroll
                    for (int i=0;i<8;i++){
                        extP[((0*5+ec)*8+i)*16+s]=aU[i];
                        extP[((1*5+ec)*8+i)*16+s]=aV[i];
                    }
                }
            }
            {
                float aX[8], aL[8];
#pragma unroll
                for (int i=0;i<8;i++){ aX[i]=0.f; aL[i]=0.f; }
#pragma unroll
                for (int d=0; d<8; d++){
                    float qbd=qb[d], qtd=qt[d];
                    float4 w0=*(const float4*)(Wb+d*8), w1=*(const float4*)(Wb+d*8+4);
                    float4 x0=*(const float4*)(Xb+d*8), x1=*(const float4*)(Xb+d*8+4);
                    aX[0]=fmaf(qbd,w0.x,aX[0]); aX[1]=fmaf(qbd,w0.y,aX[1]); aX[2]=fmaf(qbd,w0.z,aX[2]); aX[3]=fmaf(qbd,w0.w,aX[3]);
                    aX[4]=fmaf(qbd,w1.x,aX[4]); aX[5]=fmaf(qbd,w1.y,aX[5]); aX[6]=fmaf(qbd,w1.z,aX[6]); aX[7]=fmaf(qbd,w1.w,aX[7]);
                    aL[0]=fmaf(qtd,x0.x,aL[0]); aL[1]=fmaf(qtd,x0.y,aL[1]); aL[2]=fmaf(qtd,x0.z,aL[2]); aL[3]=fmaf(qtd,x0.w,aL[3]);
                    aL[4]=fmaf(qtd,x1.x,aL[4]); aL[5]=fmaf(qtd,x1.y,aL[5]); aL[6]=fmaf(qtd,x1.z,aL[6]); aL[7]=fmaf(qtd,x1.w,aL[7]);
                }
                if (!isext){
#pragma unroll
                    for (int i=0;i<8;i++){ prjXT[(pb+i)*16+s]=aX[i]; prjLT[(pb+i)*16+s]=aL[i]; }
                } else {
#pragma unroll
                    for (int i=0;i<8;i++){
                        extP[((2*5+ec)*8+i)*16+s]=aX[i];
                        extP[((3*5+ec)*8+i)*16+s]=aL[i];
                    }
                }
            }
        }
    } else {
        int j = tid - 320;
#pragma unroll
        for (int rep=0; rep<2; rep++){
            if (j < 256){
                int t = j>>4, s = j&15;
                float acc = 0.f;
#pragma unroll
                for (int g=0;g<16;g++)
                    acc += dot4v(*(const float4*)&s_k[s*KPAD+4*g], *(const float4*)&s_q[t*KPAD+4*g]);
                Dsc[j] = acc;
            }
            j += 192;
        }
    }
    __syncthreads();
    if (tid < 512){
        int a=tid>>7, i=(tid>>4)&7, s=tid&15;
        float* base = prjULT + a*1408;
        base[(64+i)*16+s] += extP[((a*5+0)*8+i)*16+s];
        base[(72+i)*16+s] += extP[((a*5+1)*8+i)*16+s];
        base[(80+i)*16+s] += extP[((a*5+2)*8+i)*16+s] + extP[((a*5+3)*8+i)*16+s] + extP[((a*5+4)*8+i)*16+s];
    }
    __syncthreads();

    for (int j=tid; j<752; j+=NT){
        if (j < 240){
            int ng = j>>4, t = j&15;
            int pb = s_nd[ng*5+2];
            float4 a0=make_float4(0,0,0,0), a1=a0, a2=a0, a3=a0;
            if (ng < 8){
#pragma unroll
                for (int i=0;i<4;i++){
                    float w = prjXT[(pb+i)*16+t];
                    const float4* vr = (const float4*)&prjVRT[(pb+i)*16];
                    fma4(a0,w,vr[0]); fma4(a1,w,vr[1]); fma4(a2,w,vr[2]); fma4(a3,w,vr[3]);
                }
            } else {
#pragma unroll
                for (int i=0;i<8;i++){
                    float w = prjXT[(pb+i)*16+t];
                    const float4* vr = (const float4*)&prjVRT[(pb+i)*16];
                    fma4(a0,w,vr[0]); fma4(a1,w,vr[1]); fma4(a2,w,vr[2]); fma4(a3,w,vr[3]);
                }
            }
            float* dst = &Asc[(ng*16+t)*16];
            dst[0]=a0.x; dst[1]=(1<=t)?a0.y:0.f; dst[2]=(2<=t)?a0.z:0.f; dst[3]=(3<=t)?a0.w:0.f;
            dst[4]=(4<=t)?a1.x:0.f; dst[5]=(5<=t)?a1.y:0.f; dst[6]=(6<=t)?a1.z:0.f; dst[7]=(7<=t)?a1.w:0.f;
            dst[8]=(8<=t)?a2.x:0.f; dst[9]=(9<=t)?a2.y:0.f; dst[10]=(10<=t)?a2.z:0.f; dst[11]=(11<=t)?a2.w:0.f;
            dst[12]=(12<=t)?a3.x:0.f; dst[13]=(13<=t)?a3.y:0.f; dst[14]=(14<=t)?a3.z:0.f; dst[15]=(15<=t)?a3.w:0.f;
        } else if (j < 480){
            int jj = j-240;
            int ng = jj>>4, t = jj&15;
            int pb = s_nd[ng*5+2];
            float4 a0=make_float4(0,0,0,0), a1=a0, a2=a0, a3=a0;
            if (ng < 8){
#pragma unroll
                for (int i=0;i<4;i++){
                    float w = prjLT[(pb+i)*16+t];
                    const float4* ul = (const float4*)&prjULT[(pb+i)*16];
                    fma4(a0,w,ul[0]); fma4(a1,w,ul[1]); fma4(a2,w,ul[2]); fma4(a3,w,ul[3]);
                }
            } else {
#pragma unroll
                for (int i=0;i<8;i++){
                    float w = prjLT[(pb+i)*16+t];
                    const float4* ul = (const float4*)&prjULT[(pb+i)*16];
                    fma4(a0,w,ul[0]); fma4(a1,w,ul[1]); fma4(a2,w,ul[2]); fma4(a3,w,ul[3]);
                }
            }
            float* dst = &Bsc[(ng*16+t)*16];
            dst[0]=a0.x; dst[1]=(1<=t)?a0.y:0.f; dst[2]=(2<=t)?a0.z:0.f; dst[3]=(3<=t)?a0.w:0.f;
            dst[4]=(4<=t)?a1.x:0.f; dst[5]=(5<=t)?a1.y:0.f; dst[6]=(6<=t)?a1.z:0.f; dst[7]=(7<=t)?a1.w:0.f;
            dst[8]=(8<=t)?a2.x:0.f; dst[9]=(9<=t)?a2.y:0.f; dst[10]=(10<=t)?a2.z:0.f; dst[11]=(11<=t)?a2.w:0.f;
            dst[12]=(12<=t)?a3.x:0.f; dst[13]=(13<=t)?a3.y:0.f; dst[14]=(14<=t)?a3.z:0.f; dst[15]=(15<=t)?a3.w:0.f;
        } else if (j < 736){
            int jj = j-480;
            int n = jj>>4, t = jj&15;
            float4 qv = *(const float4*)&s_q[t*KPAD+4*n];
            float cvals[16];
#pragma unroll
            for (int s=0;s<16;s++){
                float val = dot4v(*(const float4*)&s_v[s*KPAD+4*n], qv);
                cvals[s] = (s<=t)? val : 0.f;
            }
            float acc0 = dot4v(*(const float4*)&s_leaf[(4*n+0)*4], qv);
            float acc1 = dot4v(*(const float4*)&s_leaf[(4*n+1)*4], qv);
            float acc2 = dot4v(*(const float4*)&s_leaf[(4*n+2)*4], qv);
            float acc3 = dot4v(*(const float4*)&s_leaf[(4*n+3)*4], qv);
#pragma unroll
            for (int s=0;s<16;s++){
                float4 kv = *(const float4*)&s_k[s*KPAD+4*n];
                float cs = cvals[s];
                acc0 = fmaf(kv.x, cs, acc0);
                acc1 = fmaf(kv.y, cs, acc1);
                acc2 = fmaf(kv.z, cs, acc2);
                acc3 = fmaf(kv.w, cs, acc3);
            }
            yl[(4*n+0)*17+t] = acc0;
            yl[(4*n+1)*17+t] = acc1;
            yl[(4*n+2)*17+t] = acc2;
            yl[(4*n+3)*17+t] = acc3;
        } else {
            int t = j-736;
            float acc = 0.f;
#pragma unroll
            for (int g=0;g<16;g++)
                acc += dot4v(*(const float4*)&s_z[4*g], *(const float4*)&s_q[t*KPAD+4*g]);
            for (int s=0;s<=t;s++) acc += Dsc[t*16+s];
            s_den[t] = fmaxf(acc, 1e-6f);
        }
    }
    __syncthreads();

    for (int j=tid; j<2816; j+=NT){
        if (j < 1408){
            int i88 = j>>4, t = j&15;
            int info = lutP[i88]; int pb = info&255, ng=(info>>8)&255;
            float acc = 0.f;
            int wr = lutWT[i88];
            if (i88 < 32){
#pragma unroll
                for (int u=0;u<4;u++) acc = fmaf(s_Ws[wr+u], prjXT[(pb+u)*16+t], acc);
            } else {
#pragma unroll
                for (int u=0;u<8;u++) acc = fmaf(s_Ws[wr+u], prjXT[(pb+u)*16+t], acc);
            }
            const float4* uu = (const float4*)&prjULT[i88*16];
            const float4* aa = (const float4*)&Asc[(ng*16+t)*16];
            acc += dot4v(uu[0],aa[0]) + dot4v(uu[1],aa[1]) + dot4v(uu[2],aa[2]) + dot4v(uu[3],aa[3]);
            TT[i88*17+t] = acc;
        } else {
            int jj = j-1408;
            int i88 = jj>>4, t = jj&15;
            int info = lutP[i88]; int pb = info&255, ng=(info>>8)&255;
            float acc = 0.f;
            int wc = lutWB[i88];
            if (i88 < 32){
#pragma unroll
                for (int u=0;u<4;u++) acc = fmaf(s_Ws[wc+u*4], prjLT[(pb+u)*16+t], acc);
            } else {
#pragma unroll
                for (int u=0;u<8;u++) acc = fmaf(s_Ws[wc+u*8], prjLT[(pb+u)*16+t], acc);
            }
            const float4* vv = (const float4*)&prjVRT[i88*16];
            const float4* bb = (const float4*)&Bsc[(ng*16+t)*16];
            acc += dot4v(vv[0],bb[0]) + dot4v(vv[1],bb[1]) + dot4v(vv[2],bb[2]) + dot4v(vv[3],bb[3]);
            TBB[i88*17+t] = acc;
        }
    }
    __syncthreads();

    for (int j=tid; j<1024; j+=NT){
        int d = j&63, t = j>>6;
        float y = yl[d*17+t];
#pragma unroll
        for (int l=0;l<4;l++){
            const int bs = 4<<l;
            const int r  = (l==0)?4:8;
            const int n = d >> (3+l);
            const int loc = d & (2*bs - 1);
            const int pb = Knro(l) + n*r;
            const int bso = Kbso(l);
            if (loc < bs){
                const float* u = sUL + bso + loc*r;
#pragma unroll
                for (int i=0;i<8;i++){
                    if (i < r) y = fmaf(u[i], TT[(pb+i)*17+t], y);
                }
            } else {
                const float* u = sUR + bso + (loc-bs)*r;
#pragma unroll
                for (int i=0;i<8;i++){
                    if (i < r) y = fmaf(u[i], TBB[(pb+i)*17+t], y);
                }
            }
        }
        g_o[(size_t)t*DH + d] = y / s_den[t];
    }
}

// ---------------- output GEMM: att(16384x64) @ Wo(64x1024) ----------------
__global__ __launch_bounds__(256) void wo_kernel(const float* __restrict__ Wo,
                                                 float* __restrict__ out){
    __shared__ float As[64][64];
    __shared__ float Bs[64][64];
    const int tid = threadIdx.x;
    const int rb = blockIdx.x*64, cbase = blockIdx.y*256;
#pragma unroll
    for(int i=0;i<4;i++){
        int idx = tid + i*256;
        int row = idx >> 4, g = idx & 15;
        float4 av = *(const float4*)(g_att + (size_t)(rb+row)*DH + g*4);
        *(float4*)&As[row][g*4] = av;
    }
    const int ty = tid >> 4, tx = tid & 15;
    for(int sub=0; sub<4; sub++){
        const int cbk = cbase + sub*64;
        __syncthreads();
#pragma unroll
        for(int i=0;i<4;i++){
            int idx = tid + i*256;
            int row = idx >> 4, g = idx & 15;
            float4 bv = *(const float4*)(Wo + (size_t)row*DM + cbk + g*4);
            *(float4*)&Bs[row][g*4] = bv;
        }
        __syncthreads();
        unsigned long long acc[4][2];
#pragma unroll
        for(int i=0;i<4;i++){ acc[i][0]=0ULL; acc[i][1]=0ULL; }
        for(int kk=0;kk<64;kk++){
            float a0 = As[ty*4+0][kk];
            float a1 = As[ty*4+1][kk];
            float a2 = As[ty*4+2][kk];
            float a3 = As[ty*4+3][kk];
            const unsigned long long* bpp = (const unsigned long long*)&Bs[kk][tx*4];
            unsigned long long b0 = bpp[0], b1 = bpp[1];
            unsigned long long ap;
            ap = pack2(a0,a0); fma2(acc[0][0],ap,b0); fma2(acc[0][1],ap,b1);
            ap = pack2(a1,a1); fma2(acc[1][0],ap,b0); fma2(acc[1][1],ap,b1);
            ap = pack2(a2,a2); fma2(acc[2][0],ap,b0); fma2(acc[2][1],ap,b1);
            ap = pack2(a3,a3); fma2(acc[3][0],ap,b0); fma2(acc[3][1],ap,b1);
        }
#pragma unroll
        for(int i=0;i<4;i++){
            float4 ov;
            unpack2(acc[i][0], ov.x, ov.y);
            unpack2(acc[i][1], ov.z, ov.w);
            *(float4*)(out + (size_t)(rb+ty*4+i)*DM + cbk + tx*4) = ov;
        }
    }
}

extern "C" void kernel_launch(void* const* d_in, const int* in_sizes, int n_in,
                              void* d_out, int out_size){
    (void)in_sizes; (void)n_in; (void)out_size;
    const float* x  = (const float*)d_in[0];
    const float* Wq = (const float*)d_in[1];
    const float* Wk = (const float*)d_in[2];
    const float* Wv = (const float*)d_in[3];
    const float* Wo = (const float*)d_in[4];
    BasePtrs bp;
    for(int i=0;i<16;i++) bp.p[i] = (const float*)d_in[5+i];
    float* out = (float*)d_out;

    cudaFuncSetAttribute(chunk_sum_kernel,  cudaFuncAttributeMaxDynamicSharedMemorySize, P1_BYTES);
    cudaFuncSetAttribute(chunk_scan_kernel, cudaFuncAttributeMaxDynamicSharedMemorySize, P3_BYTES);

    wprep_kernel<<<(DM*NW)/256, 256>>>(Wq, Wk, Wv);
    qkv_mma_kernel<<<NTOK/64, 256>>>(x);
    chunk_sum_kernel<<<BB*NCH, NT, P1_BYTES>>>(bp);
    prefix_kernel<<<dim3(NST/128, BB), 128>>>();
    chunk_scan_kernel<<<BB*NCH, NT, P3_BYTES>>>(bp);
    wo_kernel<<<dim3(NTOK/64, DM/256), 256>>>(Wo, out);
}

// round 7
// speedup vs baseline: 59.6133x; 1.1451x over previous
#include <cuda_runtime.h>
#include <cuda_bf16.h>
#include <math.h>

#define TSEQ 2048
#define BB 8
#define DH 64
#define DM 1024
#define NTOK (BB*TSEQ)
#define CCH 16
#define NCH (TSEQ/CCH)   /* 128 */
#define NST 896
#define KPAD 68
#define NT 512
#define NW 192           /* qkv output cols */

// scratch (device globals -- no allocation allowed)
__device__ float g_q[NTOK*DH];
__device__ float g_k[NTOK*DH];
__device__ float g_v[NTOK*DH];
__device__ float g_state[BB*NCH*NST];
__device__ float g_prefix[BB*NCH*NST];
__device__ __nv_bfloat16 g_wh[DM*NW];
__device__ __nv_bfloat16 g_wl[DM*NW];
__device__ __nv_bfloat16 g_ah[NTOK*DH];   // attention out hi
__device__ __nv_bfloat16 g_al[NTOK*DH];   // attention out lo
__device__ __nv_bfloat16 g_woh[DH*DM];
__device__ __nv_bfloat16 g_wol[DH*DM];

struct BasePtrs { const float* p[16]; }; // UL0-3, VR0-3, UR0-3, VL0-3

// ---------------- helpers ----------------
__device__ __forceinline__ void cp_async16(void* sptr, const void* gptr){
    unsigned s = (unsigned)__cvta_generic_to_shared(sptr);
    asm volatile("cp.async.ca.shared.global [%0], [%1], 16;" :: "r"(s), "l"(gptr));
}
__device__ __forceinline__ float dot4v(float4 a, float4 b){
    return fmaf(a.x,b.x, fmaf(a.y,b.y, fmaf(a.z,b.z, a.w*b.w)));
}
__device__ __forceinline__ void fma4(float4 &acc, float s, float4 v){
    acc.x = fmaf(s, v.x, acc.x); acc.y = fmaf(s, v.y, acc.y);
    acc.z = fmaf(s, v.z, acc.z); acc.w = fmaf(s, v.w, acc.w);
}
__device__ __forceinline__ unsigned smem_u32(const void* p){
    return (unsigned)__cvta_generic_to_shared(p);
}
__device__ __forceinline__ void ldmx4(unsigned &r0, unsigned &r1, unsigned &r2, unsigned &r3, const void* p){
    asm volatile("ldmatrix.sync.aligned.m8n8.x4.shared.b16 {%0,%1,%2,%3}, [%4];"
        : "=r"(r0),"=r"(r1),"=r"(r2),"=r"(r3) : "r"(smem_u32(p)));
}
__device__ __forceinline__ void ldmx4t(unsigned &r0, unsigned &r1, unsigned &r2, unsigned &r3, const void* p){
    asm volatile("ldmatrix.sync.aligned.m8n8.x4.trans.shared.b16 {%0,%1,%2,%3}, [%4];"
        : "=r"(r0),"=r"(r1),"=r"(r2),"=r"(r3) : "r"(smem_u32(p)));
}
__device__ __forceinline__ void mma16816(float* c, unsigned a0,unsigned a1,unsigned a2,unsigned a3,
                                         unsigned b0, unsigned b1){
    asm volatile("mma.sync.aligned.m16n8k16.row.col.f32.bf16.bf16.f32 "
        "{%0,%1,%2,%3}, {%4,%5,%6,%7}, {%8,%9}, {%0,%1,%2,%3};"
        : "+f"(c[0]),"+f"(c[1]),"+f"(c[2]),"+f"(c[3])
        : "r"(a0),"r"(a1),"r"(a2),"r"(a3),"r"(b0),"r"(b1));
}

__device__ __forceinline__ int Knro(int l){ return (l==0)?0:(l==1)?32:(l==2)?64:80; }
__device__ __forceinline__ int Kwso(int l){ return (l==0)?0:(l==1)?128:(l==2)?384:512; }
__device__ __forceinline__ int Kbso(int l){ return (l==0)?0:(l==1)?16:(l==2)?80:208; }
__device__ __forceinline__ int Knoff(int l){ return (l==0)?0:(l==1)?8:(l==2)?12:14; }

// ---------------- weight split prep ----------------
__global__ __launch_bounds__(256) void wprep_kernel(const float* __restrict__ Wq,
                                                    const float* __restrict__ Wk,
                                                    const float* __restrict__ Wv,
                                                    const float* __restrict__ Wo){
    int idx = blockIdx.x*256 + threadIdx.x;        // 0 .. 262143
    if (idx < DM*NW){
        int k = idx / NW, n = idx - k*NW;
        const float* W = (n<64)?Wq:(n<128?Wk:Wv);
        float w = W[(size_t)k*DH + (n&63)];
        __nv_bfloat16 hi = __float2bfloat16(w);
        g_wh[idx] = hi;
        g_wl[idx] = __float2bfloat16(w - __bfloat162float(hi));
    } else {
        int j = idx - DM*NW;                        // 0 .. 65535
        float w = Wo[j];
        __nv_bfloat16 hi = __float2bfloat16(w);
        g_woh[j] = hi;
        g_wol[j] = __float2bfloat16(w - __bfloat162float(hi));
    }
}

// ---------------- QKV via mma.sync bf16x3 ----------------
#define ASTR 24
#define BSTR 200
__global__ __launch_bounds__(256) void qkv_mma_kernel(const float* __restrict__ x){
    __shared__ __nv_bfloat16 sAh[2][64*ASTR];
    __shared__ __nv_bfloat16 sAl[2][64*ASTR];
    __shared__ __nv_bfloat16 sBh[2][16*BSTR];
    __shared__ __nv_bfloat16 sBl[2][16*BSTR];

    const int tid = threadIdx.x;
    const int wid = tid >> 5, lane = tid & 31;
    const int wy = wid & 3, wx = wid >> 2;
    const int rb = blockIdx.x * 64;
    const int arow = tid >> 2, akg = tid & 3;

    float acc[12][4];
#pragma unroll
    for (int i=0;i<12;i++){ acc[i][0]=acc[i][1]=acc[i][2]=acc[i][3]=0.f; }

    auto loadB = [&](int k0, int buf){
#pragma unroll
        for (int i=0;i<3;i++){
            int idx = tid + i*256;
            int m2 = (idx >= 384);
            int id2 = idx - m2*384;
            int r = id2 / 24, c8 = id2 - r*24;
            const __nv_bfloat16* src = (m2 ? g_wl : g_wh) + (size_t)(k0+r)*NW + c8*8;
            __nv_bfloat16* dst = (m2 ? sBl[buf] : sBh[buf]) + r*BSTR + c8*8;
            cp_async16(dst, src);
        }
    };
    auto storeA = [&](float4 v, int buf){
        __nv_bfloat16 h0=__float2bfloat16(v.x), h1=__float2bfloat16(v.y),
                      h2=__float2bfloat16(v.z), h3=__float2bfloat16(v.w);
        float l0 = v.x-__bfloat162float(h0), l1 = v.y-__bfloat162float(h1),
              l2 = v.z-__bfloat162float(h2), l3 = v.w-__bfloat162float(h3);
        __nv_bfloat162 hh0 = __halves2bfloat162(h0,h1), hh1 = __halves2bfloat162(h2,h3);
        __nv_bfloat162 ll0 = __floats2bfloat162_rn(l0,l1), ll1 = __floats2bfloat162_rn(l2,l3);
        uint2 hu = make_uint2(*(unsigned*)&hh0, *(unsigned*)&hh1);
        uint2 lu = make_uint2(*(unsigned*)&ll0, *(unsigned*)&ll1);
        *(uint2*)&sAh[buf][arow*ASTR + akg*4] = hu;
        *(uint2*)&sAl[buf][arow*ASTR + akg*4] = lu;
    };

    float4 av = *(const float4*)(x + (size_t)(rb+arow)*DM + akg*4);
    loadB(0, 0);
    asm volatile("cp.async.commit_group;\n");
    storeA(av, 0);
    asm volatile("cp.async.wait_group 0;\n");
    __syncthreads();

    const int a_off = (wy*16 + (lane&15))*ASTR + (lane>>4)*8;
    const int b_off = (lane&15)*BSTR + wx*96 + (lane>>4)*8;

    for (int kt=0; kt<64; kt++){
        const int buf = kt & 1;
        if (kt < 63){
            int k0 = (kt+1)*16;
            av = *(const float4*)(x + (size_t)(rb+arow)*DM + k0 + akg*4);
            loadB(k0, buf^1);
            asm volatile("cp.async.commit_group;\n");
        }
        unsigned ah0,ah1,ah2,ah3, al0,al1,al2,al3;
        ldmx4(ah0,ah1,ah2,ah3, sAh[buf] + a_off);
        ldmx4(al0,al1,al2,al3, sAl[buf] + a_off);
#pragma unroll
        for (int nb=0; nb<6; nb++){
            unsigned bh0,bh1,bh2,bh3, bl0,bl1,bl2,bl3;
            ldmx4t(bh0,bh1,bh2,bh3, sBh[buf] + b_off + nb*16);
            ldmx4t(bl0,bl1,bl2,bl3, sBl[buf] + b_off + nb*16);
            mma16816(acc[2*nb],   ah0,ah1,ah2,ah3, bh0,bh1);
            mma16816(acc[2*nb],   ah0,ah1,ah2,ah3, bl0,bl1);
            mma16816(acc[2*nb],   al0,al1,al2,al3, bh0,bh1);
            mma16816(acc[2*nb+1], ah0,ah1,ah2,ah3, bh2,bh3);
            mma16816(acc[2*nb+1], ah0,ah1,ah2,ah3, bl2,bl3);
            mma16816(acc[2*nb+1], al0,al1,al2,al3, bh2,bh3);
        }
        __syncthreads();
        if (kt < 63){
            storeA(av, buf^1);
            asm volatile("cp.async.wait_group 0;\n");
            __syncthreads();
        }
    }

    const int row0 = rb + wy*16 + (lane>>2);
#pragma unroll
    for (int t=0; t<12; t++){
        int col = wx*96 + t*8 + (lane&3)*2;
        bool act = (col < 128);
        float* base = (col < 64) ? g_q : (col < 128 ? g_k : g_v);
        int cc = col & 63;
        float v0 = acc[t][0], v1 = acc[t][1], v2 = acc[t][2], v3 = acc[t][3];
        if (act){
            v0 = (v0>0.f)? v0+1.f : expf(v0);
            v1 = (v1>0.f)? v1+1.f : expf(v1);
            v2 = (v2>0.f)? v2+1.f : expf(v2);
            v3 = (v3>0.f)? v3+1.f : expf(v3);
        }
        base[(size_t)row0*DH + cc]       = v0;
        base[(size_t)row0*DH + cc + 1]   = v1;
        base[(size_t)(row0+8)*DH + cc]   = v2;
        base[(size_t)(row0+8)*DH + cc+1] = v3;
    }
}

// =====================================================================
// shared LUT builders
// =====================================================================
__device__ __forceinline__ void build_node_lut(int* s_nd, int tid){
    if (tid < 15){
        int l = (tid<8)?0:(tid<12)?1:(tid<14)?2:3;
        int n = tid - Knoff(l);
        int bs = 4<<l, r = (l==0)?4:8;
        s_nd[tid*5+0]=bs; s_nd[tid*5+1]=r; s_nd[tid*5+2]=Knro(l)+n*r;
        s_nd[tid*5+3]=2*bs*n; s_nd[tid*5+4]=Kbso(l);
    }
}
__device__ __forceinline__ void build_ws_lut(int* s_lutAB, int tid, int nthr){
    for (int m = tid; m < 576; m += nthr){
        int l = (m<128)?0:(m<384)?1:(m<512)?2:3;
        int r = (l==0)?4:8;
        int rem = m - Kwso(l);
        int rr2 = r*r;
        int n = rem / rr2;
        int ij = rem - n*rr2;
        int i = ij / r, j = ij - i*r;
        int pb = Knro(l) + n*r;
        s_lutAB[m] = (pb+i) | ((pb+j)<<16);
    }
}
__device__ __forceinline__ void build_chunk_lut(int* s_ck, int tid){
    if (tid < 20){
        int c = tid, m, dd0=0, ext=0, ec=0;
        if (c < 13){ m = c; }
        else if (c == 13){ m=12; dd0=8; ext=1; ec=0; }
        else if (c == 14){ m=13; }
        else if (c == 15){ m=13; dd0=8; ext=1; ec=1; }
        else if (c == 16){ m=14; }
        else { m=14; dd0=8*(c-16); ext=1; ec=c-15; }
        s_ck[c] = m | (dd0<<8) | (ext<<16) | (ec<<20);
    }
}

// =====================================================================
// Pass 1: per-chunk state sums
// =====================================================================
#define P1_FLOATS (2176 + 2816 + 928 + 1280)
#define P1_BYTES (P1_FLOATS*4 + (75+576+20)*4)
__global__ __launch_bounds__(512,2) void chunk_sum_kernel(BasePtrs bp){
    extern __shared__ float sm[];
    float* s_k    = sm;
    float* s_v    = s_k + 16*KPAD;
    float* prjULT = s_v + 16*KPAD;
    float* prjVRT = prjULT + 1408;
    float* sUL    = prjVRT + 1408;
    float* sVR    = sUL + 464;
    float* extP   = sVR + 464;
    int*   s_nd   = (int*)(extP + 1280);
    int*   lutAB  = s_nd + 75;
    int*   s_ck   = lutAB + 576;

    const int tid = threadIdx.x;
    const int blk = blockIdx.x;
    const int b = blk / NCH, c = blk % NCH;
    const float* gk = g_k + ((size_t)b*TSEQ + c*CCH)*DH;
    const float* gv = g_v + ((size_t)b*TSEQ + c*CCH)*DH;

    for (int i=tid;i<464;i+=NT){
        int l = (i<16)?0:(i<80)?1:(i<208)?2:3;
        int off = i - Kbso(l);
        sUL[i] = bp.p[l][off];
        sVR[i] = bp.p[4+l][off];
    }
    for (int i=tid;i<512;i+=NT){
        int arr = i>>8;
        int rem = i & 255; int row = rem>>4, g = rem&15;
        const float* src = (arr==0?gk:gv) + row*64 + g*4;
        float* dst = (arr==0?s_k:s_v) + row*KPAD + g*4;
        *(float4*)dst = *(const float4*)src;
    }
    build_node_lut(s_nd, tid);
    build_ws_lut(lutAB, tid, NT);
    build_chunk_lut(s_ck, tid);
    __syncthreads();

    if (tid < 320){
        int cd = s_ck[tid>>4]; int s = tid&15;
        int m = cd & 31, dd0 = (cd>>8)&63, isext=(cd>>16)&1, ec=(cd>>20)&7;
        int bs=s_nd[m*5], r=s_nd[m*5+1], pb=s_nd[m*5+2], topo=s_nd[m*5+3], bso=s_nd[m*5+4];
        const float* kt = s_k + s*KPAD + topo + dd0;
        const float* vb = s_v + s*KPAD + topo + bs + dd0;
        const float* Ub = sUL + bso + dd0*r;
        const float* Wb = sVR + bso + dd0*r;
        if (r == 4){
            float4 aU=make_float4(0,0,0,0), aV=aU;
#pragma unroll
            for (int d=0; d<4; d++){
                float kd=kt[d], vd=vb[d];
                float4 u=*(const float4*)(Ub+d*4), w=*(const float4*)(Wb+d*4);
                fma4(aU,kd,u); fma4(aV,vd,w);
            }
            float au[4]={aU.x,aU.y,aU.z,aU.w}, avv[4]={aV.x,aV.y,aV.z,aV.w};
#pragma unroll
            for (int i=0;i<4;i++){
                prjULT[(pb+i)*16+s]=au[i];
                prjVRT[(pb+i)*16+s]=avv[i];
            }
        } else {
            float aU[8], aV[8];
#pragma unroll
            for (int i=0;i<8;i++){ aU[i]=0.f; aV[i]=0.f; }
#pragma unroll
            for (int d=0; d<8; d++){
                float kd=kt[d], vd=vb[d];
                float4 u0=*(const float4*)(Ub+d*8), u1=*(const float4*)(Ub+d*8+4);
                float4 w0=*(const float4*)(Wb+d*8), w1=*(const float4*)(Wb+d*8+4);
                aU[0]=fmaf(kd,u0.x,aU[0]); aU[1]=fmaf(kd,u0.y,aU[1]); aU[2]=fmaf(kd,u0.z,aU[2]); aU[3]=fmaf(kd,u0.w,aU[3]);
                aU[4]=fmaf(kd,u1.x,aU[4]); aU[5]=fmaf(kd,u1.y,aU[5]); aU[6]=fmaf(kd,u1.z,aU[6]); aU[7]=fmaf(kd,u1.w,aU[7]);
                aV[0]=fmaf(vd,w0.x,aV[0]); aV[1]=fmaf(vd,w0.y,aV[1]); aV[2]=fmaf(vd,w0.z,aV[2]); aV[3]=fmaf(vd,w0.w,aV[3]);
                aV[4]=fmaf(vd,w1.x,aV[4]); aV[5]=fmaf(vd,w1.y,aV[5]); aV[6]=fmaf(vd,w1.z,aV[6]); aV[7]=fmaf(vd,w1.w,aV[7]);
            }
            if (!isext){
#pragma unroll
                for (int i=0;i<8;i++){
                    prjULT[(pb+i)*16+s]=aU[i];
                    prjVRT[(pb+i)*16+s]=aV[i];
                }
            } else {
#pragma unroll
                for (int i=0;i<8;i++){
                    extP[((0*5+ec)*8+i)*16+s]=aU[i];
                    extP[((1*5+ec)*8+i)*16+s]=aV[i];
                }
            }
        }
    }
    __syncthreads();
    if (tid < 256){
        int a=tid>>7, i=(tid>>4)&7, s=tid&15;
        float* base = prjULT + a*1408;
        base[(64+i)*16+s] += extP[((a*5+0)*8+i)*16+s];
        base[(72+i)*16+s] += extP[((a*5+1)*8+i)*16+s];
        base[(80+i)*16+s] += extP[((a*5+2)*8+i)*16+s] + extP[((a*5+3)*8+i)*16+s] + extP[((a*5+4)*8+i)*16+s];
    }
    __syncthreads();

    float* go = g_state + (size_t)blk*NST;
    for (int e=tid; e<NST; e+=NT){
        float acc = 0.f;
        if (e < 256){
            int n=e>>4, i=(e>>2)&3, j2=e&3;
            int ki=4*n+i, vi=4*n+j2;
#pragma unroll
            for (int s=0;s<CCH;s++) acc = fmaf(s_k[s*KPAD+ki], s_v[s*KPAD+vi], acc);
        } else if (e < 832){
            int m = e-256;
            int ab = lutAB[m]; int a = ab & 0xffff, b3 = ab >> 16;
            const float4* pa = (const float4*)&prjULT[a*16];
            const float4* pb4 = (const float4*)&prjVRT[b3*16];
#pragma unroll
            for (int g=0;g<4;g++) acc += dot4v(pa[g], pb4[g]);
        } else {
            int d = e-832;
#pragma unroll
            for (int s=0;s<CCH;s++) acc += s_k[s*KPAD+d];
        }
        go[e] = acc;
    }
}

// =====================================================================
// Pass 2: exclusive prefix over chunks (MLP=16)
// =====================================================================
__global__ __launch_bounds__(128) void prefix_kernel(){
    const int b = blockIdx.y;
    const int e = blockIdx.x*128 + threadIdx.x;
    const float* gs = g_state  + (size_t)b*NCH*NST + e;
    float*       gp = g_prefix + (size_t)b*NCH*NST + e;
    float run = 0.f;
    for (int c0=0;c0<NCH;c0+=16){
        float v[16];
#pragma unroll
        for (int j=0;j<16;j++) v[j] = gs[(size_t)(c0+j)*NST];
#pragma unroll
        for (int j=0;j<16;j++){ gp[(size_t)(c0+j)*NST] = run; run += v[j]; }
    }
}

// =====================================================================
// Pass 3: fully parallel intra-chunk attention, 512 threads
// =====================================================================
#define P3_FLOATS (3264 + 5632 + 1856 + 896 + 3840 + 3840 + 2560 + 256 + 16 + 1496 + 1496 + 1088)
#define P3_BYTES (P3_FLOATS*4 + (75 + 88*3 + 20)*4)
__global__ __launch_bounds__(512,2) void chunk_scan_kernel(BasePtrs bp){
    extern __shared__ float sm[];
    float* s_k    = sm;
    float* s_v    = s_k + 16*KPAD;
    float* s_q    = s_v + 16*KPAD;
    float* prjULT = s_q + 16*KPAD;
    float* prjVRT = prjULT + 1408;
    float* prjXT  = prjVRT + 1408;
    float* prjLT  = prjXT + 1408;
    float* sUL    = prjLT + 1408;
    float* sVR    = sUL + 464;
    float* sUR    = sVR + 464;
    float* sVL    = sUR + 464;
    float* s_leaf = sVL + 464;
    float* s_Ws   = s_leaf + 256;
    float* s_z    = s_Ws + 576;
    float* Asc    = s_z + 64;
    float* Bsc    = Asc + 3840;
    float* extP   = Bsc + 3840;
    float* Dsc    = extP + 2560;
    float* s_den  = Dsc + 256;
    float* TT     = s_den + 16;
    float* TBB    = TT + 1496;
    float* yl     = TBB + 1496;
    int*   s_nd   = (int*)(yl + 1088);
    int*   lutP   = s_nd + 75;
    int*   lutWT  = lutP + 88;
    int*   lutWB  = lutWT + 88;
    int*   s_ck   = lutWB + 88;

    const int tid = threadIdx.x;
    const int blk = blockIdx.x;
    const int b = blk / NCH, c = blk % NCH;
    const float* gk = g_k + ((size_t)b*TSEQ + c*CCH)*DH;
    const float* gv = g_v + ((size_t)b*TSEQ + c*CCH)*DH;
    const float* gq = g_q + ((size_t)b*TSEQ + c*CCH)*DH;
    __nv_bfloat16* g_oh = g_ah + ((size_t)b*TSEQ + c*CCH)*DH;
    __nv_bfloat16* g_ol = g_al + ((size_t)b*TSEQ + c*CCH)*DH;

    for (int i=tid;i<464;i+=NT){
        int l = (i<16)?0:(i<80)?1:(i<208)?2:3;
        int off = i - Kbso(l);
        sUL[i] = bp.p[l   ][off];
        sVR[i] = bp.p[4+l ][off];
        sUR[i] = bp.p[8+l ][off];
        sVL[i] = bp.p[12+l][off];
    }
    for (int i=tid;i<768;i+=NT){
        int arr = i>>8;
        int rem = i & 255; int row = rem>>4, g = rem&15;
        const float* src = (arr==0?gk:(arr==1?gv:gq)) + row*64 + g*4;
        float* dst = (arr==0?s_k:(arr==1?s_v:s_q)) + row*KPAD + g*4;
        *(float4*)dst = *(const float4*)src;
    }
    {
        const float* gp = g_prefix + (size_t)blk*NST;
        for (int e=tid;e<NST;e+=NT){
            float vle = gp[e];
            if (e<256) s_leaf[e]=vle;
            else if (e<832) s_Ws[e-256]=vle;
            else s_z[e-832]=vle;
        }
    }
    build_node_lut(s_nd, tid);
    build_chunk_lut(s_ck, tid);
    if (tid < 88){
        int i88 = tid;
        int l = (i88<32)?0:(i88<64)?1:(i88<80)?2:3;
        int r = (l==0)?4:8;
        int rem = i88 - Knro(l);
        int n = rem / r, i = rem - n*r;
        int pb = Knro(l) + n*r;
        int ng = Knoff(l) + n;
        lutP[i88]  = pb | (ng<<8) | (r<<16);
        lutWT[i88] = Kwso(l) + n*r*r + i*r;
        lutWB[i88] = Kwso(l) + n*r*r + i;
    }
    __syncthreads();

    if (tid < 320){
        int cd = s_ck[tid>>4]; int s = tid&15;
        int m = cd & 31, dd0 = (cd>>8)&63, isext=(cd>>16)&1, ec=(cd>>20)&7;
        int bs=s_nd[m*5], r=s_nd[m*5+1], pb=s_nd[m*5+2], topo=s_nd[m*5+3], bso=s_nd[m*5+4];
        const float* kt = s_k + s*KPAD + topo + dd0;
        const float* vb = s_v + s*KPAD + topo + bs + dd0;
        const float* qt = s_q + s*KPAD + topo + dd0;
        const float* qb = s_q + s*KPAD + topo + bs + dd0;
        const float* Ub = sUL + bso + dd0*r;
        const float* Wb = sVR + bso + dd0*r;
        const float* Xb = sVL + bso + dd0*r;
        if (r == 4){
            float4 aU=make_float4(0,0,0,0), aV=aU, aX=aU, aL=aU;
#pragma unroll
            for (int d=0; d<4; d++){
                float kd=kt[d], vd=vb[d], qtd=qt[d], qbd=qb[d];
                float4 u=*(const float4*)(Ub+d*4), w=*(const float4*)(Wb+d*4), x=*(const float4*)(Xb+d*4);
                fma4(aU,kd,u); fma4(aV,vd,w); fma4(aX,qbd,w); fma4(aL,qtd,x);
            }
            float t0[4]={aU.x,aU.y,aU.z,aU.w}, t1[4]={aV.x,aV.y,aV.z,aV.w};
            float t2[4]={aX.x,aX.y,aX.z,aX.w}, t3[4]={aL.x,aL.y,aL.z,aL.w};
#pragma unroll
            for (int i=0;i<4;i++){
                prjULT[(pb+i)*16+s]=t0[i];
                prjVRT[(pb+i)*16+s]=t1[i];
                prjXT [(pb+i)*16+s]=t2[i];
                prjLT [(pb+i)*16+s]=t3[i];
            }
        } else {
            {
                float aU[8], aV[8];
#pragma unroll
                for (int i=0;i<8;i++){ aU[i]=0.f; aV[i]=0.f; }
#pragma unroll
                for (int d=0; d<8; d++){
                    float kd=kt[d], vd=vb[d];
                    float4 u0=*(const float4*)(Ub+d*8), u1=*(const float4*)(Ub+d*8+4);
                    float4 w0=*(const float4*)(Wb+d*8), w1=*(const float4*)(Wb+d*8+4);
                    aU[0]=fmaf(kd,u0.x,aU[0]); aU[1]=fmaf(kd,u0.y,aU[1]); aU[2]=fmaf(kd,u0.z,aU[2]); aU[3]=fmaf(kd,u0.w,aU[3]);
                    aU[4]=fmaf(kd,u1.x,aU[4]); aU[5]=fmaf(kd,u1.y,aU[5]); aU[6]=fmaf(kd,u1.z,aU[6]); aU[7]=fmaf(kd,u1.w,aU[7]);
                    aV[0]=fmaf(vd,w0.x,aV[0]); aV[1]=fmaf(vd,w0.y,aV[1]); aV[2]=fmaf(vd,w0.z,aV[2]); aV[3]=fmaf(vd,w0.w,aV[3]);
                    aV[4]=fmaf(vd,w1.x,aV[4]); aV[5]=fmaf(vd,w1.y,aV[5]); aV[6]=fmaf(vd,w1.z,aV[6]); aV[7]=fmaf(vd,w1.w,aV[7]);
                }
                if (!isext){
#pragma unroll
                    for (int i=0;i<8;i++){ prjULT[(pb+i)*16+s]=aU[i]; prjVRT[(pb+i)*16+s]=aV[i]; }
                } else {
#pragma unroll
                    for (int i=0;i<8;i++){
                        extP[((0*5+ec)*8+i)*16+s]=aU[i];
                        extP[((1*5+ec)*8+i)*16+s]=aV[i];
                    }
                }
            }
            {
                float aX[8], aL[8];
#pragma unroll
                for (int i=0;i<8;i++){ aX[i]=0.f; aL[i]=0.f; }
#pragma unroll
                for (int d=0; d<8; d++){
                    float qbd=qb[d], qtd=qt[d];
                    float4 w0=*(const float4*)(Wb+d*8), w1=*(const float4*)(Wb+d*8+4);
                    float4 x0=*(const float4*)(Xb+d*8), x1=*(const float4*)(Xb+d*8+4);
                    aX[0]=fmaf(qbd,w0.x,aX[0]); aX[1]=fmaf(qbd,w0.y,aX[1]); aX[2]=fmaf(qbd,w0.z,aX[2]); aX[3]=fmaf(qbd,w0.w,aX[3]);
                    aX[4]=fmaf(qbd,w1.x,aX[4]); aX[5]=fmaf(qbd,w1.y,aX[5]); aX[6]=fmaf(qbd,w1.z,aX[6]); aX[7]=fmaf(qbd,w1.w,aX[7]);
                    aL[0]=fmaf(qtd,x0.x,aL[0]); aL[1]=fmaf(qtd,x0.y,aL[1]); aL[2]=fmaf(qtd,x0.z,aL[2]); aL[3]=fmaf(qtd,x0.w,aL[3]);
                    aL[4]=fmaf(qtd,x1.x,aL[4]); aL[5]=fmaf(qtd,x1.y,aL[5]); aL[6]=fmaf(qtd,x1.z,aL[6]); aL[7]=fmaf(qtd,x1.w,aL[7]);
                }
                if (!isext){
#pragma unroll
                    for (int i=0;i<8;i++){ prjXT[(pb+i)*16+s]=aX[i]; prjLT[(pb+i)*16+s]=aL[i]; }
                } else {
#pragma unroll
                    for (int i=0;i<8;i++){
                        extP[((2*5+ec)*8+i)*16+s]=aX[i];
                        extP[((3*5+ec)*8+i)*16+s]=aL[i];
                    }
                }
            }
        }
    } else {
        int j = tid - 320;
#pragma unroll
        for (int rep=0; rep<2; rep++){
            if (j < 256){
                int t = j>>4, s = j&15;
                float acc = 0.f;
#pragma unroll
                for (int g=0;g<16;g++)
                    acc += dot4v(*(const float4*)&s_k[s*KPAD+4*g], *(const float4*)&s_q[t*KPAD+4*g]);
                Dsc[j] = acc;
            }
            j += 192;
        }
    }
    __syncthreads();
    if (tid < 512){
        int a=tid>>7, i=(tid>>4)&7, s=tid&15;
        float* base = prjULT + a*1408;
        base[(64+i)*16+s] += extP[((a*5+0)*8+i)*16+s];
        base[(72+i)*16+s] += extP[((a*5+1)*8+i)*16+s];
        base[(80+i)*16+s] += extP[((a*5+2)*8+i)*16+s] + extP[((a*5+3)*8+i)*16+s] + extP[((a*5+4)*8+i)*16+s];
    }
    __syncthreads();

    for (int j=tid; j<752; j+=NT){
        if (j < 240){
            int ng = j>>4, t = j&15;
            int pb = s_nd[ng*5+2];
            float4 a0=make_float4(0,0,0,0), a1=a0, a2=a0, a3=a0;
            if (ng < 8){
#pragma unroll
                for (int i=0;i<4;i++){
                    float w = prjXT[(pb+i)*16+t];
                    const float4* vr = (const float4*)&prjVRT[(pb+i)*16];
                    fma4(a0,w,vr[0]); fma4(a1,w,vr[1]); fma4(a2,w,vr[2]); fma4(a3,w,vr[3]);
                }
            } else {
#pragma unroll
                for (int i=0;i<8;i++){
                    float w = prjXT[(pb+i)*16+t];
                    const float4* vr = (const float4*)&prjVRT[(pb+i)*16];
                    fma4(a0,w,vr[0]); fma4(a1,w,vr[1]); fma4(a2,w,vr[2]); fma4(a3,w,vr[3]);
                }
            }
            float* dst = &Asc[(ng*16+t)*16];
            dst[0]=a0.x; dst[1]=(1<=t)?a0.y:0.f; dst[2]=(2<=t)?a0.z:0.f; dst[3]=(3<=t)?a0.w:0.f;
            dst[4]=(4<=t)?a1.x:0.f; dst[5]=(5<=t)?a1.y:0.f; dst[6]=(6<=t)?a1.z:0.f; dst[7]=(7<=t)?a1.w:0.f;
            dst[8]=(8<=t)?a2.x:0.f; dst[9]=(9<=t)?a2.y:0.f; dst[10]=(10<=t)?a2.z:0.f; dst[11]=(11<=t)?a2.w:0.f;
            dst[12]=(12<=t)?a3.x:0.f; dst[13]=(13<=t)?a3.y:0.f; dst[14]=(14<=t)?a3.z:0.f; dst[15]=(15<=t)?a3.w:0.f;
        } else if (j < 480){
            int jj = j-240;
            int ng = jj>>4, t = jj&15;
            int pb = s_nd[ng*5+2];
            float4 a0=make_float4(0,0,0,0), a1=a0, a2=a0, a3=a0;
            if (ng < 8){
#pragma unroll
                for (int i=0;i<4;i++){
                    float w = prjLT[(pb+i)*16+t];
                    const float4* ul = (const float4*)&prjULT[(pb+i)*16];
                    fma4(a0,w,ul[0]); fma4(a1,w,ul[1]); fma4(a2,w,ul[2]); fma4(a3,w,ul[3]);
                }
            } else {
#pragma unroll
                for (int i=0;i<8;i++){
                    float w = prjLT[(pb+i)*16+t];
                    const float4* ul = (const float4*)&prjULT[(pb+i)*16];
                    fma4(a0,w,ul[0]); fma4(a1,w,ul[1]); fma4(a2,w,ul[2]); fma4(a3,w,ul[3]);
                }
            }
            float* dst = &Bsc[(ng*16+t)*16];
            dst[0]=a0.x; dst[1]=(1<=t)?a0.y:0.f; dst[2]=(2<=t)?a0.z:0.f; dst[3]=(3<=t)?a0.w:0.f;
            dst[4]=(4<=t)?a1.x:0.f; dst[5]=(5<=t)?a1.y:0.f; dst[6]=(6<=t)?a1.z:0.f; dst[7]=(7<=t)?a1.w:0.f;
            dst[8]=(8<=t)?a2.x:0.f; dst[9]=(9<=t)?a2.y:0.f; dst[10]=(10<=t)?a2.z:0.f; dst[11]=(11<=t)?a2.w:0.f;
            dst[12]=(12<=t)?a3.x:0.f; dst[13]=(13<=t)?a3.y:0.f; dst[14]=(14<=t)?a3.z:0.f; dst[15]=(15<=t)?a3.w:0.f;
        } else if (j < 736){
            int jj = j-480;
            int n = jj>>4, t = jj&15;
            float4 qv = *(const float4*)&s_q[t*KPAD+4*n];
            float cvals[16];
#pragma unroll
            for (int s=0;s<16;s++){
                float val = dot4v(*(const float4*)&s_v[s*KPAD+4*n], qv);
                cvals[s] = (s<=t)? val : 0.f;
            }
            float acc0 = dot4v(*(const float4*)&s_leaf[(4*n+0)*4], qv);
            float acc1 = dot4v(*(const float4*)&s_leaf[(4*n+1)*4], qv);
            float acc2 = dot4v(*(const float4*)&s_leaf[(4*n+2)*4], qv);
            float acc3 = dot4v(*(const float4*)&s_leaf[(4*n+3)*4], qv);
#pragma unroll
            for (int s=0;s<16;s++){
                float4 kv = *(const float4*)&s_k[s*KPAD+4*n];
                float cs = cvals[s];
                acc0 = fmaf(kv.x, cs, acc0);
                acc1 = fmaf(kv.y, cs, acc1);
                acc2 = fmaf(kv.z, cs, acc2);
                acc3 = fmaf(kv.w, cs, acc3);
            }
            yl[(4*n+0)*17+t] = acc0;
            yl[(4*n+1)*17+t] = acc1;
            yl[(4*n+2)*17+t] = acc2;
            yl[(4*n+3)*17+t] = acc3;
        } else {
            int t = j-736;
            float acc = 0.f;
#pragma unroll
            for (int g=0;g<16;g++)
                acc += dot4v(*(const float4*)&s_z[4*g], *(const float4*)&s_q[t*KPAD+4*g]);
            for (int s=0;s<=t;s++) acc += Dsc[t*16+s];
            s_den[t] = fmaxf(acc, 1e-6f);
        }
    }
    __syncthreads();

    for (int j=tid; j<2816; j+=NT){
        if (j < 1408){
            int i88 = j>>4, t = j&15;
            int info = lutP[i88]; int pb = info&255, ng=(info>>8)&255;
            float acc = 0.f;
            int wr = lutWT[i88];
            if (i88 < 32){
#pragma unroll
                for (int u=0;u<4;u++) acc = fmaf(s_Ws[wr+u], prjXT[(pb+u)*16+t], acc);
            } else {
#pragma unroll
                for (int u=0;u<8;u++) acc = fmaf(s_Ws[wr+u], prjXT[(pb+u)*16+t], acc);
            }
            const float4* uu = (const float4*)&prjULT[i88*16];
            const float4* aa = (const float4*)&Asc[(ng*16+t)*16];
            acc += dot4v(uu[0],aa[0]) + dot4v(uu[1],aa[1]) + dot4v(uu[2],aa[2]) + dot4v(uu[3],aa[3]);
            TT[i88*17+t] = acc;
        } else {
            int jj = j-1408;
            int i88 = jj>>4, t = jj&15;
            int info = lutP[i88]; int pb = info&255, ng=(info>>8)&255;
            float acc = 0.f;
            int wc = lutWB[i88];
            if (i88 < 32){
#pragma unroll
                for (int u=0;u<4;u++) acc = fmaf(s_Ws[wc+u*4], prjLT[(pb+u)*16+t], acc);
            } else {
#pragma unroll
                for (int u=0;u<8;u++) acc = fmaf(s_Ws[wc+u*8], prjLT[(pb+u)*16+t], acc);
            }
            const float4* vv = (const float4*)&prjVRT[i88*16];
            const float4* bb = (const float4*)&Bsc[(ng*16+t)*16];
            acc += dot4v(vv[0],bb[0]) + dot4v(vv[1],bb[1]) + dot4v(vv[2],bb[2]) + dot4v(vv[3],bb[3]);
            TBB[i88*17+t] = acc;
        }
    }
    __syncthreads();

    for (int j=tid; j<1024; j+=NT){
        int d = j&63, t = j>>6;
        float y = yl[d*17+t];
#pragma unroll
        for (int l=0;l<4;l++){
            const int bs = 4<<l;
            const int r  = (l==0)?4:8;
            const int n = d >> (3+l);
            const int loc = d & (2*bs - 1);
            const int pb = Knro(l) + n*r;
            const int bso = Kbso(l);
            if (loc < bs){
                const float* u = sUL + bso + loc*r;
#pragma unroll
                for (int i=0;i<8;i++){
                    if (i < r) y = fmaf(u[i], TT[(pb+i)*17+t], y);
                }
            } else {
                const float* u = sUR + bso + (loc-bs)*r;
#pragma unroll
                for (int i=0;i<8;i++){
                    if (i < r) y = fmaf(u[i], TBB[(pb+i)*17+t], y);
                }
            }
        }
        float o = y / s_den[t];
        __nv_bfloat16 h = __float2bfloat16(o);
        g_oh[(size_t)t*DH + d] = h;
        g_ol[(size_t)t*DH + d] = __float2bfloat16(o - __bfloat162float(h));
    }
}

// ---------------- output GEMM via mma.sync bf16x3 ----------------
// block: 128 rows x 128 cols, K=64 (single stage), 256 threads (8 warps 4x2)
#define WA 72
#define WB 136
#define WO_BYTES ((128*WA*2 + 64*WB*2)*2)
__global__ __launch_bounds__(256) void wo_mma_kernel(float* __restrict__ out){
    extern __shared__ __nv_bfloat16 ws[];
    __nv_bfloat16* sAh = ws;
    __nv_bfloat16* sAl = sAh + 128*WA;
    __nv_bfloat16* sBh = sAl + 128*WA;
    __nv_bfloat16* sBl = sBh + 64*WB;

    const int tid = threadIdx.x;
    const int wid = tid >> 5, lane = tid & 31;
    const int wy = wid & 3, wx = wid >> 2;
    const int rb = blockIdx.x * 128, cb = blockIdx.y * 128;

#pragma unroll
    for (int i=0;i<4;i++){
        int idx = tid + i*256;               // 0..1023
        int row = idx >> 3, c8 = idx & 7;
        cp_async16(sAh + row*WA + c8*8, g_ah + (size_t)(rb+row)*DH + c8*8);
        cp_async16(sAl + row*WA + c8*8, g_al + (size_t)(rb+row)*DH + c8*8);
    }
#pragma unroll
    for (int i=0;i<4;i++){
        int idx = tid + i*256;               // 0..1023
        int k = idx >> 4, c16 = idx & 15;
        cp_async16(sBh + k*WB + c16*8, g_woh + (size_t)k*DM + cb + c16*8);
        cp_async16(sBl + k*WB + c16*8, g_wol + (size_t)k*DM + cb + c16*8);
    }
    asm volatile("cp.async.commit_group;\n");
    asm volatile("cp.async.wait_group 0;\n");
    __syncthreads();

    float acc[2][8][4];
#pragma unroll
    for (int m=0;m<2;m++)
#pragma unroll
        for (int n=0;n<8;n++){ acc[m][n][0]=acc[m][n][1]=acc[m][n][2]=acc[m][n][3]=0.f; }

#pragma unroll
    for (int k0=0;k0<64;k0+=16){
        unsigned ah[2][4], al[2][4];
#pragma unroll
        for (int mt=0;mt<2;mt++){
            const __nv_bfloat16* ap = sAh + (wy*32 + mt*16 + (lane&15))*WA + k0 + (lane>>4)*8;
            ldmx4(ah[mt][0],ah[mt][1],ah[mt][2],ah[mt][3], ap);
            const __nv_bfloat16* ap2 = sAl + (wy*32 + mt*16 + (lane&15))*WA + k0 + (lane>>4)*8;
            ldmx4(al[mt][0],al[mt][1],al[mt][2],al[mt][3], ap2);
        }
#pragma unroll
        for (int nt=0;nt<4;nt++){
            unsigned bh0,bh1,bh2,bh3, bl0,bl1,bl2,bl3;
            const __nv_bfloat16* bp = sBh + (k0 + (lane&15))*WB + wx*64 + nt*16 + (lane>>4)*8;
            ldmx4t(bh0,bh1,bh2,bh3, bp);
            const __nv_bfloat16* bp2 = sBl + (k0 + (lane&15))*WB + wx*64 + nt*16 + (lane>>4)*8;
            ldmx4t(bl0,bl1,bl2,bl3, bp2);
#pragma unroll
            for (int mt=0;mt<2;mt++){
                mma16816(acc[mt][2*nt],   ah[mt][0],ah[mt][1],ah[mt][2],ah[mt][3], bh0,bh1);
                mma16816(acc[mt][2*nt],   ah[mt][0],ah[mt][1],ah[mt][2],ah[mt][3], bl0,bl1);
                mma16816(acc[mt][2*nt],   al[mt][0],al[mt][1],al[mt][2],al[mt][3], bh0,bh1);
                mma16816(acc[mt][2*nt+1], ah[mt][0],ah[mt][1],ah[mt][2],ah[mt][3], bh2,bh3);
                mma16816(acc[mt][2*nt+1], ah[mt][0],ah[mt][1],ah[mt][2],ah[mt][3], bl2,bl3);
                mma16816(acc[mt][2*nt+1], al[mt][0],al[mt][1],al[mt][2],al[mt][3], bh2,bh3);
            }
        }
    }

#pragma unroll
    for (int mt=0;mt<2;mt++){
        int row = rb + wy*32 + mt*16 + (lane>>2);
#pragma unroll
        for (int nt=0;nt<8;nt++){
            int col = cb + wx*64 + nt*8 + (lane&3)*2;
            *(float2*)(out + (size_t)row*DM + col)     = make_float2(acc[mt][nt][0], acc[mt][nt][1]);
            *(float2*)(out + (size_t)(row+8)*DM + col) = make_float2(acc[mt][nt][2], acc[mt][nt][3]);
        }
    }
}

extern "C" void kernel_launch(void* const* d_in, const int* in_sizes, int n_in,
                              void* d_out, int out_size){
    (void)in_sizes; (void)n_in; (void)out_size;
    const float* x  = (const float*)d_in[0];
    const float* Wq = (const float*)d_in[1];
    const float* Wk = (const float*)d_in[2];
    const float* Wv = (const float*)d_in[3];
    const float* Wo = (const float*)d_in[4];
    BasePtrs bp;
    for(int i=0;i<16;i++) bp.p[i] = (const float*)d_in[5+i];
    float* out = (float*)d_out;

    cudaFuncSetAttribute(chunk_sum_kernel,  cudaFuncAttributeMaxDynamicSharedMemorySize, P1_BYTES);
    cudaFuncSetAttribute(chunk_scan_kernel, cudaFuncAttributeMaxDynamicSharedMemorySize, P3_BYTES);
    cudaFuncSetAttribute(wo_mma_kernel,     cudaFuncAttributeMaxDynamicSharedMemorySize, WO_BYTES);

    wprep_kernel<<<(DM*NW + DH*DM)/256, 256>>>(Wq, Wk, Wv, Wo);
    qkv_mma_kernel<<<NTOK/64, 256>>>(x);
    chunk_sum_kernel<<<BB*NCH, NT, P1_BYTES>>>(bp);
    prefix_kernel<<<dim3(NST/128, BB), 128>>>();
    chunk_scan_kernel<<<BB*NCH, NT, P3_BYTES>>>(bp);
    wo_mma_kernel<<<dim3(NTOK/128, DM/128), 256, WO_BYTES>>>(out);
}

// round 8
// speedup vs baseline: 60.0009x; 1.0065x over previous
#include <cuda_runtime.h>
#include <cuda_bf16.h>
#include <math.h>

#define TSEQ 2048
#define BB 8
#define DH 64
#define DM 1024
#define NTOK (BB*TSEQ)
#define CCH 16
#define NCH (TSEQ/CCH)   /* 128 */
#define NST 896
#define KPAD 68
#define NT 512
#define NW 192
#define NGRP 32          /* chunk groups of 4 per batch */

// scratch (device globals -- no allocation allowed)
__device__ float g_q[NTOK*DH];
__device__ float g_k[NTOK*DH];
__device__ float g_v[NTOK*DH];
__device__ float g_prefix[BB*NCH*NST];     // intra-group exclusive prefix
__device__ float g_gtot[BB*NGRP*NST];      // group totals
__device__ float g_goff[BB*NGRP*NST];      // exclusive prefix over groups
__device__ __nv_bfloat16 g_wh[DM*NW];
__device__ __nv_bfloat16 g_wl[DM*NW];
__device__ __nv_bfloat16 g_ah[NTOK*DH];
__device__ __nv_bfloat16 g_al[NTOK*DH];
__device__ __nv_bfloat16 g_woh[DH*DM];
__device__ __nv_bfloat16 g_wol[DH*DM];

struct BasePtrs { const float* p[16]; }; // UL0-3, VR0-3, UR0-3, VL0-3

// ---------------- helpers ----------------
__device__ __forceinline__ void cp_async16(void* sptr, const void* gptr){
    unsigned s = (unsigned)__cvta_generic_to_shared(sptr);
    asm volatile("cp.async.ca.shared.global [%0], [%1], 16;" :: "r"(s), "l"(gptr));
}
__device__ __forceinline__ float dot4v(float4 a, float4 b){
    return fmaf(a.x,b.x, fmaf(a.y,b.y, fmaf(a.z,b.z, a.w*b.w)));
}
__device__ __forceinline__ void fma4(float4 &acc, float s, float4 v){
    acc.x = fmaf(s, v.x, acc.x); acc.y = fmaf(s, v.y, acc.y);
    acc.z = fmaf(s, v.z, acc.z); acc.w = fmaf(s, v.w, acc.w);
}
__device__ __forceinline__ unsigned smem_u32(const void* p){
    return (unsigned)__cvta_generic_to_shared(p);
}
__device__ __forceinline__ void ldmx4(unsigned &r0, unsigned &r1, unsigned &r2, unsigned &r3, const void* p){
    asm volatile("ldmatrix.sync.aligned.m8n8.x4.shared.b16 {%0,%1,%2,%3}, [%4];"
        : "=r"(r0),"=r"(r1),"=r"(r2),"=r"(r3) : "r"(smem_u32(p)));
}
__device__ __forceinline__ void ldmx4t(unsigned &r0, unsigned &r1, unsigned &r2, unsigned &r3, const void* p){
    asm volatile("ldmatrix.sync.aligned.m8n8.x4.trans.shared.b16 {%0,%1,%2,%3}, [%4];"
        : "=r"(r0),"=r"(r1),"=r"(r2),"=r"(r3) : "r"(smem_u32(p)));
}
__device__ __forceinline__ void mma16816(float* c, unsigned a0,unsigned a1,unsigned a2,unsigned a3,
                                         unsigned b0, unsigned b1){
    asm volatile("mma.sync.aligned.m16n8k16.row.col.f32.bf16.bf16.f32 "
        "{%0,%1,%2,%3}, {%4,%5,%6,%7}, {%8,%9}, {%0,%1,%2,%3};"
        : "+f"(c[0]),"+f"(c[1]),"+f"(c[2]),"+f"(c[3])
        : "r"(a0),"r"(a1),"r"(a2),"r"(a3),"r"(b0),"r"(b1));
}

__device__ __forceinline__ int Knro(int l){ return (l==0)?0:(l==1)?32:(l==2)?64:80; }
__device__ __forceinline__ int Kwso(int l){ return (l==0)?0:(l==1)?128:(l==2)?384:512; }
__device__ __forceinline__ int Kbso(int l){ return (l==0)?0:(l==1)?16:(l==2)?80:208; }
__device__ __forceinline__ int Knoff(int l){ return (l==0)?0:(l==1)?8:(l==2)?12:14; }

// ---------------- weight split prep ----------------
__global__ __launch_bounds__(256) void wprep_kernel(const float* __restrict__ Wq,
                                                    const float* __restrict__ Wk,
                                                    const float* __restrict__ Wv,
                                                    const float* __restrict__ Wo){
    int idx = blockIdx.x*256 + threadIdx.x;
    if (idx < DM*NW){
        int k = idx / NW, n = idx - k*NW;
        const float* W = (n<64)?Wq:(n<128?Wk:Wv);
        float w = W[(size_t)k*DH + (n&63)];
        __nv_bfloat16 hi = __float2bfloat16(w);
        g_wh[idx] = hi;
        g_wl[idx] = __float2bfloat16(w - __bfloat162float(hi));
    } else {
        int j = idx - DM*NW;
        float w = Wo[j];
        __nv_bfloat16 hi = __float2bfloat16(w);
        g_woh[j] = hi;
        g_wol[j] = __float2bfloat16(w - __bfloat162float(hi));
    }
}

// ---------------- QKV via mma.sync bf16x3 ----------------
#define ASTR 24
#define BSTR 200
__global__ __launch_bounds__(256) void qkv_mma_kernel(const float* __restrict__ x){
    __shared__ __nv_bfloat16 sAh[2][64*ASTR];
    __shared__ __nv_bfloat16 sAl[2][64*ASTR];
    __shared__ __nv_bfloat16 sBh[2][16*BSTR];
    __shared__ __nv_bfloat16 sBl[2][16*BSTR];

    const int tid = threadIdx.x;
    const int wid = tid >> 5, lane = tid & 31;
    const int wy = wid & 3, wx = wid >> 2;
    const int rb = blockIdx.x * 64;
    const int arow = tid >> 2, akg = tid & 3;

    float acc[12][4];
#pragma unroll
    for (int i=0;i<12;i++){ acc[i][0]=acc[i][1]=acc[i][2]=acc[i][3]=0.f; }

    auto loadB = [&](int k0, int buf){
#pragma unroll
        for (int i=0;i<3;i++){
            int idx = tid + i*256;
            int m2 = (idx >= 384);
            int id2 = idx - m2*384;
            int r = id2 / 24, c8 = id2 - r*24;
            const __nv_bfloat16* src = (m2 ? g_wl : g_wh) + (size_t)(k0+r)*NW + c8*8;
            __nv_bfloat16* dst = (m2 ? sBl[buf] : sBh[buf]) + r*BSTR + c8*8;
            cp_async16(dst, src);
        }
    };
    auto storeA = [&](float4 v, int buf){
        __nv_bfloat16 h0=__float2bfloat16(v.x), h1=__float2bfloat16(v.y),
                      h2=__float2bfloat16(v.z), h3=__float2bfloat16(v.w);
        float l0 = v.x-__bfloat162float(h0), l1 = v.y-__bfloat162float(h1),
              l2 = v.z-__bfloat162float(h2), l3 = v.w-__bfloat162float(h3);
        __nv_bfloat162 hh0 = __halves2bfloat162(h0,h1), hh1 = __halves2bfloat162(h2,h3);
        __nv_bfloat162 ll0 = __floats2bfloat162_rn(l0,l1), ll1 = __floats2bfloat162_rn(l2,l3);
        uint2 hu = make_uint2(*(unsigned*)&hh0, *(unsigned*)&hh1);
        uint2 lu = make_uint2(*(unsigned*)&ll0, *(unsigned*)&ll1);
        *(uint2*)&sAh[buf][arow*ASTR + akg*4] = hu;
        *(uint2*)&sAl[buf][arow*ASTR + akg*4] = lu;
    };

    float4 av = *(const float4*)(x + (size_t)(rb+arow)*DM + akg*4);
    loadB(0, 0);
    asm volatile("cp.async.commit_group;\n");
    storeA(av, 0);
    asm volatile("cp.async.wait_group 0;\n");
    __syncthreads();

    const int a_off = (wy*16 + (lane&15))*ASTR + (lane>>4)*8;
    const int b_off = (lane&15)*BSTR + wx*96 + (lane>>4)*8;

    for (int kt=0; kt<64; kt++){
        const int buf = kt & 1;
        if (kt < 63){
            int k0 = (kt+1)*16;
            av = *(const float4*)(x + (size_t)(rb+arow)*DM + k0 + akg*4);
            loadB(k0, buf^1);
            asm volatile("cp.async.commit_group;\n");
        }
        unsigned ah0,ah1,ah2,ah3, al0,al1,al2,al3;
        ldmx4(ah0,ah1,ah2,ah3, sAh[buf] + a_off);
        ldmx4(al0,al1,al2,al3, sAl[buf] + a_off);
#pragma unroll
        for (int nb=0; nb<6; nb++){
            unsigned bh0,bh1,bh2,bh3, bl0,bl1,bl2,bl3;
            ldmx4t(bh0,bh1,bh2,bh3, sBh[buf] + b_off + nb*16);
            ldmx4t(bl0,bl1,bl2,bl3, sBl[buf] + b_off + nb*16);
            mma16816(acc[2*nb],   ah0,ah1,ah2,ah3, bh0,bh1);
            mma16816(acc[2*nb],   ah0,ah1,ah2,ah3, bl0,bl1);
            mma16816(acc[2*nb],   al0,al1,al2,al3, bh0,bh1);
            mma16816(acc[2*nb+1], ah0,ah1,ah2,ah3, bh2,bh3);
            mma16816(acc[2*nb+1], ah0,ah1,ah2,ah3, bl2,bl3);
            mma16816(acc[2*nb+1], al0,al1,al2,al3, bh2,bh3);
        }
        __syncthreads();
        if (kt < 63){
            storeA(av, buf^1);
            asm volatile("cp.async.wait_group 0;\n");
            __syncthreads();
        }
    }

    const int row0 = rb + wy*16 + (lane>>2);
#pragma unroll
    for (int t=0; t<12; t++){
        int col = wx*96 + t*8 + (lane&3)*2;
        bool act = (col < 128);
        float* base = (col < 64) ? g_q : (col < 128 ? g_k : g_v);
        int cc = col & 63;
        float v0 = acc[t][0], v1 = acc[t][1], v2 = acc[t][2], v3 = acc[t][3];
        if (act){
            v0 = (v0>0.f)? v0+1.f : expf(v0);
            v1 = (v1>0.f)? v1+1.f : expf(v1);
            v2 = (v2>0.f)? v2+1.f : expf(v2);
            v3 = (v3>0.f)? v3+1.f : expf(v3);
        }
        base[(size_t)row0*DH + cc]       = v0;
        base[(size_t)row0*DH + cc + 1]   = v1;
        base[(size_t)(row0+8)*DH + cc]   = v2;
        base[(size_t)(row0+8)*DH + cc+1] = v3;
    }
}

// =====================================================================
// shared LUT builders
// =====================================================================
__device__ __forceinline__ void build_node_lut(int* s_nd, int tid){
    if (tid < 15){
        int l = (tid<8)?0:(tid<12)?1:(tid<14)?2:3;
        int n = tid - Knoff(l);
        int bs = 4<<l, r = (l==0)?4:8;
        s_nd[tid*5+0]=bs; s_nd[tid*5+1]=r; s_nd[tid*5+2]=Knro(l)+n*r;
        s_nd[tid*5+3]=2*bs*n; s_nd[tid*5+4]=Kbso(l);
    }
}
__device__ __forceinline__ void build_ws_lut(int* s_lutAB, int tid, int nthr){
    for (int m = tid; m < 576; m += nthr){
        int l = (m<128)?0:(m<384)?1:(m<512)?2:3;
        int r = (l==0)?4:8;
        int rem = m - Kwso(l);
        int rr2 = r*r;
        int n = rem / rr2;
        int ij = rem - n*rr2;
        int i = ij / r, j = ij - i*r;
        int pb = Knro(l) + n*r;
        s_lutAB[m] = (pb+i) | ((pb+j)<<16);
    }
}
__device__ __forceinline__ void build_chunk_lut(int* s_ck, int tid){
    if (tid < 20){
        int c = tid, m, dd0=0, ext=0, ec=0;
        if (c < 13){ m = c; }
        else if (c == 13){ m=12; dd0=8; ext=1; ec=0; }
        else if (c == 14){ m=13; }
        else if (c == 15){ m=13; dd0=8; ext=1; ec=1; }
        else if (c == 16){ m=14; }
        else { m=14; dd0=8*(c-16); ext=1; ec=c-15; }
        s_ck[c] = m | (dd0<<8) | (ext<<16) | (ec<<20);
    }
}

// =====================================================================
// Pass 1: per-group (4 chunks) state sums + intra-group prefix
// grid = BB*NGRP = 256 blocks
// =====================================================================
#define P1_FLOATS (2176 + 2816 + 928 + 1280)
#define P1_BYTES (P1_FLOATS*4 + (75+576+20)*4)
__global__ __launch_bounds__(512,2) void chunk_sum4_kernel(BasePtrs bp){
    extern __shared__ float sm[];
    float* s_k    = sm;
    float* s_v    = s_k + 16*KPAD;
    float* prjULT = s_v + 16*KPAD;
    float* prjVRT = prjULT + 1408;
    float* sUL    = prjVRT + 1408;
    float* sVR    = sUL + 464;
    float* extP   = sVR + 464;
    int*   s_nd   = (int*)(extP + 1280);
    int*   lutAB  = s_nd + 75;
    int*   s_ck   = lutAB + 576;

    const int tid = threadIdx.x;
    const int blk = blockIdx.x;                 // b*NGRP + grp
    const int b = blk / NGRP, grp = blk % NGRP;

    for (int i=tid;i<464;i+=NT){
        int l = (i<16)?0:(i<80)?1:(i<208)?2:3;
        int off = i - Kbso(l);
        sUL[i] = bp.p[l][off];
        sVR[i] = bp.p[4+l][off];
    }
    build_node_lut(s_nd, tid);
    build_ws_lut(lutAB, tid, NT);
    build_chunk_lut(s_ck, tid);
    __syncthreads();

    float sreg[2][4];

    for (int j=0;j<4;j++){
        const int c = grp*4 + j;
        const float* gk = g_k + ((size_t)b*TSEQ + c*CCH)*DH;
        const float* gv = g_v + ((size_t)b*TSEQ + c*CCH)*DH;
        if (tid < 512){
            int arr = tid>>8;
            int rem = tid & 255; int row = rem>>4, g = rem&15;
            const float* src = (arr==0?gk:gv) + row*64 + g*4;
            float* dst = (arr==0?s_k:s_v) + row*KPAD + g*4;
            *(float4*)dst = *(const float4*)src;
        }
        __syncthreads();

        if (tid < 320){
            int cd = s_ck[tid>>4]; int s = tid&15;
            int m = cd & 31, dd0 = (cd>>8)&63, isext=(cd>>16)&1, ec=(cd>>20)&7;
            int bs=s_nd[m*5], r=s_nd[m*5+1], pb=s_nd[m*5+2], topo=s_nd[m*5+3], bso=s_nd[m*5+4];
            const float* kt = s_k + s*KPAD + topo + dd0;
            const float* vb = s_v + s*KPAD + topo + bs + dd0;
            const float* Ub = sUL + bso + dd0*r;
            const float* Wb = sVR + bso + dd0*r;
            if (r == 4){
                float4 aU=make_float4(0,0,0,0), aV=aU;
#pragma unroll
                for (int d=0; d<4; d++){
                    float kd=kt[d], vd=vb[d];
                    float4 u=*(const float4*)(Ub+d*4), w=*(const float4*)(Wb+d*4);
                    fma4(aU,kd,u); fma4(aV,vd,w);
                }
                float au[4]={aU.x,aU.y,aU.z,aU.w}, avv[4]={aV.x,aV.y,aV.z,aV.w};
#pragma unroll
                for (int i=0;i<4;i++){
                    prjULT[(pb+i)*16+s]=au[i];
                    prjVRT[(pb+i)*16+s]=avv[i];
                }
            } else {
                float aU[8], aV[8];
#pragma unroll
                for (int i=0;i<8;i++){ aU[i]=0.f; aV[i]=0.f; }
#pragma unroll
                for (int d=0; d<8; d++){
                    float kd=kt[d], vd=vb[d];
                    float4 u0=*(const float4*)(Ub+d*8), u1=*(const float4*)(Ub+d*8+4);
                    float4 w0=*(const float4*)(Wb+d*8), w1=*(const float4*)(Wb+d*8+4);
                    aU[0]=fmaf(kd,u0.x,aU[0]); aU[1]=fmaf(kd,u0.y,aU[1]); aU[2]=fmaf(kd,u0.z,aU[2]); aU[3]=fmaf(kd,u0.w,aU[3]);
                    aU[4]=fmaf(kd,u1.x,aU[4]); aU[5]=fmaf(kd,u1.y,aU[5]); aU[6]=fmaf(kd,u1.z,aU[6]); aU[7]=fmaf(kd,u1.w,aU[7]);
                    aV[0]=fmaf(vd,w0.x,aV[0]); aV[1]=fmaf(vd,w0.y,aV[1]); aV[2]=fmaf(vd,w0.z,aV[2]); aV[3]=fmaf(vd,w0.w,aV[3]);
                    aV[4]=fmaf(vd,w1.x,aV[4]); aV[5]=fmaf(vd,w1.y,aV[5]); aV[6]=fmaf(vd,w1.z,aV[6]); aV[7]=fmaf(vd,w1.w,aV[7]);
                }
                if (!isext){
#pragma unroll
                    for (int i=0;i<8;i++){
                        prjULT[(pb+i)*16+s]=aU[i];
                        prjVRT[(pb+i)*16+s]=aV[i];
                    }
                } else {
#pragma unroll
                    for (int i=0;i<8;i++){
                        extP[((0*5+ec)*8+i)*16+s]=aU[i];
                        extP[((1*5+ec)*8+i)*16+s]=aV[i];
                    }
                }
            }
        }
        __syncthreads();
        if (tid < 256){
            int a=tid>>7, i=(tid>>4)&7, s=tid&15;
            float* base = prjULT + a*1408;
            base[(64+i)*16+s] += extP[((a*5+0)*8+i)*16+s];
            base[(72+i)*16+s] += extP[((a*5+1)*8+i)*16+s];
            base[(80+i)*16+s] += extP[((a*5+2)*8+i)*16+s] + extP[((a*5+3)*8+i)*16+s] + extP[((a*5+4)*8+i)*16+s];
        }
        __syncthreads();

#pragma unroll
        for (int o=0;o<2;o++){
            int e = tid + o*512;
            if (e < NST){
                float acc = 0.f;
                if (e < 256){
                    int n=e>>4, i=(e>>2)&3, j2=e&3;
                    int ki=4*n+i, vi=4*n+j2;
#pragma unroll
                    for (int s=0;s<CCH;s++) acc = fmaf(s_k[s*KPAD+ki], s_v[s*KPAD+vi], acc);
                } else if (e < 832){
                    int m = e-256;
                    int ab = lutAB[m]; int a = ab & 0xffff, b3 = ab >> 16;
                    const float4* pa = (const float4*)&prjULT[a*16];
                    const float4* pb4 = (const float4*)&prjVRT[b3*16];
#pragma unroll
                    for (int g=0;g<4;g++) acc += dot4v(pa[g], pb4[g]);
                } else {
                    int d = e-832;
#pragma unroll
                    for (int s=0;s<CCH;s++) acc += s_k[s*KPAD+d];
                }
                sreg[o][j] = acc;
            }
        }
        __syncthreads();
    }

    // write intra-group exclusive prefix + group total
#pragma unroll
    for (int o=0;o<2;o++){
        int e = tid + o*512;
        if (e < NST){
            float run = 0.f;
#pragma unroll
            for (int j=0;j<4;j++){
                g_prefix[(size_t)(blk*4+j)*NST + e] = run;
                run += sreg[o][j];
            }
            g_gtot[(size_t)blk*NST + e] = run;
        }
    }
}

// =====================================================================
// Pass 2: exclusive prefix over 32 group totals per batch
// grid (7, BB), 128 threads
// =====================================================================
__global__ __launch_bounds__(128) void midscan_kernel(){
    const int b = blockIdx.y;
    const int e = blockIdx.x*128 + threadIdx.x;
    const float* gt = g_gtot + (size_t)b*NGRP*NST + e;
    float*       go = g_goff + (size_t)b*NGRP*NST + e;
    float run = 0.f;
    for (int g0=0; g0<NGRP; g0+=8){
        float v[8];
#pragma unroll
        for (int j=0;j<8;j++) v[j] = gt[(size_t)(g0+j)*NST];
#pragma unroll
        for (int j=0;j<8;j++){ go[(size_t)(g0+j)*NST] = run; run += v[j]; }
    }
}

// =====================================================================
// Pass 3: fully parallel intra-chunk attention, 2 chunks per block
// grid = BB*NCH/2 = 512 blocks
// =====================================================================
#define P3_FLOATS (3264 + 5632 + 1856 + 896 + 3840 + 3840 + 2560 + 256 + 16 + 1496 + 1496 + 1088)
#define P3_BYTES (P3_FLOATS*4 + (75 + 88*3 + 20)*4)
__global__ __launch_bounds__(512,2) void chunk_scan_kernel(BasePtrs bp){
    extern __shared__ float sm[];
    float* s_k    = sm;
    float* s_v    = s_k + 16*KPAD;
    float* s_q    = s_v + 16*KPAD;
    float* prjULT = s_q + 16*KPAD;
    float* prjVRT = prjULT + 1408;
    float* prjXT  = prjVRT + 1408;
    float* prjLT  = prjXT + 1408;
    float* sUL    = prjLT + 1408;
    float* sVR    = sUL + 464;
    float* sUR    = sVR + 464;
    float* sVL    = sUR + 464;
    float* s_leaf = sVL + 464;
    float* s_Ws   = s_leaf + 256;
    float* s_z    = s_Ws + 576;
    float* Asc    = s_z + 64;
    float* Bsc    = Asc + 3840;
    float* extP   = Bsc + 3840;
    float* Dsc    = extP + 2560;
    float* s_den  = Dsc + 256;
    float* TT     = s_den + 16;
    float* TBB    = TT + 1496;
    float* yl     = TBB + 1496;
    int*   s_nd   = (int*)(yl + 1088);
    int*   lutP   = s_nd + 75;
    int*   lutWT  = lutP + 88;
    int*   lutWB  = lutWT + 88;
    int*   s_ck   = lutWB + 88;

    const int tid = threadIdx.x;
    const int blk = blockIdx.x;                 // 0..511
    const int b = blk / (NCH/2), cp = blk % (NCH/2);

    // one-time: bases + LUTs
    for (int i=tid;i<464;i+=NT){
        int l = (i<16)?0:(i<80)?1:(i<208)?2:3;
        int off = i - Kbso(l);
        sUL[i] = bp.p[l   ][off];
        sVR[i] = bp.p[4+l ][off];
        sUR[i] = bp.p[8+l ][off];
        sVL[i] = bp.p[12+l][off];
    }
    build_node_lut(s_nd, tid);
    build_chunk_lut(s_ck, tid);
    if (tid < 88){
        int i88 = tid;
        int l = (i88<32)?0:(i88<64)?1:(i88<80)?2:3;
        int r = (l==0)?4:8;
        int rem = i88 - Knro(l);
        int n = rem / r, i = rem - n*r;
        int pb = Knro(l) + n*r;
        int ng = Knoff(l) + n;
        lutP[i88]  = pb | (ng<<8) | (r<<16);
        lutWT[i88] = Kwso(l) + n*r*r + i*r;
        lutWB[i88] = Kwso(l) + n*r*r + i;
    }

    for (int cc=0; cc<2; cc++){
        const int c = cp*2 + cc;
        const int ci = b*NCH + c;
        const float* gk = g_k + ((size_t)b*TSEQ + c*CCH)*DH;
        const float* gv = g_v + ((size_t)b*TSEQ + c*CCH)*DH;
        const float* gq = g_q + ((size_t)b*TSEQ + c*CCH)*DH;
        __nv_bfloat16* g_oh = g_ah + ((size_t)b*TSEQ + c*CCH)*DH;
        __nv_bfloat16* g_ol = g_al + ((size_t)b*TSEQ + c*CCH)*DH;

        // init: k/v/q + state (local prefix + group offset)
        for (int i=tid;i<768;i+=NT){
            int arr = i>>8;
            int rem = i & 255; int row = rem>>4, g = rem&15;
            const float* src = (arr==0?gk:(arr==1?gv:gq)) + row*64 + g*4;
            float* dst = (arr==0?s_k:(arr==1?s_v:s_q)) + row*KPAD + g*4;
            *(float4*)dst = *(const float4*)src;
        }
        {
            const float* gp = g_prefix + (size_t)ci*NST;
            const float* gof = g_goff + ((size_t)(b*NGRP) + (c>>2))*NST;
            for (int e=tid;e<NST;e+=NT){
                float vle = gp[e] + gof[e];
                if (e<256) s_leaf[e]=vle;
                else if (e<832) s_Ws[e-256]=vle;
                else s_z[e-832]=vle;
            }
        }
        __syncthreads();

        // phase P: projections + D scores
        if (tid < 320){
            int cd = s_ck[tid>>4]; int s = tid&15;
            int m = cd & 31, dd0 = (cd>>8)&63, isext=(cd>>16)&1, ec=(cd>>20)&7;
            int bs=s_nd[m*5], r=s_nd[m*5+1], pb=s_nd[m*5+2], topo=s_nd[m*5+3], bso=s_nd[m*5+4];
            const float* kt = s_k + s*KPAD + topo + dd0;
            const float* vb = s_v + s*KPAD + topo + bs + dd0;
            const float* qt = s_q + s*KPAD + topo + dd0;
            const float* qb = s_q + s*KPAD + topo + bs + dd0;
            const float* Ub = sUL + bso + dd0*r;
            const float* Wb = sVR + bso + dd0*r;
            const float* Xb = sVL + bso + dd0*r;
            if (r == 4){
                float4 aU=make_float4(0,0,0,0), aV=aU, aX=aU, aL=aU;
#pragma unroll
                for (int d=0; d<4; d++){
                    float kd=kt[d], vd=vb[d], qtd=qt[d], qbd=qb[d];
                    float4 u=*(const float4*)(Ub+d*4), w=*(const float4*)(Wb+d*4), x=*(const float4*)(Xb+d*4);
                    fma4(aU,kd,u); fma4(aV,vd,w); fma4(aX,qbd,w); fma4(aL,qtd,x);
                }
                float t0[4]={aU.x,aU.y,aU.z,aU.w}, t1[4]={aV.x,aV.y,aV.z,aV.w};
                float t2[4]={aX.x,aX.y,aX.z,aX.w}, t3[4]={aL.x,aL.y,aL.z,aL.w};
#pragma unroll
                for (int i=0;i<4;i++){
                    prjULT[(pb+i)*16+s]=t0[i];
                    prjVRT[(pb+i)*16+s]=t1[i];
                    prjXT [(pb+i)*16+s]=t2[i];
                    prjLT [(pb+i)*16+s]=t3[i];
                }
            } else {
                {
                    float aU[8], aV[8];
#pragma unroll
                    for (int i=0;i<8;i++){ aU[i]=0.f; aV[i]=0.f; }
#pragma unroll
                    for (int d=0; d<8; d++){
                        float kd=kt[d], vd=vb[d];
                        float4 u0=*(const float4*)(Ub+d*8), u1=*(const float4*)(Ub+d*8+4);
                        float4 w0=*(const float4*)(Wb+d*8), w1=*(const float4*)(Wb+d*8+4);
                        aU[0]=fmaf(kd,u0.x,aU[0]); aU[1]=fmaf(kd,u0.y,aU[1]); aU[2]=fmaf(kd,u0.z,aU[2]); aU[3]=fmaf(kd,u0.w,aU[3]);
                        aU[4]=fmaf(kd,u1.x,aU[4]); aU[5]=fmaf(kd,u1.y,aU[5]); aU[6]=fmaf(kd,u1.z,aU[6]); aU[7]=fmaf(kd,u1.w,aU[7]);
                        aV[0]=fmaf(vd,w0.x,aV[0]); aV[1]=fmaf(vd,w0.y,aV[1]); aV[2]=fmaf(vd,w0.z,aV[2]); aV[3]=fmaf(vd,w0.w,aV[3]);
                        aV[4]=fmaf(vd,w1.x,aV[4]); aV[5]=fmaf(vd,w1.y,aV[5]); aV[6]=fmaf(vd,w1.z,aV[6]); aV[7]=fmaf(vd,w1.w,aV[7]);
                    }
                    if (!isext){
#pragma unroll
                        for (int i=0;i<8;i++){ prjULT[(pb+i)*16+s]=aU[i]; prjVRT[(pb+i)*16+s]=aV[i]; }
                    } else {
#pragma unroll
                        for (int i=0;i<8;i++){
                            extP[((0*5+ec)*8+i)*16+s]=aU[i];
                            extP[((1*5+ec)*8+i)*16+s]=aV[i];
                        }
                    }
                }
                {
                    float aX[8], aL[8];
#pragma unroll
                    for (int i=0;i<8;i++){ aX[i]=0.f; aL[i]=0.f; }
#pragma unroll
                    for (int d=0; d<8; d++){
                        float qbd=qb[d], qtd=qt[d];
                        float4 w0=*(const float4*)(Wb+d*8), w1=*(const float4*)(Wb+d*8+4);
                        float4 x0=*(const float4*)(Xb+d*8), x1=*(const float4*)(Xb+d*8+4);
                        aX[0]=fmaf(qbd,w0.x,aX[0]); aX[1]=fmaf(qbd,w0.y,aX[1]); aX[2]=fmaf(qbd,w0.z,aX[2]); aX[3]=fmaf(qbd,w0.w,aX[3]);
                        aX[4]=fmaf(qbd,w1.x,aX[4]); aX[5]=fmaf(qbd,w1.y,aX[5]); aX[6]=fmaf(qbd,w1.z,aX[6]); aX[7]=fmaf(qbd,w1.w,aX[7]);
                        aL[0]=fmaf(qtd,x0.x,aL[0]); aL[1]=fmaf(qtd,x0.y,aL[1]); aL[2]=fmaf(qtd,x0.z,aL[2]); aL[3]=fmaf(qtd,x0.w,aL[3]);
                        aL[4]=fmaf(qtd,x1.x,aL[4]); aL[5]=fmaf(qtd,x1.y,aL[5]); aL[6]=fmaf(qtd,x1.z,aL[6]); aL[7]=fmaf(qtd,x1.w,aL[7]);
                    }
                    if (!isext){
#pragma unroll
                        for (int i=0;i<8;i++){ prjXT[(pb+i)*16+s]=aX[i]; prjLT[(pb+i)*16+s]=aL[i]; }
                    } else {
#pragma unroll
                        for (int i=0;i<8;i++){
                            extP[((2*5+ec)*8+i)*16+s]=aX[i];
                            extP[((3*5+ec)*8+i)*16+s]=aL[i];
                        }
                    }
                }
            }
        } else {
            int j = tid - 320;
#pragma unroll
            for (int rep=0; rep<2; rep++){
                if (j < 256){
                    int t = j>>4, s = j&15;
                    float acc = 0.f;
#pragma unroll
                    for (int g=0;g<16;g++)
                        acc += dot4v(*(const float4*)&s_k[s*KPAD+4*g], *(const float4*)&s_q[t*KPAD+4*g]);
                    Dsc[j] = acc;
                }
                j += 192;
            }
        }
        __syncthreads();
        {
            int a=tid>>7, i=(tid>>4)&7, s=tid&15;
            float* base = prjULT + a*1408;
            base[(64+i)*16+s] += extP[((a*5+0)*8+i)*16+s];
            base[(72+i)*16+s] += extP[((a*5+1)*8+i)*16+s];
            base[(80+i)*16+s] += extP[((a*5+2)*8+i)*16+s] + extP[((a*5+3)*8+i)*16+s] + extP[((a*5+4)*8+i)*16+s];
        }
        __syncthreads();

        // scores + yl + den
        for (int j=tid; j<752; j+=NT){
            if (j < 240){
                int ng = j>>4, t = j&15;
                int pb = s_nd[ng*5+2];
                float4 a0=make_float4(0,0,0,0), a1=a0, a2=a0, a3=a0;
                if (ng < 8){
#pragma unroll
                    for (int i=0;i<4;i++){
                        float w = prjXT[(pb+i)*16+t];
                        const float4* vr = (const float4*)&prjVRT[(pb+i)*16];
                        fma4(a0,w,vr[0]); fma4(a1,w,vr[1]); fma4(a2,w,vr[2]); fma4(a3,w,vr[3]);
                    }
                } else {
#pragma unroll
                    for (int i=0;i<8;i++){
                        float w = prjXT[(pb+i)*16+t];
                        const float4* vr = (const float4*)&prjVRT[(pb+i)*16];
                        fma4(a0,w,vr[0]); fma4(a1,w,vr[1]); fma4(a2,w,vr[2]); fma4(a3,w,vr[3]);
                    }
                }
                float* dst = &Asc[(ng*16+t)*16];
                dst[0]=a0.x; dst[1]=(1<=t)?a0.y:0.f; dst[2]=(2<=t)?a0.z:0.f; dst[3]=(3<=t)?a0.w:0.f;
                dst[4]=(4<=t)?a1.x:0.f; dst[5]=(5<=t)?a1.y:0.f; dst[6]=(6<=t)?a1.z:0.f; dst[7]=(7<=t)?a1.w:0.f;
                dst[8]=(8<=t)?a2.x:0.f; dst[9]=(9<=t)?a2.y:0.f; dst[10]=(10<=t)?a2.z:0.f; dst[11]=(11<=t)?a2.w:0.f;
                dst[12]=(12<=t)?a3.x:0.f; dst[13]=(13<=t)?a3.y:0.f; dst[14]=(14<=t)?a3.z:0.f; dst[15]=(15<=t)?a3.w:0.f;
            } else if (j < 480){
                int jj = j-240;
                int ng = jj>>4, t = jj&15;
                int pb = s_nd[ng*5+2];
                float4 a0=make_float4(0,0,0,0), a1=a0, a2=a0, a3=a0;
                if (ng < 8){
#pragma unroll
                    for (int i=0;i<4;i++){
                        float w = prjLT[(pb+i)*16+t];
                        const float4* ul = (const float4*)&prjULT[(pb+i)*16];
                        fma4(a0,w,ul[0]); fma4(a1,w,ul[1]); fma4(a2,w,ul[2]); fma4(a3,w,ul[3]);
                    }
                } else {
#pragma unroll
                    for (int i=0;i<8;i++){
                        float w = prjLT[(pb+i)*16+t];
                        const float4* ul = (const float4*)&prjULT[(pb+i)*16];
                        fma4(a0,w,ul[0]); fma4(a1,w,ul[1]); fma4(a2,w,ul[2]); fma4(a3,w,ul[3]);
                    }
                }
                float* dst = &Bsc[(ng*16+t)*16];
                dst[0]=a0.x; dst[1]=(1<=t)?a0.y:0.f; dst[2]=(2<=t)?a0.z:0.f; dst[3]=(3<=t)?a0.w:0.f;
                dst[4]=(4<=t)?a1.x:0.f; dst[5]=(5<=t)?a1.y:0.f; dst[6]=(6<=t)?a1.z:0.f; dst[7]=(7<=t)?a1.w:0.f;
                dst[8]=(8<=t)?a2.x:0.f; dst[9]=(9<=t)?a2.y:0.f; dst[10]=(10<=t)?a2.z:0.f; dst[11]=(11<=t)?a2.w:0.f;
                dst[12]=(12<=t)?a3.x:0.f; dst[13]=(13<=t)?a3.y:0.f; dst[14]=(14<=t)?a3.z:0.f; dst[15]=(15<=t)?a3.w:0.f;
            } else if (j < 736){
                int jj = j-480;
                int n = jj>>4, t = jj&15;
                float4 qv = *(const float4*)&s_q[t*KPAD+4*n];
                float cvals[16];
#pragma unroll
                for (int s=0;s<16;s++){
                    float val = dot4v(*(const float4*)&s_v[s*KPAD+4*n], qv);
                    cvals[s] = (s<=t)? val : 0.f;
                }
                float acc0 = dot4v(*(const float4*)&s_leaf[(4*n+0)*4], qv);
                float acc1 = dot4v(*(const float4*)&s_leaf[(4*n+1)*4], qv);
                float acc2 = dot4v(*(const float4*)&s_leaf[(4*n+2)*4], qv);
                float acc3 = dot4v(*(const float4*)&s_leaf[(4*n+3)*4], qv);
#pragma unroll
                for (int s=0;s<16;s++){
                    float4 kv = *(const float4*)&s_k[s*KPAD+4*n];
                    float cs = cvals[s];
                    acc0 = fmaf(kv.x, cs, acc0);
                    acc1 = fmaf(kv.y, cs, acc1);
                    acc2 = fmaf(kv.z, cs, acc2);
                    acc3 = fmaf(kv.w, cs, acc3);
                }
                yl[(4*n+0)*17+t] = acc0;
                yl[(4*n+1)*17+t] = acc1;
                yl[(4*n+2)*17+t] = acc2;
                yl[(4*n+3)*17+t] = acc3;
            } else {
                int t = j-736;
                float acc = 0.f;
#pragma unroll
                for (int g=0;g<16;g++)
                    acc += dot4v(*(const float4*)&s_z[4*g], *(const float4*)&s_q[t*KPAD+4*g]);
                for (int s=0;s<=t;s++) acc += Dsc[t*16+s];
                s_den[t] = fmaxf(acc, 1e-6f);
            }
        }
        __syncthreads();

        // TT / TBB
        for (int j=tid; j<2816; j+=NT){
            if (j < 1408){
                int i88 = j>>4, t = j&15;
                int info = lutP[i88]; int pb = info&255, ng=(info>>8)&255;
                float acc = 0.f;
                int wr = lutWT[i88];
                if (i88 < 32){
#pragma unroll
                    for (int u=0;u<4;u++) acc = fmaf(s_Ws[wr+u], prjXT[(pb+u)*16+t], acc);
                } else {
#pragma unroll
                    for (int u=0;u<8;u++) acc = fmaf(s_Ws[wr+u], prjXT[(pb+u)*16+t], acc);
                }
                const float4* uu = (const float4*)&prjULT[i88*16];
                const float4* aa = (const float4*)&Asc[(ng*16+t)*16];
                acc += dot4v(uu[0],aa[0]) + dot4v(uu[1],aa[1]) + dot4v(uu[2],aa[2]) + dot4v(uu[3],aa[3]);
                TT[i88*17+t] = acc;
            } else {
                int jj = j-1408;
                int i88 = jj>>4, t = jj&15;
                int info = lutP[i88]; int pb = info&255, ng=(info>>8)&255;
                float acc = 0.f;
                int wc = lutWB[i88];
                if (i88 < 32){
#pragma unroll
                    for (int u=0;u<4;u++) acc = fmaf(s_Ws[wc+u*4], prjLT[(pb+u)*16+t], acc);
                } else {
#pragma unroll
                    for (int u=0;u<8;u++) acc = fmaf(s_Ws[wc+u*8], prjLT[(pb+u)*16+t], acc);
                }
                const float4* vv = (const float4*)&prjVRT[i88*16];
                const float4* bb = (const float4*)&Bsc[(ng*16+t)*16];
                acc += dot4v(vv[0],bb[0]) + dot4v(vv[1],bb[1]) + dot4v(vv[2],bb[2]) + dot4v(vv[3],bb[3]);
                TBB[i88*17+t] = acc;
            }
        }
        __syncthreads();

        // final assembly
        for (int j=tid; j<1024; j+=NT){
            int d = j&63, t = j>>6;
            float y = yl[d*17+t];
#pragma unroll
            for (int l=0;l<4;l++){
                const int bs = 4<<l;
                const int r  = (l==0)?4:8;
                const int n = d >> (3+l);
                const int loc = d & (2*bs - 1);
                const int pb = Knro(l) + n*r;
                const int bso = Kbso(l);
                if (loc < bs){
                    const float* u = sUL + bso + loc*r;
#pragma unroll
                    for (int i=0;i<8;i++){
                        if (i < r) y = fmaf(u[i], TT[(pb+i)*17+t], y);
                    }
                } else {
                    const float* u = sUR + bso + (loc-bs)*r;
#pragma unroll
                    for (int i=0;i<8;i++){
                        if (i < r) y = fmaf(u[i], TBB[(pb+i)*17+t], y);
                    }
                }
            }
            float o = y / s_den[t];
            __nv_bfloat16 h = __float2bfloat16(o);
            g_oh[(size_t)t*DH + d] = h;
            g_ol[(size_t)t*DH + d] = __float2bfloat16(o - __bfloat162float(h));
        }
    }
}

// ---------------- output GEMM via mma.sync bf16x3 ----------------
#define WA 72
#define WB 136
#define WO_BYTES ((128*WA*2 + 64*WB*2)*2)
__global__ __launch_bounds__(256) void wo_mma_kernel(float* __restrict__ out){
    extern __shared__ __nv_bfloat16 ws[];
    __nv_bfloat16* sAh = ws;
    __nv_bfloat16* sAl = sAh + 128*WA;
    __nv_bfloat16* sBh = sAl + 128*WA;
    __nv_bfloat16* sBl = sBh + 64*WB;

    const int tid = threadIdx.x;
    const int wid = tid >> 5, lane = tid & 31;
    const int wy = wid & 3, wx = wid >> 2;
    const int rb = blockIdx.x * 128, cb = blockIdx.y * 128;

#pragma unroll
    for (int i=0;i<4;i++){
        int idx = tid + i*256;
        int row = idx >> 3, c8 = idx & 7;
        cp_async16(sAh + row*WA + c8*8, g_ah + (size_t)(rb+row)*DH + c8*8);
        cp_async16(sAl + row*WA + c8*8, g_al + (size_t)(rb+row)*DH + c8*8);
    }
#pragma unroll
    for (int i=0;i<4;i++){
        int idx = tid + i*256;
        int k = idx >> 4, c16 = idx & 15;
        cp_async16(sBh + k*WB + c16*8, g_woh + (size_t)k*DM + cb + c16*8);
        cp_async16(sBl + k*WB + c16*8, g_wol + (size_t)k*DM + cb + c16*8);
    }
    asm volatile("cp.async.commit_group;\n");
    asm volatile("cp.async.wait_group 0;\n");
    __syncthreads();

    float acc[2][8][4];
#pragma unroll
    for (int m=0;m<2;m++)
#pragma unroll
        for (int n=0;n<8;n++){ acc[m][n][0]=acc[m][n][1]=acc[m][n][2]=acc[m][n][3]=0.f; }

#pragma unroll
    for (int k0=0;k0<64;k0+=16){
        unsigned ah[2][4], al[2][4];
#pragma unroll
        for (int mt=0;mt<2;mt++){
            const __nv_bfloat16* ap = sAh + (wy*32 + mt*16 + (lane&15))*WA + k0 + (lane>>4)*8;
            ldmx4(ah[mt][0],ah[mt][1],ah[mt][2],ah[mt][3], ap);
            const __nv_bfloat16* ap2 = sAl + (wy*32 + mt*16 + (lane&15))*WA + k0 + (lane>>4)*8;
            ldmx4(al[mt][0],al[mt][1],al[mt][2],al[mt][3], ap2);
        }
#pragma unroll
        for (int nt=0;nt<4;nt++){
            unsigned bh0,bh1,bh2,bh3, bl0,bl1,bl2,bl3;
            const __nv_bfloat16* bp = sBh + (k0 + (lane&15))*WB + wx*64 + nt*16 + (lane>>4)*8;
            ldmx4t(bh0,bh1,bh2,bh3, bp);
            const __nv_bfloat16* bp2 = sBl + (k0 + (lane&15))*WB + wx*64 + nt*16 + (lane>>4)*8;
            ldmx4t(bl0,bl1,bl2,bl3, bp2);
#pragma unroll
            for (int mt=0;mt<2;mt++){
                mma16816(acc[mt][2*nt],   ah[mt][0],ah[mt][1],ah[mt][2],ah[mt][3], bh0,bh1);
                mma16816(acc[mt][2*nt],   ah[mt][0],ah[mt][1],ah[mt][2],ah[mt][3], bl0,bl1);
                mma16816(acc[mt][2*nt],   al[mt][0],al[mt][1],al[mt][2],al[mt][3], bh0,bh1);
                mma16816(acc[mt][2*nt+1], ah[mt][0],ah[mt][1],ah[mt][2],ah[mt][3], bh2,bh3);
                mma16816(acc[mt][2*nt+1], ah[mt][0],ah[mt][1],ah[mt][2],ah[mt][3], bl2,bl3);
                mma16816(acc[mt][2*nt+1], al[mt][0],al[mt][1],al[mt][2],al[mt][3], bh2,bh3);
            }
        }
    }

#pragma unroll
    for (int mt=0;mt<2;mt++){
        int row = rb + wy*32 + mt*16 + (lane>>2);
#pragma unroll
        for (int nt=0;nt<8;nt++){
            int col = cb + wx*64 + nt*8 + (lane&3)*2;
            *(float2*)(out + (size_t)row*DM + col)     = make_float2(acc[mt][nt][0], acc[mt][nt][1]);
            *(float2*)(out + (size_t)(row+8)*DM + col) = make_float2(acc[mt][nt][2], acc[mt][nt][3]);
        }
    }
}

extern "C" void kernel_launch(void* const* d_in, const int* in_sizes, int n_in,
                              void* d_out, int out_size){
    (void)in_sizes; (void)n_in; (void)out_size;
    const float* x  = (const float*)d_in[0];
    const float* Wq = (const float*)d_in[1];
    const float* Wk = (const float*)d_in[2];
    const float* Wv = (const float*)d_in[3];
    const float* Wo = (const float*)d_in[4];
    BasePtrs bp;
    for(int i=0;i<16;i++) bp.p[i] = (const float*)d_in[5+i];
    float* out = (float*)d_out;

    cudaFuncSetAttribute(chunk_sum4_kernel, cudaFuncAttributeMaxDynamicSharedMemorySize, P1_BYTES);
    cudaFuncSetAttribute(chunk_scan_kernel, cudaFuncAttributeMaxDynamicSharedMemorySize, P3_BYTES);
    cudaFuncSetAttribute(wo_mma_kernel,     cudaFuncAttributeMaxDynamicSharedMemorySize, WO_BYTES);

    wprep_kernel<<<(DM*NW + DH*DM)/256, 256>>>(Wq, Wk, Wv, Wo);
    qkv_mma_kernel<<<NTOK/64, 256>>>(x);
    chunk_sum4_kernel<<<BB*NGRP, NT, P1_BYTES>>>(bp);
    midscan_kernel<<<dim3(NST/128, BB), 128>>>();
    chunk_scan_kernel<<<BB*NCH/2, NT, P3_BYTES>>>(bp);
    wo_mma_kernel<<<dim3(NTOK/128, DM/128), 256, WO_BYTES>>>(out);
}

// round 9
// speedup vs baseline: 66.1962x; 1.1033x over previous
#include <cuda_runtime.h>
#include <cuda_bf16.h>
#include <math.h>

#define TSEQ 2048
#define BB 8
#define DH 64
#define DM 1024
#define NTOK (BB*TSEQ)
#define CCH 16
#define NCH (TSEQ/CCH)   /* 128 */
#define NST 896
#define KPAD 68
#define NT 512
#define NW 192
#define NGRP 32          /* chunk groups of 4 per batch */

// scratch (device globals -- no allocation allowed)
__device__ float g_q[NTOK*DH];
__device__ float g_k[NTOK*DH];
__device__ float g_v[NTOK*DH];
__device__ float g_prefix[BB*NCH*NST];     // intra-group exclusive prefix
__device__ float g_gtot[BB*NGRP*NST];      // group totals
__device__ float g_goff[BB*NGRP*NST];      // exclusive prefix over groups
__device__ __nv_bfloat16 g_wh[DM*NW];
__device__ __nv_bfloat16 g_wl[DM*NW];
__device__ __nv_bfloat16 g_ah[NTOK*DH];
__device__ __nv_bfloat16 g_al[NTOK*DH];
__device__ __nv_bfloat16 g_woh[DH*DM];
__device__ __nv_bfloat16 g_wol[DH*DM];

struct BasePtrs { const float* p[16]; }; // UL0-3, VR0-3, UR0-3, VL0-3

// ---------------- helpers ----------------
__device__ __forceinline__ void cp_async16(void* sptr, const void* gptr){
    unsigned s = (unsigned)__cvta_generic_to_shared(sptr);
    asm volatile("cp.async.ca.shared.global [%0], [%1], 16;" :: "r"(s), "l"(gptr));
}
__device__ __forceinline__ float dot4v(float4 a, float4 b){
    return fmaf(a.x,b.x, fmaf(a.y,b.y, fmaf(a.z,b.z, a.w*b.w)));
}
__device__ __forceinline__ void fma4(float4 &acc, float s, float4 v){
    acc.x = fmaf(s, v.x, acc.x); acc.y = fmaf(s, v.y, acc.y);
    acc.z = fmaf(s, v.z, acc.z); acc.w = fmaf(s, v.w, acc.w);
}
__device__ __forceinline__ unsigned smem_u32(const void* p){
    return (unsigned)__cvta_generic_to_shared(p);
}
__device__ __forceinline__ void ldmx4(unsigned &r0, unsigned &r1, unsigned &r2, unsigned &r3, const void* p){
    asm volatile("ldmatrix.sync.aligned.m8n8.x4.shared.b16 {%0,%1,%2,%3}, [%4];"
        : "=r"(r0),"=r"(r1),"=r"(r2),"=r"(r3) : "r"(smem_u32(p)));
}
__device__ __forceinline__ void ldmx4t(unsigned &r0, unsigned &r1, unsigned &r2, unsigned &r3, const void* p){
    asm volatile("ldmatrix.sync.aligned.m8n8.x4.trans.shared.b16 {%0,%1,%2,%3}, [%4];"
        : "=r"(r0),"=r"(r1),"=r"(r2),"=r"(r3) : "r"(smem_u32(p)));
}
__device__ __forceinline__ void mma16816(float* c, unsigned a0,unsigned a1,unsigned a2,unsigned a3,
                                         unsigned b0, unsigned b1){
    asm volatile("mma.sync.aligned.m16n8k16.row.col.f32.bf16.bf16.f32 "
        "{%0,%1,%2,%3}, {%4,%5,%6,%7}, {%8,%9}, {%0,%1,%2,%3};"
        : "+f"(c[0]),"+f"(c[1]),"+f"(c[2]),"+f"(c[3])
        : "r"(a0),"r"(a1),"r"(a2),"r"(a3),"r"(b0),"r"(b1));
}

__device__ __forceinline__ int Knro(int l){ return (l==0)?0:(l==1)?32:(l==2)?64:80; }
__device__ __forceinline__ int Kwso(int l){ return (l==0)?0:(l==1)?128:(l==2)?384:512; }
__device__ __forceinline__ int Kbso(int l){ return (l==0)?0:(l==1)?16:(l==2)?80:208; }
__device__ __forceinline__ int Knoff(int l){ return (l==0)?0:(l==1)?8:(l==2)?12:14; }

// ---------------- weight split prep ----------------
__global__ __launch_bounds__(256) void wprep_kernel(const float* __restrict__ Wq,
                                                    const float* __restrict__ Wk,
                                                    const float* __restrict__ Wv,
                                                    const float* __restrict__ Wo){
    int idx = blockIdx.x*256 + threadIdx.x;
    if (idx < DM*NW){
        int k = idx / NW, n = idx - k*NW;
        const float* W = (n<64)?Wq:(n<128?Wk:Wv);
        float w = W[(size_t)k*DH + (n&63)];
        __nv_bfloat16 hi = __float2bfloat16(w);
        g_wh[idx] = hi;
        g_wl[idx] = __float2bfloat16(w - __bfloat162float(hi));
    } else {
        int j = idx - DM*NW;
        float w = Wo[j];
        __nv_bfloat16 hi = __float2bfloat16(w);
        g_woh[j] = hi;
        g_wol[j] = __float2bfloat16(w - __bfloat162float(hi));
    }
}

// ---------------- QKV via mma.sync bf16x3 ----------------
#define ASTR 24
#define BSTR 200
__global__ __launch_bounds__(256) void qkv_mma_kernel(const float* __restrict__ x){
    __shared__ __nv_bfloat16 sAh[2][64*ASTR];
    __shared__ __nv_bfloat16 sAl[2][64*ASTR];
    __shared__ __nv_bfloat16 sBh[2][16*BSTR];
    __shared__ __nv_bfloat16 sBl[2][16*BSTR];

    const int tid = threadIdx.x;
    const int wid = tid >> 5, lane = tid & 31;
    const int wy = wid & 3, wx = wid >> 2;
    const int rb = blockIdx.x * 64;
    const int arow = tid >> 2, akg = tid & 3;

    float acc[12][4];
#pragma unroll
    for (int i=0;i<12;i++){ acc[i][0]=acc[i][1]=acc[i][2]=acc[i][3]=0.f; }

    auto loadB = [&](int k0, int buf){
#pragma unroll
        for (int i=0;i<3;i++){
            int idx = tid + i*256;
            int m2 = (idx >= 384);
            int id2 = idx - m2*384;
            int r = id2 / 24, c8 = id2 - r*24;
            const __nv_bfloat16* src = (m2 ? g_wl : g_wh) + (size_t)(k0+r)*NW + c8*8;
            __nv_bfloat16* dst = (m2 ? sBl[buf] : sBh[buf]) + r*BSTR + c8*8;
            cp_async16(dst, src);
        }
    };
    auto storeA = [&](float4 v, int buf){
        __nv_bfloat16 h0=__float2bfloat16(v.x), h1=__float2bfloat16(v.y),
                      h2=__float2bfloat16(v.z), h3=__float2bfloat16(v.w);
        float l0 = v.x-__bfloat162float(h0), l1 = v.y-__bfloat162float(h1),
              l2 = v.z-__bfloat162float(h2), l3 = v.w-__bfloat162float(h3);
        __nv_bfloat162 hh0 = __halves2bfloat162(h0,h1), hh1 = __halves2bfloat162(h2,h3);
        __nv_bfloat162 ll0 = __floats2bfloat162_rn(l0,l1), ll1 = __floats2bfloat162_rn(l2,l3);
        uint2 hu = make_uint2(*(unsigned*)&hh0, *(unsigned*)&hh1);
        uint2 lu = make_uint2(*(unsigned*)&ll0, *(unsigned*)&ll1);
        *(uint2*)&sAh[buf][arow*ASTR + akg*4] = hu;
        *(uint2*)&sAl[buf][arow*ASTR + akg*4] = lu;
    };

    float4 av = *(const float4*)(x + (size_t)(rb+arow)*DM + akg*4);
    loadB(0, 0);
    asm volatile("cp.async.commit_group;\n");
    storeA(av, 0);
    asm volatile("cp.async.wait_group 0;\n");
    __syncthreads();

    const int a_off = (wy*16 + (lane&15))*ASTR + (lane>>4)*8;
    const int b_off = (lane&15)*BSTR + wx*96 + (lane>>4)*8;

    for (int kt=0; kt<64; kt++){
        const int buf = kt & 1;
        if (kt < 63){
            int k0 = (kt+1)*16;
            av = *(const float4*)(x + (size_t)(rb+arow)*DM + k0 + akg*4);
            loadB(k0, buf^1);
            asm volatile("cp.async.commit_group;\n");
        }
        unsigned ah0,ah1,ah2,ah3, al0,al1,al2,al3;
        ldmx4(ah0,ah1,ah2,ah3, sAh[buf] + a_off);
        ldmx4(al0,al1,al2,al3, sAl[buf] + a_off);
#pragma unroll
        for (int nb=0; nb<6; nb++){
            unsigned bh0,bh1,bh2,bh3, bl0,bl1,bl2,bl3;
            ldmx4t(bh0,bh1,bh2,bh3, sBh[buf] + b_off + nb*16);
            ldmx4t(bl0,bl1,bl2,bl3, sBl[buf] + b_off + nb*16);
            mma16816(acc[2*nb],   ah0,ah1,ah2,ah3, bh0,bh1);
            mma16816(acc[2*nb],   ah0,ah1,ah2,ah3, bl0,bl1);
            mma16816(acc[2*nb],   al0,al1,al2,al3, bh0,bh1);
            mma16816(acc[2*nb+1], ah0,ah1,ah2,ah3, bh2,bh3);
            mma16816(acc[2*nb+1], ah0,ah1,ah2,ah3, bl2,bl3);
            mma16816(acc[2*nb+1], al0,al1,al2,al3, bh2,bh3);
        }
        __syncthreads();
        if (kt < 63){
            storeA(av, buf^1);
            asm volatile("cp.async.wait_group 0;\n");
            __syncthreads();
        }
    }

    const int row0 = rb + wy*16 + (lane>>2);
#pragma unroll
    for (int t=0; t<12; t++){
        int col = wx*96 + t*8 + (lane&3)*2;
        bool act = (col < 128);
        float* base = (col < 64) ? g_q : (col < 128 ? g_k : g_v);
        int cc = col & 63;
        float v0 = acc[t][0], v1 = acc[t][1], v2 = acc[t][2], v3 = acc[t][3];
        if (act){
            v0 = (v0>0.f)? v0+1.f : expf(v0);
            v1 = (v1>0.f)? v1+1.f : expf(v1);
            v2 = (v2>0.f)? v2+1.f : expf(v2);
            v3 = (v3>0.f)? v3+1.f : expf(v3);
        }
        base[(size_t)row0*DH + cc]       = v0;
        base[(size_t)row0*DH + cc + 1]   = v1;
        base[(size_t)(row0+8)*DH + cc]   = v2;
        base[(size_t)(row0+8)*DH + cc+1] = v3;
    }
}

// =====================================================================
// shared LUT builders
// =====================================================================
__device__ __forceinline__ void build_node_lut(int* s_nd, int tid){
    if (tid < 15){
        int l = (tid<8)?0:(tid<12)?1:(tid<14)?2:3;
        int n = tid - Knoff(l);
        int bs = 4<<l, r = (l==0)?4:8;
        s_nd[tid*5+0]=bs; s_nd[tid*5+1]=r; s_nd[tid*5+2]=Knro(l)+n*r;
        s_nd[tid*5+3]=2*bs*n; s_nd[tid*5+4]=Kbso(l);
    }
}
__device__ __forceinline__ void build_ws_lut(int* s_lutAB, int tid, int nthr){
    for (int m = tid; m < 576; m += nthr){
        int l = (m<128)?0:(m<384)?1:(m<512)?2:3;
        int r = (l==0)?4:8;
        int rem = m - Kwso(l);
        int rr2 = r*r;
        int n = rem / rr2;
        int ij = rem - n*rr2;
        int i = ij / r, j = ij - i*r;
        int pb = Knro(l) + n*r;
        s_lutAB[m] = (pb+i) | ((pb+j)<<16);
    }
}
__device__ __forceinline__ void build_chunk_lut(int* s_ck, int tid){
    if (tid < 20){
        int c = tid, m, dd0=0, ext=0, ec=0;
        if (c < 13){ m = c; }
        else if (c == 13){ m=12; dd0=8; ext=1; ec=0; }
        else if (c == 14){ m=13; }
        else if (c == 15){ m=13; dd0=8; ext=1; ec=1; }
        else if (c == 16){ m=14; }
        else { m=14; dd0=8*(c-16); ext=1; ec=c-15; }
        s_ck[c] = m | (dd0<<8) | (ext<<16) | (ec<<20);
    }
}

// =====================================================================
// Pass 1: per-group (4 chunks) state sums + intra-group prefix
// =====================================================================
#define P1_FLOATS (2176 + 2816 + 928 + 1280)
#define P1_BYTES (P1_FLOATS*4 + (75+576+20)*4)
__global__ __launch_bounds__(512,2) void chunk_sum4_kernel(BasePtrs bp){
    extern __shared__ float sm[];
    float* s_k    = sm;
    float* s_v    = s_k + 16*KPAD;
    float* prjULT = s_v + 16*KPAD;
    float* prjVRT = prjULT + 1408;
    float* sUL    = prjVRT + 1408;
    float* sVR    = sUL + 464;
    float* extP   = sVR + 464;
    int*   s_nd   = (int*)(extP + 1280);
    int*   lutAB  = s_nd + 75;
    int*   s_ck   = lutAB + 576;

    const int tid = threadIdx.x;
    const int blk = blockIdx.x;
    const int b = blk / NGRP, grp = blk % NGRP;

    for (int i=tid;i<464;i+=NT){
        int l = (i<16)?0:(i<80)?1:(i<208)?2:3;
        int off = i - Kbso(l);
        sUL[i] = bp.p[l][off];
        sVR[i] = bp.p[4+l][off];
    }
    build_node_lut(s_nd, tid);
    build_ws_lut(lutAB, tid, NT);
    build_chunk_lut(s_ck, tid);
    __syncthreads();

    float sreg[2][4];

    for (int j=0;j<4;j++){
        const int c = grp*4 + j;
        const float* gk = g_k + ((size_t)b*TSEQ + c*CCH)*DH;
        const float* gv = g_v + ((size_t)b*TSEQ + c*CCH)*DH;
        if (tid < 512){
            int arr = tid>>8;
            int rem = tid & 255; int row = rem>>4, g = rem&15;
            const float* src = (arr==0?gk:gv) + row*64 + g*4;
            float* dst = (arr==0?s_k:s_v) + row*KPAD + g*4;
            *(float4*)dst = *(const float4*)src;
        }
        __syncthreads();

        if (tid < 320){
            int cd = s_ck[tid>>4]; int s = tid&15;
            int m = cd & 31, dd0 = (cd>>8)&63, isext=(cd>>16)&1, ec=(cd>>20)&7;
            int bs=s_nd[m*5], r=s_nd[m*5+1], pb=s_nd[m*5+2], topo=s_nd[m*5+3], bso=s_nd[m*5+4];
            const float* kt = s_k + s*KPAD + topo + dd0;
            const float* vb = s_v + s*KPAD + topo + bs + dd0;
            const float* Ub = sUL + bso + dd0*r;
            const float* Wb = sVR + bso + dd0*r;
            if (r == 4){
                float4 aU=make_float4(0,0,0,0), aV=aU;
#pragma unroll
                for (int d=0; d<4; d++){
                    float kd=kt[d], vd=vb[d];
                    float4 u=*(const float4*)(Ub+d*4), w=*(const float4*)(Wb+d*4);
                    fma4(aU,kd,u); fma4(aV,vd,w);
                }
                float au[4]={aU.x,aU.y,aU.z,aU.w}, avv[4]={aV.x,aV.y,aV.z,aV.w};
#pragma unroll
                for (int i=0;i<4;i++){
                    prjULT[(pb+i)*16+s]=au[i];
                    prjVRT[(pb+i)*16+s]=avv[i];
                }
            } else {
                float aU[8], aV[8];
#pragma unroll
                for (int i=0;i<8;i++){ aU[i]=0.f; aV[i]=0.f; }
#pragma unroll
                for (int d=0; d<8; d++){
                    float kd=kt[d], vd=vb[d];
                    float4 u0=*(const float4*)(Ub+d*8), u1=*(const float4*)(Ub+d*8+4);
                    float4 w0=*(const float4*)(Wb+d*8), w1=*(const float4*)(Wb+d*8+4);
                    aU[0]=fmaf(kd,u0.x,aU[0]); aU[1]=fmaf(kd,u0.y,aU[1]); aU[2]=fmaf(kd,u0.z,aU[2]); aU[3]=fmaf(kd,u0.w,aU[3]);
                    aU[4]=fmaf(kd,u1.x,aU[4]); aU[5]=fmaf(kd,u1.y,aU[5]); aU[6]=fmaf(kd,u1.z,aU[6]); aU[7]=fmaf(kd,u1.w,aU[7]);
                    aV[0]=fmaf(vd,w0.x,aV[0]); aV[1]=fmaf(vd,w0.y,aV[1]); aV[2]=fmaf(vd,w0.z,aV[2]); aV[3]=fmaf(vd,w0.w,aV[3]);
                    aV[4]=fmaf(vd,w1.x,aV[4]); aV[5]=fmaf(vd,w1.y,aV[5]); aV[6]=fmaf(vd,w1.z,aV[6]); aV[7]=fmaf(vd,w1.w,aV[7]);
                }
                if (!isext){
#pragma unroll
                    for (int i=0;i<8;i++){
                        prjULT[(pb+i)*16+s]=aU[i];
                        prjVRT[(pb+i)*16+s]=aV[i];
                    }
                } else {
#pragma unroll
                    for (int i=0;i<8;i++){
                        extP[((0*5+ec)*8+i)*16+s]=aU[i];
                        extP[((1*5+ec)*8+i)*16+s]=aV[i];
                    }
                }
            }
        }
        __syncthreads();
        if (tid < 256){
            int a=tid>>7, i=(tid>>4)&7, s=tid&15;
            float* base = prjULT + a*1408;
            base[(64+i)*16+s] += extP[((a*5+0)*8+i)*16+s];
            base[(72+i)*16+s] += extP[((a*5+1)*8+i)*16+s];
            base[(80+i)*16+s] += extP[((a*5+2)*8+i)*16+s] + extP[((a*5+3)*8+i)*16+s] + extP[((a*5+4)*8+i)*16+s];
        }
        __syncthreads();

#pragma unroll
        for (int o=0;o<2;o++){
            int e = tid + o*512;
            if (e < NST){
                float acc = 0.f;
                if (e < 256){
                    int n=e>>4, i=(e>>2)&3, j2=e&3;
                    int ki=4*n+i, vi=4*n+j2;
#pragma unroll
                    for (int s=0;s<CCH;s++) acc = fmaf(s_k[s*KPAD+ki], s_v[s*KPAD+vi], acc);
                } else if (e < 832){
                    int m = e-256;
                    int ab = lutAB[m]; int a = ab & 0xffff, b3 = ab >> 16;
                    const float4* pa = (const float4*)&prjULT[a*16];
                    const float4* pb4 = (const float4*)&prjVRT[b3*16];
#pragma unroll
                    for (int g=0;g<4;g++) acc += dot4v(pa[g], pb4[g]);
                } else {
                    int d = e-832;
#pragma unroll
                    for (int s=0;s<CCH;s++) acc += s_k[s*KPAD+d];
                }
                sreg[o][j] = acc;
            }
        }
        __syncthreads();
    }

#pragma unroll
    for (int o=0;o<2;o++){
        int e = tid + o*512;
        if (e < NST){
            float run = 0.f;
#pragma unroll
            for (int j=0;j<4;j++){
                g_prefix[(size_t)(blk*4+j)*NST + e] = run;
                run += sreg[o][j];
            }
            g_gtot[(size_t)blk*NST + e] = run;
        }
    }
}

// =====================================================================
// Pass 2: exclusive prefix over 32 group totals per batch
// =====================================================================
__global__ __launch_bounds__(128) void midscan_kernel(){
    const int b = blockIdx.y;
    const int e = blockIdx.x*128 + threadIdx.x;
    const float* gt = g_gtot + (size_t)b*NGRP*NST + e;
    float*       go = g_goff + (size_t)b*NGRP*NST + e;
    float run = 0.f;
    for (int g0=0; g0<NGRP; g0+=8){
        float v[8];
#pragma unroll
        for (int j=0;j<8;j++) v[j] = gt[(size_t)(g0+j)*NST];
#pragma unroll
        for (int j=0;j<8;j++){ go[(size_t)(g0+j)*NST] = run; run += v[j]; }
    }
}

// =====================================================================
// Pass 3: fully parallel intra-chunk attention, 2 chunks per block
// Asc/Bsc TRANSPOSED: [s][240] -> conflict-free STS/LDS
// =====================================================================
#define P3_FLOATS (3264 + 5632 + 1856 + 896 + 3840 + 3840 + 2560 + 256 + 16 + 1496 + 1496 + 1088)
#define P3_BYTES (P3_FLOATS*4 + (75 + 88*3 + 20)*4)
__global__ __launch_bounds__(512,2) void chunk_scan_kernel(BasePtrs bp){
    extern __shared__ float sm[];
    float* s_k    = sm;
    float* s_v    = s_k + 16*KPAD;
    float* s_q    = s_v + 16*KPAD;
    float* prjULT = s_q + 16*KPAD;
    float* prjVRT = prjULT + 1408;
    float* prjXT  = prjVRT + 1408;
    float* prjLT  = prjXT + 1408;
    float* sUL    = prjLT + 1408;
    float* sVR    = sUL + 464;
    float* sUR    = sVR + 464;
    float* sVL    = sUR + 464;
    float* s_leaf = sVL + 464;
    float* s_Ws   = s_leaf + 256;
    float* s_z    = s_Ws + 576;
    float* Asc    = s_z + 64;          // [16 s][240 col]
    float* Bsc    = Asc + 3840;        // [16 s][240 col]
    float* extP   = Bsc + 3840;
    float* Dsc    = extP + 2560;
    float* s_den  = Dsc + 256;
    float* TT     = s_den + 16;
    float* TBB    = TT + 1496;
    float* yl     = TBB + 1496;
    int*   s_nd   = (int*)(yl + 1088);
    int*   lutP   = s_nd + 75;
    int*   lutWT  = lutP + 88;
    int*   lutWB  = lutWT + 88;
    int*   s_ck   = lutWB + 88;

    const int tid = threadIdx.x;
    const int blk = blockIdx.x;
    const int b = blk / (NCH/2), cp = blk % (NCH/2);

    for (int i=tid;i<464;i+=NT){
        int l = (i<16)?0:(i<80)?1:(i<208)?2:3;
        int off = i - Kbso(l);
        sUL[i] = bp.p[l   ][off];
        sVR[i] = bp.p[4+l ][off];
        sUR[i] = bp.p[8+l ][off];
        sVL[i] = bp.p[12+l][off];
    }
    build_node_lut(s_nd, tid);
    build_chunk_lut(s_ck, tid);
    if (tid < 88){
        int i88 = tid;
        int l = (i88<32)?0:(i88<64)?1:(i88<80)?2:3;
        int r = (l==0)?4:8;
        int rem = i88 - Knro(l);
        int n = rem / r, i = rem - n*r;
        int pb = Knro(l) + n*r;
        int ng = Knoff(l) + n;
        lutP[i88]  = pb | (ng<<8) | (r<<16);
        lutWT[i88] = Kwso(l) + n*r*r + i*r;
        lutWB[i88] = Kwso(l) + n*r*r + i;
    }

    for (int cc=0; cc<2; cc++){
        const int c = cp*2 + cc;
        const int ci = b*NCH + c;
        const float* gk = g_k + ((size_t)b*TSEQ + c*CCH)*DH;
        const float* gv = g_v + ((size_t)b*TSEQ + c*CCH)*DH;
        const float* gq = g_q + ((size_t)b*TSEQ + c*CCH)*DH;
        __nv_bfloat16* g_oh = g_ah + ((size_t)b*TSEQ + c*CCH)*DH;
        __nv_bfloat16* g_ol = g_al + ((size_t)b*TSEQ + c*CCH)*DH;

        for (int i=tid;i<768;i+=NT){
            int arr = i>>8;
            int rem = i & 255; int row = rem>>4, g = rem&15;
            const float* src = (arr==0?gk:(arr==1?gv:gq)) + row*64 + g*4;
            float* dst = (arr==0?s_k:(arr==1?s_v:s_q)) + row*KPAD + g*4;
            *(float4*)dst = *(const float4*)src;
        }
        {
            const float* gp = g_prefix + (size_t)ci*NST;
            const float* gof = g_goff + ((size_t)(b*NGRP) + (c>>2))*NST;
            for (int e=tid;e<NST;e+=NT){
                float vle = gp[e] + gof[e];
                if (e<256) s_leaf[e]=vle;
                else if (e<832) s_Ws[e-256]=vle;
                else s_z[e-832]=vle;
            }
        }
        __syncthreads();

        // phase P: projections + D scores
        if (tid < 320){
            int cd = s_ck[tid>>4]; int s = tid&15;
            int m = cd & 31, dd0 = (cd>>8)&63, isext=(cd>>16)&1, ec=(cd>>20)&7;
            int bs=s_nd[m*5], r=s_nd[m*5+1], pb=s_nd[m*5+2], topo=s_nd[m*5+3], bso=s_nd[m*5+4];
            const float* kt = s_k + s*KPAD + topo + dd0;
            const float* vb = s_v + s*KPAD + topo + bs + dd0;
            const float* qt = s_q + s*KPAD + topo + dd0;
            const float* qb = s_q + s*KPAD + topo + bs + dd0;
            const float* Ub = sUL + bso + dd0*r;
            const float* Wb = sVR + bso + dd0*r;
            const float* Xb = sVL + bso + dd0*r;
            if (r == 4){
                float4 aU=make_float4(0,0,0,0), aV=aU, aX=aU, aL=aU;
#pragma unroll
                for (int d=0; d<4; d++){
                    float kd=kt[d], vd=vb[d], qtd=qt[d], qbd=qb[d];
                    float4 u=*(const float4*)(Ub+d*4), w=*(const float4*)(Wb+d*4), x=*(const float4*)(Xb+d*4);
                    fma4(aU,kd,u); fma4(aV,vd,w); fma4(aX,qbd,w); fma4(aL,qtd,x);
                }
                float t0[4]={aU.x,aU.y,aU.z,aU.w}, t1[4]={aV.x,aV.y,aV.z,aV.w};
                float t2[4]={aX.x,aX.y,aX.z,aX.w}, t3[4]={aL.x,aL.y,aL.z,aL.w};
#pragma unroll
                for (int i=0;i<4;i++){
                    prjULT[(pb+i)*16+s]=t0[i];
                    prjVRT[(pb+i)*16+s]=t1[i];
                    prjXT [(pb+i)*16+s]=t2[i];
                    prjLT [(pb+i)*16+s]=t3[i];
                }
            } else {
                {
                    float aU[8], aV[8];
#pragma unroll
                    for (int i=0;i<8;i++){ aU[i]=0.f; aV[i]=0.f; }
#pragma unroll
                    for (int d=0; d<8; d++){
                        float kd=kt[d], vd=vb[d];
                        float4 u0=*(const float4*)(Ub+d*8), u1=*(const float4*)(Ub+d*8+4);
                        float4 w0=*(const float4*)(Wb+d*8), w1=*(const float4*)(Wb+d*8+4);
                        aU[0]=fmaf(kd,u0.x,aU[0]); aU[1]=fmaf(kd,u0.y,aU[1]); aU[2]=fmaf(kd,u0.z,aU[2]); aU[3]=fmaf(kd,u0.w,aU[3]);
                        aU[4]=fmaf(kd,u1.x,aU[4]); aU[5]=fmaf(kd,u1.y,aU[5]); aU[6]=fmaf(kd,u1.z,aU[6]); aU[7]=fmaf(kd,u1.w,aU[7]);
                        aV[0]=fmaf(vd,w0.x,aV[0]); aV[1]=fmaf(vd,w0.y,aV[1]); aV[2]=fmaf(vd,w0.z,aV[2]); aV[3]=fmaf(vd,w0.w,aV[3]);
                        aV[4]=fmaf(vd,w1.x,aV[4]); aV[5]=fmaf(vd,w1.y,aV[5]); aV[6]=fmaf(vd,w1.z,aV[6]); aV[7]=fmaf(vd,w1.w,aV[7]);
                    }
                    if (!isext){
#pragma unroll
                        for (int i=0;i<8;i++){ prjULT[(pb+i)*16+s]=aU[i]; prjVRT[(pb+i)*16+s]=aV[i]; }
                    } else {
#pragma unroll
                        for (int i=0;i<8;i++){
                            extP[((0*5+ec)*8+i)*16+s]=aU[i];
                            extP[((1*5+ec)*8+i)*16+s]=aV[i];
                        }
                    }
                }
                {
                    float aX[8], aL[8];
#pragma unroll
                    for (int i=0;i<8;i++){ aX[i]=0.f; aL[i]=0.f; }
#pragma unroll
                    for (int d=0; d<8; d++){
                        float qbd=qb[d], qtd=qt[d];
                        float4 w0=*(const float4*)(Wb+d*8), w1=*(const float4*)(Wb+d*8+4);
                        float4 x0=*(const float4*)(Xb+d*8), x1=*(const float4*)(Xb+d*8+4);
                        aX[0]=fmaf(qbd,w0.x,aX[0]); aX[1]=fmaf(qbd,w0.y,aX[1]); aX[2]=fmaf(qbd,w0.z,aX[2]); aX[3]=fmaf(qbd,w0.w,aX[3]);
                        aX[4]=fmaf(qbd,w1.x,aX[4]); aX[5]=fmaf(qbd,w1.y,aX[5]); aX[6]=fmaf(qbd,w1.z,aX[6]); aX[7]=fmaf(qbd,w1.w,aX[7]);
                        aL[0]=fmaf(qtd,x0.x,aL[0]); aL[1]=fmaf(qtd,x0.y,aL[1]); aL[2]=fmaf(qtd,x0.z,aL[2]); aL[3]=fmaf(qtd,x0.w,aL[3]);
                        aL[4]=fmaf(qtd,x1.x,aL[4]); aL[5]=fmaf(qtd,x1.y,aL[5]); aL[6]=fmaf(qtd,x1.z,aL[6]); aL[7]=fmaf(qtd,x1.w,aL[7]);
                    }
                    if (!isext){
#pragma unroll
                        for (int i=0;i<8;i++){ prjXT[(pb+i)*16+s]=aX[i]; prjLT[(pb+i)*16+s]=aL[i]; }
                    } else {
#pragma unroll
                        for (int i=0;i<8;i++){
                            extP[((2*5+ec)*8+i)*16+s]=aX[i];
                            extP[((3*5+ec)*8+i)*16+s]=aL[i];
                        }
                    }
                }
            }
        } else {
            int j = tid - 320;
#pragma unroll
            for (int rep=0; rep<2; rep++){
                if (j < 256){
                    int t = j>>4, s = j&15;
                    float acc = 0.f;
#pragma unroll
                    for (int g=0;g<16;g++)
                        acc += dot4v(*(const float4*)&s_k[s*KPAD+4*g], *(const float4*)&s_q[t*KPAD+4*g]);
                    Dsc[j] = acc;
                }
                j += 192;
            }
        }
        __syncthreads();
        {
            int a=tid>>7, i=(tid>>4)&7, s=tid&15;
            float* base = prjULT + a*1408;
            base[(64+i)*16+s] += extP[((a*5+0)*8+i)*16+s];
            base[(72+i)*16+s] += extP[((a*5+1)*8+i)*16+s];
            base[(80+i)*16+s] += extP[((a*5+2)*8+i)*16+s] + extP[((a*5+3)*8+i)*16+s] + extP[((a*5+4)*8+i)*16+s];
        }
        __syncthreads();

        // scores (transposed store) + yl + den
        for (int j=tid; j<752; j+=NT){
            if (j < 240){
                int ng = j>>4, t = j&15;
                int pb = s_nd[ng*5+2];
                float4 a0=make_float4(0,0,0,0), a1=a0, a2=a0, a3=a0;
                if (ng < 8){
#pragma unroll
                    for (int i=0;i<4;i++){
                        float w = prjXT[(pb+i)*16+t];
                        const float4* vr = (const float4*)&prjVRT[(pb+i)*16];
                        fma4(a0,w,vr[0]); fma4(a1,w,vr[1]); fma4(a2,w,vr[2]); fma4(a3,w,vr[3]);
                    }
                } else {
#pragma unroll
                    for (int i=0;i<8;i++){
                        float w = prjXT[(pb+i)*16+t];
                        const float4* vr = (const float4*)&prjVRT[(pb+i)*16];
                        fma4(a0,w,vr[0]); fma4(a1,w,vr[1]); fma4(a2,w,vr[2]); fma4(a3,w,vr[3]);
                    }
                }
                int col = ng*16 + t;
                Asc[ 0*240+col]=a0.x;            Asc[ 1*240+col]=(1<=t)?a0.y:0.f;
                Asc[ 2*240+col]=(2<=t)?a0.z:0.f; Asc[ 3*240+col]=(3<=t)?a0.w:0.f;
                Asc[ 4*240+col]=(4<=t)?a1.x:0.f; Asc[ 5*240+col]=(5<=t)?a1.y:0.f;
                Asc[ 6*240+col]=(6<=t)?a1.z:0.f; Asc[ 7*240+col]=(7<=t)?a1.w:0.f;
                Asc[ 8*240+col]=(8<=t)?a2.x:0.f; Asc[ 9*240+col]=(9<=t)?a2.y:0.f;
                Asc[10*240+col]=(10<=t)?a2.z:0.f; Asc[11*240+col]=(11<=t)?a2.w:0.f;
                Asc[12*240+col]=(12<=t)?a3.x:0.f; Asc[13*240+col]=(13<=t)?a3.y:0.f;
                Asc[14*240+col]=(14<=t)?a3.z:0.f; Asc[15*240+col]=(15<=t)?a3.w:0.f;
            } else if (j < 480){
                int jj = j-240;
                int ng = jj>>4, t = jj&15;
                int pb = s_nd[ng*5+2];
                float4 a0=make_float4(0,0,0,0), a1=a0, a2=a0, a3=a0;
                if (ng < 8){
#pragma unroll
                    for (int i=0;i<4;i++){
                        float w = prjLT[(pb+i)*16+t];
                        const float4* ul = (const float4*)&prjULT[(pb+i)*16];
                        fma4(a0,w,ul[0]); fma4(a1,w,ul[1]); fma4(a2,w,ul[2]); fma4(a3,w,ul[3]);
                    }
                } else {
#pragma unroll
                    for (int i=0;i<8;i++){
                        float w = prjLT[(pb+i)*16+t];
                        const float4* ul = (const float4*)&prjULT[(pb+i)*16];
                        fma4(a0,w,ul[0]); fma4(a1,w,ul[1]); fma4(a2,w,ul[2]); fma4(a3,w,ul[3]);
                    }
                }
                int col = ng*16 + t;
                Bsc[ 0*240+col]=a0.x;            Bsc[ 1*240+col]=(1<=t)?a0.y:0.f;
                Bsc[ 2*240+col]=(2<=t)?a0.z:0.f; Bsc[ 3*240+col]=(3<=t)?a0.w:0.f;
                Bsc[ 4*240+col]=(4<=t)?a1.x:0.f; Bsc[ 5*240+col]=(5<=t)?a1.y:0.f;
                Bsc[ 6*240+col]=(6<=t)?a1.z:0.f; Bsc[ 7*240+col]=(7<=t)?a1.w:0.f;
                Bsc[ 8*240+col]=(8<=t)?a2.x:0.f; Bsc[ 9*240+col]=(9<=t)?a2.y:0.f;
                Bsc[10*240+col]=(10<=t)?a2.z:0.f; Bsc[11*240+col]=(11<=t)?a2.w:0.f;
                Bsc[12*240+col]=(12<=t)?a3.x:0.f; Bsc[13*240+col]=(13<=t)?a3.y:0.f;
                Bsc[14*240+col]=(14<=t)?a3.z:0.f; Bsc[15*240+col]=(15<=t)?a3.w:0.f;
            } else if (j < 736){
                int jj = j-480;
                int n = jj>>4, t = jj&15;
                float4 qv = *(const float4*)&s_q[t*KPAD+4*n];
                float cvals[16];
#pragma unroll
                for (int s=0;s<16;s++){
                    float val = dot4v(*(const float4*)&s_v[s*KPAD+4*n], qv);
                    cvals[s] = (s<=t)? val : 0.f;
                }
                float acc0 = dot4v(*(const float4*)&s_leaf[(4*n+0)*4], qv);
                float acc1 = dot4v(*(const float4*)&s_leaf[(4*n+1)*4], qv);
                float acc2 = dot4v(*(const float4*)&s_leaf[(4*n+2)*4], qv);
                float acc3 = dot4v(*(const float4*)&s_leaf[(4*n+3)*4], qv);
#pragma unroll
                for (int s=0;s<16;s++){
                    float4 kv = *(const float4*)&s_k[s*KPAD+4*n];
                    float cs = cvals[s];
                    acc0 = fmaf(kv.x, cs, acc0);
                    acc1 = fmaf(kv.y, cs, acc1);
                    acc2 = fmaf(kv.z, cs, acc2);
                    acc3 = fmaf(kv.w, cs, acc3);
                }
                yl[(4*n+0)*17+t] = acc0;
                yl[(4*n+1)*17+t] = acc1;
                yl[(4*n+2)*17+t] = acc2;
                yl[(4*n+3)*17+t] = acc3;
            } else {
                int t = j-736;
                float acc = 0.f;
#pragma unroll
                for (int g=0;g<16;g++)
                    acc += dot4v(*(const float4*)&s_z[4*g], *(const float4*)&s_q[t*KPAD+4*g]);
                for (int s=0;s<=t;s++) acc += Dsc[t*16+s];
                s_den[t] = fmaxf(acc, 1e-6f);
            }
        }
        __syncthreads();

        // TT / TBB (transposed score reads)
        for (int j=tid; j<2816; j+=NT){
            if (j < 1408){
                int i88 = j>>4, t = j&15;
                int info = lutP[i88]; int pb = info&255, ng=(info>>8)&255;
                float acc = 0.f;
                int wr = lutWT[i88];
                if (i88 < 32){
#pragma unroll
                    for (int u=0;u<4;u++) acc = fmaf(s_Ws[wr+u], prjXT[(pb+u)*16+t], acc);
                } else {
#pragma unroll
                    for (int u=0;u<8;u++) acc = fmaf(s_Ws[wr+u], prjXT[(pb+u)*16+t], acc);
                }
                const float4* uu4 = (const float4*)&prjULT[i88*16];
                float4 u0=uu4[0], u1=uu4[1], u2=uu4[2], u3=uu4[3];
                const int col = ng*16 + t;
                acc = fmaf(u0.x, Asc[ 0*240+col], acc);
                acc = fmaf(u0.y, Asc[ 1*240+col], acc);
                acc = fmaf(u0.z, Asc[ 2*240+col], acc);
                acc = fmaf(u0.w, Asc[ 3*240+col], acc);
                acc = fmaf(u1.x, Asc[ 4*240+col], acc);
                acc = fmaf(u1.y, Asc[ 5*240+col], acc);
                acc = fmaf(u1.z, Asc[ 6*240+col], acc);
                acc = fmaf(u1.w, Asc[ 7*240+col], acc);
                acc = fmaf(u2.x, Asc[ 8*240+col], acc);
                acc = fmaf(u2.y, Asc[ 9*240+col], acc);
                acc = fmaf(u2.z, Asc[10*240+col], acc);
                acc = fmaf(u2.w, Asc[11*240+col], acc);
                acc = fmaf(u3.x, Asc[12*240+col], acc);
                acc = fmaf(u3.y, Asc[13*240+col], acc);
                acc = fmaf(u3.z, Asc[14*240+col], acc);
                acc = fmaf(u3.w, Asc[15*240+col], acc);
                TT[i88*17+t] = acc;
            } else {
                int jj = j-1408;
                int i88 = jj>>4, t = jj&15;
                int info = lutP[i88]; int pb = info&255, ng=(info>>8)&255;
                float acc = 0.f;
                int wc = lutWB[i88];
                if (i88 < 32){
#pragma unroll
                    for (int u=0;u<4;u++) acc = fmaf(s_Ws[wc+u*4], prjLT[(pb+u)*16+t], acc);
                } else {
#pragma unroll
                    for (int u=0;u<8;u++) acc = fmaf(s_Ws[wc+u*8], prjLT[(pb+u)*16+t], acc);
                }
                const float4* vv4 = (const float4*)&prjVRT[i88*16];
                float4 v0=vv4[0], v1=vv4[1], v2=vv4[2], v3=vv4[3];
                const int col = ng*16 + t;
                acc = fmaf(v0.x, Bsc[ 0*240+col], acc);
                acc = fmaf(v0.y, Bsc[ 1*240+col], acc);
                acc = fmaf(v0.z, Bsc[ 2*240+col], acc);
                acc = fmaf(v0.w, Bsc[ 3*240+col], acc);
                acc = fmaf(v1.x, Bsc[ 4*240+col], acc);
                acc = fmaf(v1.y, Bsc[ 5*240+col], acc);
                acc = fmaf(v1.z, Bsc[ 6*240+col], acc);
                acc = fmaf(v1.w, Bsc[ 7*240+col], acc);
                acc = fmaf(v2.x, Bsc[ 8*240+col], acc);
                acc = fmaf(v2.y, Bsc[ 9*240+col], acc);
                acc = fmaf(v2.z, Bsc[10*240+col], acc);
                acc = fmaf(v2.w, Bsc[11*240+col], acc);
                acc = fmaf(v3.x, Bsc[12*240+col], acc);
                acc = fmaf(v3.y, Bsc[13*240+col], acc);
                acc = fmaf(v3.z, Bsc[14*240+col], acc);
                acc = fmaf(v3.w, Bsc[15*240+col], acc);
                TBB[i88*17+t] = acc;
            }
        }
        __syncthreads();

        // final assembly
        for (int j=tid; j<1024; j+=NT){
            int d = j&63, t = j>>6;
            float y = yl[d*17+t];
#pragma unroll
            for (int l=0;l<4;l++){
                const int bs = 4<<l;
                const int r  = (l==0)?4:8;
                const int n = d >> (3+l);
                const int loc = d & (2*bs - 1);
                const int pb = Knro(l) + n*r;
                const int bso = Kbso(l);
                if (loc < bs){
                    const float* u = sUL + bso + loc*r;
#pragma unroll
                    for (int i=0;i<8;i++){
                        if (i < r) y = fmaf(u[i], TT[(pb+i)*17+t], y);
                    }
                } else {
                    const float* u = sUR + bso + (loc-bs)*r;
#pragma unroll
                    for (int i=0;i<8;i++){
                        if (i < r) y = fmaf(u[i], TBB[(pb+i)*17+t], y);
                    }
                }
            }
            float o = y / s_den[t];
            __nv_bfloat16 h = __float2bfloat16(o);
            g_oh[(size_t)t*DH + d] = h;
            g_ol[(size_t)t*DH + d] = __float2bfloat16(o - __bfloat162float(h));
        }
    }
}

// ---------------- output GEMM via mma.sync bf16x3 ----------------
#define WA 72
#define WB 136
#define WO_BYTES ((128*WA*2 + 64*WB*2)*2)
__global__ __launch_bounds__(256) void wo_mma_kernel(float* __restrict__ out){
    extern __shared__ __nv_bfloat16 ws[];
    __nv_bfloat16* sAh = ws;
    __nv_bfloat16* sAl = sAh + 128*WA;
    __nv_bfloat16* sBh = sAl + 128*WA;
    __nv_bfloat16* sBl = sBh + 64*WB;

    const int tid = threadIdx.x;
    const int wid = tid >> 5, lane = tid & 31;
    const int wy = wid & 3, wx = wid >> 2;
    const int rb = blockIdx.x * 128, cb = blockIdx.y * 128;

#pragma unroll
    for (int i=0;i<4;i++){
        int idx = tid + i*256;
        int row = idx >> 3, c8 = idx & 7;
        cp_async16(sAh + row*WA + c8*8, g_ah + (size_t)(rb+row)*DH + c8*8);
        cp_async16(sAl + row*WA + c8*8, g_al + (size_t)(rb+row)*DH + c8*8);
    }
#pragma unroll
    for (int i=0;i<4;i++){
        int idx = tid + i*256;
        int k = idx >> 4, c16 = idx & 15;
        cp_async16(sBh + k*WB + c16*8, g_woh + (size_t)k*DM + cb + c16*8);
        cp_async16(sBl + k*WB + c16*8, g_wol + (size_t)k*DM + cb + c16*8);
    }
    asm volatile("cp.async.commit_group;\n");
    asm volatile("cp.async.wait_group 0;\n");
    __syncthreads();

    float acc[2][8][4];
#pragma unroll
    for (int m=0;m<2;m++)
#pragma unroll
        for (int n=0;n<8;n++){ acc[m][n][0]=acc[m][n][1]=acc[m][n][2]=acc[m][n][3]=0.f; }

#pragma unroll
    for (int k0=0;k0<64;k0+=16){
        unsigned ah[2][4], al[2][4];
#pragma unroll
        for (int mt=0;mt<2;mt++){
            const __nv_bfloat16* ap = sAh + (wy*32 + mt*16 + (lane&15))*WA + k0 + (lane>>4)*8;
            ldmx4(ah[mt][0],ah[mt][1],ah[mt][2],ah[mt][3], ap);
            const __nv_bfloat16* ap2 = sAl + (wy*32 + mt*16 + (lane&15))*WA + k0 + (lane>>4)*8;
            ldmx4(al[mt][0],al[mt][1],al[mt][2],al[mt][3], ap2);
        }
#pragma unroll
        for (int nt=0;nt<4;nt++){
            unsigned bh0,bh1,bh2,bh3, bl0,bl1,bl2,bl3;
            const __nv_bfloat16* bp = sBh + (k0 + (lane&15))*WB + wx*64 + nt*16 + (lane>>4)*8;
            ldmx4t(bh0,bh1,bh2,bh3, bp);
            const __nv_bfloat16* bp2 = sBl + (k0 + (lane&15))*WB + wx*64 + nt*16 + (lane>>4)*8;
            ldmx4t(bl0,bl1,bl2,bl3, bp2);
#pragma unroll
            for (int mt=0;mt<2;mt++){
                mma16816(acc[mt][2*nt],   ah[mt][0],ah[mt][1],ah[mt][2],ah[mt][3], bh0,bh1);
                mma16816(acc[mt][2*nt],   ah[mt][0],ah[mt][1],ah[mt][2],ah[mt][3], bl0,bl1);
                mma16816(acc[mt][2*nt],   al[mt][0],al[mt][1],al[mt][2],al[mt][3], bh0,bh1);
                mma16816(acc[mt][2*nt+1], ah[mt][0],ah[mt][1],ah[mt][2],ah[mt][3], bh2,bh3);
                mma16816(acc[mt][2*nt+1], ah[mt][0],ah[mt][1],ah[mt][2],ah[mt][3], bl2,bl3);
                mma16816(acc[mt][2*nt+1], al[mt][0],al[mt][1],al[mt][2],al[mt][3], bh2,bh3);
            }
        }
    }

#pragma unroll
    for (int mt=0;mt<2;mt++){
        int row = rb + wy*32 + mt*16 + (lane>>2);
#pragma unroll
        for (int nt=0;nt<8;nt++){
            int col = cb + wx*64 + nt*8 + (lane&3)*2;
            *(float2*)(out + (size_t)row*DM + col)     = make_float2(acc[mt][nt][0], acc[mt][nt][1]);
            *(float2*)(out + (size_t)(row+8)*DM + col) = make_float2(acc[mt][nt][2], acc[mt][nt][3]);
        }
    }
}

extern "C" void kernel_launch(void* const* d_in, const int* in_sizes, int n_in,
                              void* d_out, int out_size){
    (void)in_sizes; (void)n_in; (void)out_size;
    const float* x  = (const float*)d_in[0];
    const float* Wq = (const float*)d_in[1];
    const float* Wk = (const float*)d_in[2];
    const float* Wv = (const float*)d_in[3];
    const float* Wo = (const float*)d_in[4];
    BasePtrs bp;
    for(int i=0;i<16;i++) bp.p[i] = (const float*)d_in[5+i];
    float* out = (float*)d_out;

    cudaFuncSetAttribute(chunk_sum4_kernel, cudaFuncAttributeMaxDynamicSharedMemorySize, P1_BYTES);
    cudaFuncSetAttribute(chunk_scan_kernel, cudaFuncAttributeMaxDynamicSharedMemorySize, P3_BYTES);
    cudaFuncSetAttribute(wo_mma_kernel,     cudaFuncAttributeMaxDynamicSharedMemorySize, WO_BYTES);

    wprep_kernel<<<(DM*NW + DH*DM)/256, 256>>>(Wq, Wk, Wv, Wo);
    qkv_mma_kernel<<<NTOK/64, 256>>>(x);
    chunk_sum4_kernel<<<BB*NGRP, NT, P1_BYTES>>>(bp);
    midscan_kernel<<<dim3(NST/128, BB), 128>>>();
    chunk_scan_kernel<<<BB*NCH/2, NT, P3_BYTES>>>(bp);
    wo_mma_kernel<<<dim3(NTOK/128, DM/128), 256, WO_BYTES>>>(out);
}

// round 10
// speedup vs baseline: 66.6520x; 1.0069x over previous
#include <cuda_runtime.h>
#include <cuda_bf16.h>
#include <math.h>

#define TSEQ 2048
#define BB 8
#define DH 64
#define DM 1024
#define NTOK (BB*TSEQ)
#define CCH 16
#define NCH (TSEQ/CCH)   /* 128 */
#define NST 896
#define KPAD 68
#define NT 512
#define NW 192
#define NGRP 32
#define PSTR 97          /* transposed prj row stride in chunk_sum */

// scratch (device globals -- no allocation allowed)
__device__ float g_q[NTOK*DH];
__device__ float g_k[NTOK*DH];
__device__ float g_v[NTOK*DH];
__device__ float g_prefix[BB*NCH*NST];
__device__ float g_gtot[BB*NGRP*NST];
__device__ float g_goff[BB*NGRP*NST];
__device__ __nv_bfloat16 g_wh[DM*NW];
__device__ __nv_bfloat16 g_wl[DM*NW];
__device__ __nv_bfloat16 g_ah[NTOK*DH];
__device__ __nv_bfloat16 g_al[NTOK*DH];
__device__ __nv_bfloat16 g_woh[DH*DM];
__device__ __nv_bfloat16 g_wol[DH*DM];

struct BasePtrs { const float* p[16]; };

// ---------------- helpers ----------------
__device__ __forceinline__ void cp_async16(void* sptr, const void* gptr){
    unsigned s = (unsigned)__cvta_generic_to_shared(sptr);
    asm volatile("cp.async.ca.shared.global [%0], [%1], 16;" :: "r"(s), "l"(gptr));
}
__device__ __forceinline__ float dot4v(float4 a, float4 b){
    return fmaf(a.x,b.x, fmaf(a.y,b.y, fmaf(a.z,b.z, a.w*b.w)));
}
__device__ __forceinline__ void fma4(float4 &acc, float s, float4 v){
    acc.x = fmaf(s, v.x, acc.x); acc.y = fmaf(s, v.y, acc.y);
    acc.z = fmaf(s, v.z, acc.z); acc.w = fmaf(s, v.w, acc.w);
}
__device__ __forceinline__ unsigned smem_u32(const void* p){
    return (unsigned)__cvta_generic_to_shared(p);
}
__device__ __forceinline__ void ldmx4(unsigned &r0, unsigned &r1, unsigned &r2, unsigned &r3, const void* p){
    asm volatile("ldmatrix.sync.aligned.m8n8.x4.shared.b16 {%0,%1,%2,%3}, [%4];"
        : "=r"(r0),"=r"(r1),"=r"(r2),"=r"(r3) : "r"(smem_u32(p)));
}
__device__ __forceinline__ void ldmx4t(unsigned &r0, unsigned &r1, unsigned &r2, unsigned &r3, const void* p){
    asm volatile("ldmatrix.sync.aligned.m8n8.x4.trans.shared.b16 {%0,%1,%2,%3}, [%4];"
        : "=r"(r0),"=r"(r1),"=r"(r2),"=r"(r3) : "r"(smem_u32(p)));
}
__device__ __forceinline__ void mma16816(float* c, unsigned a0,unsigned a1,unsigned a2,unsigned a3,
                                         unsigned b0, unsigned b1){
    asm volatile("mma.sync.aligned.m16n8k16.row.col.f32.bf16.bf16.f32 "
        "{%0,%1,%2,%3}, {%4,%5,%6,%7}, {%8,%9}, {%0,%1,%2,%3};"
        : "+f"(c[0]),"+f"(c[1]),"+f"(c[2]),"+f"(c[3])
        : "r"(a0),"r"(a1),"r"(a2),"r"(a3),"r"(b0),"r"(b1));
}

__device__ __forceinline__ int Knro(int l){ return (l==0)?0:(l==1)?32:(l==2)?64:80; }
__device__ __forceinline__ int Kwso(int l){ return (l==0)?0:(l==1)?128:(l==2)?384:512; }
__device__ __forceinline__ int Kbso(int l){ return (l==0)?0:(l==1)?16:(l==2)?80:208; }
__device__ __forceinline__ int Knoff(int l){ return (l==0)?0:(l==1)?8:(l==2)?12:14; }

// ---------------- weight split prep ----------------
__global__ __launch_bounds__(256) void wprep_kernel(const float* __restrict__ Wq,
                                                    const float* __restrict__ Wk,
                                                    const float* __restrict__ Wv,
                                                    const float* __restrict__ Wo){
    int idx = blockIdx.x*256 + threadIdx.x;
    if (idx < DM*NW){
        int k = idx / NW, n = idx - k*NW;
        const float* W = (n<64)?Wq:(n<128?Wk:Wv);
        float w = W[(size_t)k*DH + (n&63)];
        __nv_bfloat16 hi = __float2bfloat16(w);
        g_wh[idx] = hi;
        g_wl[idx] = __float2bfloat16(w - __bfloat162float(hi));
    } else {
        int j = idx - DM*NW;
        float w = Wo[j];
        __nv_bfloat16 hi = __float2bfloat16(w);
        g_woh[j] = hi;
        g_wol[j] = __float2bfloat16(w - __bfloat162float(hi));
    }
}

// ---------------- QKV via mma.sync bf16x3 (single-sync pipeline) ----------------
#define ASTR 24
#define BSTR 200
__global__ __launch_bounds__(256) void qkv_mma_kernel(const float* __restrict__ x){
    __shared__ __nv_bfloat16 sAh[2][64*ASTR];
    __shared__ __nv_bfloat16 sAl[2][64*ASTR];
    __shared__ __nv_bfloat16 sBh[2][16*BSTR];
    __shared__ __nv_bfloat16 sBl[2][16*BSTR];

    const int tid = threadIdx.x;
    const int wid = tid >> 5, lane = tid & 31;
    const int wy = wid & 3, wx = wid >> 2;
    const int rb = blockIdx.x * 64;
    const int arow = tid >> 2, akg = tid & 3;

    float acc[12][4];
#pragma unroll
    for (int i=0;i<12;i++){ acc[i][0]=acc[i][1]=acc[i][2]=acc[i][3]=0.f; }

    auto loadB = [&](int k0, int buf){
#pragma unroll
        for (int i=0;i<3;i++){
            int idx = tid + i*256;
            int m2 = (idx >= 384);
            int id2 = idx - m2*384;
            int r = id2 / 24, c8 = id2 - r*24;
            const __nv_bfloat16* src = (m2 ? g_wl : g_wh) + (size_t)(k0+r)*NW + c8*8;
            __nv_bfloat16* dst = (m2 ? sBl[buf] : sBh[buf]) + r*BSTR + c8*8;
            cp_async16(dst, src);
        }
    };
    auto storeA = [&](float4 v, int buf){
        __nv_bfloat16 h0=__float2bfloat16(v.x), h1=__float2bfloat16(v.y),
                      h2=__float2bfloat16(v.z), h3=__float2bfloat16(v.w);
        float l0 = v.x-__bfloat162float(h0), l1 = v.y-__bfloat162float(h1),
              l2 = v.z-__bfloat162float(h2), l3 = v.w-__bfloat162float(h3);
        __nv_bfloat162 hh0 = __halves2bfloat162(h0,h1), hh1 = __halves2bfloat162(h2,h3);
        __nv_bfloat162 ll0 = __floats2bfloat162_rn(l0,l1), ll1 = __floats2bfloat162_rn(l2,l3);
        uint2 hu = make_uint2(*(unsigned*)&hh0, *(unsigned*)&hh1);
        uint2 lu = make_uint2(*(unsigned*)&ll0, *(unsigned*)&ll1);
        *(uint2*)&sAh[buf][arow*ASTR + akg*4] = hu;
        *(uint2*)&sAl[buf][arow*ASTR + akg*4] = lu;
    };

    const float* xrow = x + (size_t)(rb+arow)*DM + akg*4;
    float4 av = *(const float4*)xrow;
    loadB(0, 0);
    asm volatile("cp.async.commit_group;\n");
    storeA(av, 0);
    asm volatile("cp.async.wait_group 0;\n");
    __syncthreads();
    av = *(const float4*)(xrow + 16);   // prefetch stage 1

    const int a_off = (wy*16 + (lane&15))*ASTR + (lane>>4)*8;
    const int b_off = (lane&15)*BSTR + wx*96 + (lane>>4)*8;

    for(int kt=0; kt<64; kt++){
        const int buf = kt & 1;
        if (kt < 63){
            loadB((kt+1)*16, buf^1);
            asm volatile("cp.async.commit_group;\n");
            storeA(av, buf^1);               // av = stage kt+1 (prefetched)
            if (kt < 62)
                av = *(const float4*)(xrow + (kt+2)*16);   // prefetch stage kt+2
        }
        unsigned ah0,ah1,ah2,ah3, al0,al1,al2,al3;
        ldmx4(ah0,ah1,ah2,ah3, sAh[buf] + a_off);
        ldmx4(al0,al1,al2,al3, sAl[buf] + a_off);
#pragma unroll
        for(int nb=0; nb<6; nb++){
            unsigned bh0,bh1,bh2,bh3, bl0,bl1,bl2,bl3;
            ldmx4t(bh0,bh1,bh2,bh3, sBh[buf] + b_off + nb*16);
            ldmx4t(bl0,bl1,bl2,bl3, sBl[buf] + b_off + nb*16);
            mma16816(acc[2*nb],   ah0,ah1,ah2,ah3, bh0,bh1);
            mma16816(acc[2*nb],   ah0,ah1,ah2,ah3, bl0,bl1);
            mma16816(acc[2*nb],   al0,al1,al2,al3, bh0,bh1);
            mma16816(acc[2*nb+1], ah0,ah1,ah2,ah3, bh2,bh3);
            mma16816(acc[2*nb+1], ah0,ah1,ah2,ah3, bl2,bl3);
            mma16816(acc[2*nb+1], al0,al1,al2,al3, bh2,bh3);
        }
        if (kt < 63){
            asm volatile("cp.async.wait_group 0;\n");
        }
        __syncthreads();
    }

    const int row0 = rb + wy*16 + (lane>>2);
#pragma unroll
    for (int t=0; t<12; t++){
        int col = wx*96 + t*8 + (lane&3)*2;
        bool act = (col < 128);
        float* base = (col < 64) ? g_q : (col < 128 ? g_k : g_v);
        int cc = col & 63;
        float v0 = acc[t][0], v1 = acc[t][1], v2 = acc[t][2], v3 = acc[t][3];
        if (act){
            v0 = (v0>0.f)? v0+1.f : expf(v0);
            v1 = (v1>0.f)? v1+1.f : expf(v1);
            v2 = (v2>0.f)? v2+1.f : expf(v2);
            v3 = (v3>0.f)? v3+1.f : expf(v3);
        }
        base[(size_t)row0*DH + cc]       = v0;
        base[(size_t)row0*DH + cc + 1]   = v1;
        base[(size_t)(row0+8)*DH + cc]   = v2;
        base[(size_t)(row0+8)*DH + cc+1] = v3;
    }
}

// =====================================================================
// shared LUT builders
// =====================================================================
__device__ __forceinline__ void build_node_lut(int* s_nd, int tid){
    if (tid < 15){
        int l = (tid<8)?0:(tid<12)?1:(tid<14)?2:3;
        int n = tid - Knoff(l);
        int bs = 4<<l, r = (l==0)?4:8;
        s_nd[tid*5+0]=bs; s_nd[tid*5+1]=r; s_nd[tid*5+2]=Knro(l)+n*r;
        s_nd[tid*5+3]=2*bs*n; s_nd[tid*5+4]=Kbso(l);
    }
}
__device__ __forceinline__ void build_ws_lut(int* s_lutAB, int tid, int nthr){
    for (int m = tid; m < 576; m += nthr){
        int l = (m<128)?0:(m<384)?1:(m<512)?2:3;
        int r = (l==0)?4:8;
        int rem = m - Kwso(l);
        int rr2 = r*r;
        int n = rem / rr2;
        int ij = rem - n*rr2;
        int i = ij / r, j = ij - i*r;
        int pb = Knro(l) + n*r;
        s_lutAB[m] = (pb+i) | ((pb+j)<<16);
    }
}
__device__ __forceinline__ void build_chunk_lut(int* s_ck, int tid){
    if (tid < 20){
        int c = tid, m, dd0=0, ext=0, ec=0;
        if (c < 13){ m = c; }
        else if (c == 13){ m=12; dd0=8; ext=1; ec=0; }
        else if (c == 14){ m=13; }
        else if (c == 15){ m=13; dd0=8; ext=1; ec=1; }
        else if (c == 16){ m=14; }
        else { m=14; dd0=8*(c-16); ext=1; ec=c-15; }
        s_ck[c] = m | (dd0<<8) | (ext<<16) | (ec<<20);
    }
}

// =====================================================================
// Pass 1: per-group (4 chunks) sums; prj transposed [16][PSTR]
// =====================================================================
#define P1_FLOATS (2176 + 2*16*PSTR + 928 + 1280)
#define P1_BYTES (P1_FLOATS*4 + (75+576+20)*4)
__global__ __launch_bounds__(512,2) void chunk_sum4_kernel(BasePtrs bp){
    extern __shared__ float sm[];
    float* s_k    = sm;
    float* s_v    = s_k + 16*KPAD;
    float* prjULT = s_v + 16*KPAD;       // [16 s][PSTR]
    float* prjVRT = prjULT + 16*PSTR;    // [16 s][PSTR]
    float* sUL    = prjVRT + 16*PSTR;
    float* sVR    = sUL + 464;
    float* extP   = sVR + 464;
    int*   s_nd   = (int*)(extP + 1280);
    int*   lutAB  = s_nd + 75;
    int*   s_ck   = lutAB + 576;

    const int tid = threadIdx.x;
    const int blk = blockIdx.x;
    const int b = blk / NGRP, grp = blk % NGRP;

    for (int i=tid;i<464;i+=NT){
        int l = (i<16)?0:(i<80)?1:(i<208)?2:3;
        int off = i - Kbso(l);
        sUL[i] = bp.p[l][off];
        sVR[i] = bp.p[4+l][off];
    }
    build_node_lut(s_nd, tid);
    build_ws_lut(lutAB, tid, NT);
    build_chunk_lut(s_ck, tid);
    __syncthreads();

    float sreg[2][4];

    for (int j=0;j<4;j++){
        const int c = grp*4 + j;
        const float* gk = g_k + ((size_t)b*TSEQ + c*CCH)*DH;
        const float* gv = g_v + ((size_t)b*TSEQ + c*CCH)*DH;
        if (tid < 512){
            int arr = tid>>8;
            int rem = tid & 255; int row = rem>>4, g = rem&15;
            const float* src = (arr==0?gk:gv) + row*64 + g*4;
            float* dst = (arr==0?s_k:s_v) + row*KPAD + g*4;
            *(float4*)dst = *(const float4*)src;
        }
        __syncthreads();

        if (tid < 320){
            int cd = s_ck[tid>>4]; int s = tid&15;
            int m = cd & 31, dd0 = (cd>>8)&63, isext=(cd>>16)&1, ec=(cd>>20)&7;
            int bs=s_nd[m*5], r=s_nd[m*5+1], pb=s_nd[m*5+2], topo=s_nd[m*5+3], bso=s_nd[m*5+4];
            const float* kt = s_k + s*KPAD + topo + dd0;
            const float* vb = s_v + s*KPAD + topo + bs + dd0;
            const float* Ub = sUL + bso + dd0*r;
            const float* Wb = sVR + bso + dd0*r;
            if (r == 4){
                float4 aU=make_float4(0,0,0,0), aV=aU;
#pragma unroll
                for (int d=0; d<4; d++){
                    float kd=kt[d], vd=vb[d];
                    float4 u=*(const float4*)(Ub+d*4), w=*(const float4*)(Wb+d*4);
                    fma4(aU,kd,u); fma4(aV,vd,w);
                }
                float au[4]={aU.x,aU.y,aU.z,aU.w}, avv[4]={aV.x,aV.y,aV.z,aV.w};
#pragma unroll
                for (int i=0;i<4;i++){
                    prjULT[s*PSTR + pb+i]=au[i];
                    prjVRT[s*PSTR + pb+i]=avv[i];
                }
            } else {
                float aU[8], aV[8];
#pragma unroll
                for (int i=0;i<8;i++){ aU[i]=0.f; aV[i]=0.f; }
#pragma unroll
                for (int d=0; d<8; d++){
                    float kd=kt[d], vd=vb[d];
                    float4 u0=*(const float4*)(Ub+d*8), u1=*(const float4*)(Ub+d*8+4);
                    float4 w0=*(const float4*)(Wb+d*8), w1=*(const float4*)(Wb+d*8+4);
                    aU[0]=fmaf(kd,u0.x,aU[0]); aU[1]=fmaf(kd,u0.y,aU[1]); aU[2]=fmaf(kd,u0.z,aU[2]); aU[3]=fmaf(kd,u0.w,aU[3]);
                    aU[4]=fmaf(kd,u1.x,aU[4]); aU[5]=fmaf(kd,u1.y,aU[5]); aU[6]=fmaf(kd,u1.z,aU[6]); aU[7]=fmaf(kd,u1.w,aU[7]);
                    aV[0]=fmaf(vd,w0.x,aV[0]); aV[1]=fmaf(vd,w0.y,aV[1]); aV[2]=fmaf(vd,w0.z,aV[2]); aV[3]=fmaf(vd,w0.w,aV[3]);
                    aV[4]=fmaf(vd,w1.x,aV[4]); aV[5]=fmaf(vd,w1.y,aV[5]); aV[6]=fmaf(vd,w1.z,aV[6]); aV[7]=fmaf(vd,w1.w,aV[7]);
                }
                if (!isext){
#pragma unroll
                    for (int i=0;i<8;i++){
                        prjULT[s*PSTR + pb+i]=aU[i];
                        prjVRT[s*PSTR + pb+i]=aV[i];
                    }
                } else {
#pragma unroll
                    for (int i=0;i<8;i++){
                        extP[((0*5+ec)*8+i)*16+s]=aU[i];
                        extP[((1*5+ec)*8+i)*16+s]=aV[i];
                    }
                }
            }
        }
        __syncthreads();
        if (tid < 256){
            int a=tid>>7, i=(tid>>4)&7, s=tid&15;
            float* base = prjULT + a*(16*PSTR);
            base[s*PSTR + 64+i] += extP[((a*5+0)*8+i)*16+s];
            base[s*PSTR + 72+i] += extP[((a*5+1)*8+i)*16+s];
            base[s*PSTR + 80+i] += extP[((a*5+2)*8+i)*16+s] + extP[((a*5+3)*8+i)*16+s] + extP[((a*5+4)*8+i)*16+s];
        }
        __syncthreads();

#pragma unroll
        for (int o=0;o<2;o++){
            int e = tid + o*512;
            if (e < NST){
                float acc = 0.f;
                if (e < 256){
                    int n=e>>4, i=(e>>2)&3, j2=e&3;
                    int ki=4*n+i, vi=4*n+j2;
#pragma unroll
                    for (int s=0;s<CCH;s++) acc = fmaf(s_k[s*KPAD+ki], s_v[s*KPAD+vi], acc);
                } else if (e < 832){
                    int m = e-256;
                    int ab = lutAB[m]; int a = ab & 0xffff, b3 = ab >> 16;
#pragma unroll
                    for (int s=0;s<16;s++)
                        acc = fmaf(prjULT[s*PSTR+a], prjVRT[s*PSTR+b3], acc);
                } else {
                    int d = e-832;
#pragma unroll
                    for (int s=0;s<CCH;s++) acc += s_k[s*KPAD+d];
                }
                sreg[o][j] = acc;
            }
        }
        __syncthreads();
    }

#pragma unroll
    for (int o=0;o<2;o++){
        int e = tid + o*512;
        if (e < NST){
            float run = 0.f;
#pragma unroll
            for (int j=0;j<4;j++){
                g_prefix[(size_t)(blk*4+j)*NST + e] = run;
                run += sreg[o][j];
            }
            g_gtot[(size_t)blk*NST + e] = run;
        }
    }
}

// =====================================================================
// Pass 2: exclusive prefix over 32 group totals per batch
// =====================================================================
__global__ __launch_bounds__(128) void midscan_kernel(){
    const int b = blockIdx.y;
    const int e = blockIdx.x*128 + threadIdx.x;
    const float* gt = g_gtot + (size_t)b*NGRP*NST + e;
    float*       go = g_goff + (size_t)b*NGRP*NST + e;
    float run = 0.f;
    for (int g0=0; g0<NGRP; g0+=8){
        float v[8];
#pragma unroll
        for (int j=0;j<8;j++) v[j] = gt[(size_t)(g0+j)*NST];
#pragma unroll
        for (int j=0;j<8;j++){ go[(size_t)(g0+j)*NST] = run; run += v[j]; }
    }
}

// =====================================================================
// Pass 3: fully parallel intra-chunk attention (unchanged from R9)
// =====================================================================
#define P3_FLOATS (3264 + 5632 + 1856 + 896 + 3840 + 3840 + 2560 + 256 + 16 + 1496 + 1496 + 1088)
#define P3_BYTES (P3_FLOATS*4 + (75 + 88*3 + 20)*4)
__global__ __launch_bounds__(512,2) void chunk_scan_kernel(BasePtrs bp){
    extern __shared__ float sm[];
    float* s_k    = sm;
    float* s_v    = s_k + 16*KPAD;
    float* s_q    = s_v + 16*KPAD;
    float* prjULT = s_q + 16*KPAD;
    float* prjVRT = prjULT + 1408;
    float* prjXT  = prjVRT + 1408;
    float* prjLT  = prjXT + 1408;
    float* sUL    = prjLT + 1408;
    float* sVR    = sUL + 464;
    float* sUR    = sVR + 464;
    float* sVL    = sUR + 464;
    float* s_leaf = sVL + 464;
    float* s_Ws   = s_leaf + 256;
    float* s_z    = s_Ws + 576;
    float* Asc    = s_z + 64;          // [16 s][240 col]
    float* Bsc    = Asc + 3840;
    float* extP   = Bsc + 3840;
    float* Dsc    = extP + 2560;
    float* s_den  = Dsc + 256;
    float* TT     = s_den + 16;
    float* TBB    = TT + 1496;
    float* yl     = TBB + 1496;
    int*   s_nd   = (int*)(yl + 1088);
    int*   lutP   = s_nd + 75;
    int*   lutWT  = lutP + 88;
    int*   lutWB  = lutWT + 88;
    int*   s_ck   = lutWB + 88;

    const int tid = threadIdx.x;
    const int blk = blockIdx.x;
    const int b = blk / (NCH/2), cp = blk % (NCH/2);

    for (int i=tid;i<464;i+=NT){
        int l = (i<16)?0:(i<80)?1:(i<208)?2:3;
        int off = i - Kbso(l);
        sUL[i] = bp.p[l   ][off];
        sVR[i] = bp.p[4+l ][off];
        sUR[i] = bp.p[8+l ][off];
        sVL[i] = bp.p[12+l][off];
    }
    build_node_lut(s_nd, tid);
    build_chunk_lut(s_ck, tid);
    if (tid < 88){
        int i88 = tid;
        int l = (i88<32)?0:(i88<64)?1:(i88<80)?2:3;
        int r = (l==0)?4:8;
        int rem = i88 - Knro(l);
        int n = rem / r, i = rem - n*r;
        int pb = Knro(l) + n*r;
        int ng = Knoff(l) + n;
        lutP[i88]  = pb | (ng<<8) | (r<<16);
        lutWT[i88] = Kwso(l) + n*r*r + i*r;
        lutWB[i88] = Kwso(l) + n*r*r + i;
    }

    for (int cc=0; cc<2; cc++){
        const int c = cp*2 + cc;
        const int ci = b*NCH + c;
        const float* gk = g_k + ((size_t)b*TSEQ + c*CCH)*DH;
        const float* gv = g_v + ((size_t)b*TSEQ + c*CCH)*DH;
        const float* gq = g_q + ((size_t)b*TSEQ + c*CCH)*DH;
        __nv_bfloat16* g_oh = g_ah + ((size_t)b*TSEQ + c*CCH)*DH;
        __nv_bfloat16* g_ol = g_al + ((size_t)b*TSEQ + c*CCH)*DH;

        for (int i=tid;i<768;i+=NT){
            int arr = i>>8;
            int rem = i & 255; int row = rem>>4, g = rem&15;
            const float* src = (arr==0?gk:(arr==1?gv:gq)) + row*64 + g*4;
            float* dst = (arr==0?s_k:(arr==1?s_v:s_q)) + row*KPAD + g*4;
            *(float4*)dst = *(const float4*)src;
        }
        {
            const float* gp = g_prefix + (size_t)ci*NST;
            const float* gof = g_goff + ((size_t)(b*NGRP) + (c>>2))*NST;
            for (int e=tid;e<NST;e+=NT){
                float vle = gp[e] + gof[e];
                if (e<256) s_leaf[e]=vle;
                else if (e<832) s_Ws[e-256]=vle;
                else s_z[e-832]=vle;
            }
        }
        __syncthreads();

        if (tid < 320){
            int cd = s_ck[tid>>4]; int s = tid&15;
            int m = cd & 31, dd0 = (cd>>8)&63, isext=(cd>>16)&1, ec=(cd>>20)&7;
            int bs=s_nd[m*5], r=s_nd[m*5+1], pb=s_nd[m*5+2], topo=s_nd[m*5+3], bso=s_nd[m*5+4];
            const float* kt = s_k + s*KPAD + topo + dd0;
            const float* vb = s_v + s*KPAD + topo + bs + dd0;
            const float* qt = s_q + s*KPAD + topo + dd0;
            const float* qb = s_q + s*KPAD + topo + bs + dd0;
            const float* Ub = sUL + bso + dd0*r;
            const float* Wb = sVR + bso + dd0*r;
            const float* Xb = sVL + bso + dd0*r;
            if (r == 4){
                float4 aU=make_float4(0,0,0,0), aV=aU, aX=aU, aL=aU;
#pragma unroll
                for (int d=0; d<4; d++){
                    float kd=kt[d], vd=vb[d], qtd=qt[d], qbd=qb[d];
                    float4 u=*(const float4*)(Ub+d*4), w=*(const float4*)(Wb+d*4), x=*(const float4*)(Xb+d*4);
                    fma4(aU,kd,u); fma4(aV,vd,w); fma4(aX,qbd,w); fma4(aL,qtd,x);
                }
                float t0[4]={aU.x,aU.y,aU.z,aU.w}, t1[4]={aV.x,aV.y,aV.z,aV.w};
                float t2[4]={aX.x,aX.y,aX.z,aX.w}, t3[4]={aL.x,aL.y,aL.z,aL.w};
#pragma unroll
                for (int i=0;i<4;i++){
                    prjULT[(pb+i)*16+s]=t0[i];
                    prjVRT[(pb+i)*16+s]=t1[i];
                    prjXT [(pb+i)*16+s]=t2[i];
                    prjLT [(pb+i)*16+s]=t3[i];
                }
            } else {
                {
                    float aU[8], aV[8];
#pragma unroll
                    for (int i=0;i<8;i++){ aU[i]=0.f; aV[i]=0.f; }
#pragma unroll
                    for (int d=0; d<8; d++){
                        float kd=kt[d], vd=vb[d];
                        float4 u0=*(const float4*)(Ub+d*8), u1=*(const float4*)(Ub+d*8+4);
                        float4 w0=*(const float4*)(Wb+d*8), w1=*(const float4*)(Wb+d*8+4);
                        aU[0]=fmaf(kd,u0.x,aU[0]); aU[1]=fmaf(kd,u0.y,aU[1]); aU[2]=fmaf(kd,u0.z,aU[2]); aU[3]=fmaf(kd,u0.w,aU[3]);
                        aU[4]=fmaf(kd,u1.x,aU[4]); aU[5]=fmaf(kd,u1.y,aU[5]); aU[6]=fmaf(kd,u1.z,aU[6]); aU[7]=fmaf(kd,u1.w,aU[7]);
                        aV[0]=fmaf(vd,w0.x,aV[0]); aV[1]=fmaf(vd,w0.y,aV[1]); aV[2]=fmaf(vd,w0.z,aV[2]); aV[3]=fmaf(vd,w0.w,aV[3]);
                        aV[4]=fmaf(vd,w1.x,aV[4]); aV[5]=fmaf(vd,w1.y,aV[5]); aV[6]=fmaf(vd,w1.z,aV[6]); aV[7]=fmaf(vd,w1.w,aV[7]);
                    }
                    if (!isext){
#pragma unroll
                        for (int i=0;i<8;i++){ prjULT[(pb+i)*16+s]=aU[i]; prjVRT[(pb+i)*16+s]=aV[i]; }
                    } else {
#pragma unroll
                        for (int i=0;i<8;i++){
                            extP[((0*5+ec)*8+i)*16+s]=aU[i];
                            extP[((1*5+ec)*8+i)*16+s]=aV[i];
                        }
                    }
                }
                {
                    float aX[8], aL[8];
#pragma unroll
                    for (int i=0;i<8;i++){ aX[i]=0.f; aL[i]=0.f; }
#pragma unroll
                    for (int d=0; d<8; d++){
                        float qbd=qb[d], qtd=qt[d];
                        float4 w0=*(const float4*)(Wb+d*8), w1=*(const float4*)(Wb+d*8+4);
                        float4 x0=*(const float4*)(Xb+d*8), x1=*(const float4*)(Xb+d*8+4);
                        aX[0]=fmaf(qbd,w0.x,aX[0]); aX[1]=fmaf(qbd,w0.y,aX[1]); aX[2]=fmaf(qbd,w0.z,aX[2]); aX[3]=fmaf(qbd,w0.w,aX[3]);
                        aX[4]=fmaf(qbd,w1.x,aX[4]); aX[5]=fmaf(qbd,w1.y,aX[5]); aX[6]=fmaf(qbd,w1.z,aX[6]); aX[7]=fmaf(qbd,w1.w,aX[7]);
                        aL[0]=fmaf(qtd,x0.x,aL[0]); aL[1]=fmaf(qtd,x0.y,aL[1]); aL[2]=fmaf(qtd,x0.z,aL[2]); aL[3]=fmaf(qtd,x0.w,aL[3]);
                        aL[4]=fmaf(qtd,x1.x,aL[4]); aL[5]=fmaf(qtd,x1.y,aL[5]); aL[6]=fmaf(qtd,x1.z,aL[6]); aL[7]=fmaf(qtd,x1.w,aL[7]);
                    }
                    if (!isext){
#pragma unroll
                        for (int i=0;i<8;i++){ prjXT[(pb+i)*16+s]=aX[i]; prjLT[(pb+i)*16+s]=aL[i]; }
                    } else {
#pragma unroll
                        for (int i=0;i<8;i++){
                            extP[((2*5+ec)*8+i)*16+s]=aX[i];
                            extP[((3*5+ec)*8+i)*16+s]=aL[i];
                        }
                    }
                }
            }
        } else {
            int j = tid - 320;
#pragma unroll
            for (int rep=0; rep<2; rep++){
                if (j < 256){
                    int t = j>>4, s = j&15;
                    float acc = 0.f;
#pragma unroll
                    for (int g=0;g<16;g++)
                        acc += dot4v(*(const float4*)&s_k[s*KPAD+4*g], *(const float4*)&s_q[t*KPAD+4*g]);
                    Dsc[j] = acc;
                }
                j += 192;
            }
        }
        __syncthreads();
        {
            int a=tid>>7, i=(tid>>4)&7, s=tid&15;
            float* base = prjULT + a*1408;
            base[(64+i)*16+s] += extP[((a*5+0)*8+i)*16+s];
            base[(72+i)*16+s] += extP[((a*5+1)*8+i)*16+s];
            base[(80+i)*16+s] += extP[((a*5+2)*8+i)*16+s] + extP[((a*5+3)*8+i)*16+s] + extP[((a*5+4)*8+i)*16+s];
        }
        __syncthreads();

        for (int j=tid; j<752; j+=NT){
            if (j < 240){
                int ng = j>>4, t = j&15;
                int pb = s_nd[ng*5+2];
                float4 a0=make_float4(0,0,0,0), a1=a0, a2=a0, a3=a0;
                if (ng < 8){
#pragma unroll
                    for (int i=0;i<4;i++){
                        float w = prjXT[(pb+i)*16+t];
                        const float4* vr = (const float4*)&prjVRT[(pb+i)*16];
                        fma4(a0,w,vr[0]); fma4(a1,w,vr[1]); fma4(a2,w,vr[2]); fma4(a3,w,vr[3]);
                    }
                } else {
#pragma unroll
                    for (int i=0;i<8;i++){
                        float w = prjXT[(pb+i)*16+t];
                        const float4* vr = (const float4*)&prjVRT[(pb+i)*16];
                        fma4(a0,w,vr[0]); fma4(a1,w,vr[1]); fma4(a2,w,vr[2]); fma4(a3,w,vr[3]);
                    }
                }
                int col = ng*16 + t;
                Asc[ 0*240+col]=a0.x;            Asc[ 1*240+col]=(1<=t)?a0.y:0.f;
                Asc[ 2*240+col]=(2<=t)?a0.z:0.f; Asc[ 3*240+col]=(3<=t)?a0.w:0.f;
                Asc[ 4*240+col]=(4<=t)?a1.x:0.f; Asc[ 5*240+col]=(5<=t)?a1.y:0.f;
                Asc[ 6*240+col]=(6<=t)?a1.z:0.f; Asc[ 7*240+col]=(7<=t)?a1.w:0.f;
                Asc[ 8*240+col]=(8<=t)?a2.x:0.f; Asc[ 9*240+col]=(9<=t)?a2.y:0.f;
                Asc[10*240+col]=(10<=t)?a2.z:0.f; Asc[11*240+col]=(11<=t)?a2.w:0.f;
                Asc[12*240+col]=(12<=t)?a3.x:0.f; Asc[13*240+col]=(13<=t)?a3.y:0.f;
                Asc[14*240+col]=(14<=t)?a3.z:0.f; Asc[15*240+col]=(15<=t)?a3.w:0.f;
            } else if (j < 480){
                int jj = j-240;
                int ng = jj>>4, t = jj&15;
                int pb = s_nd[ng*5+2];
                float4 a0=make_float4(0,0,0,0), a1=a0, a2=a0, a3=a0;
                if (ng < 8){
#pragma unroll
                    for (int i=0;i<4;i++){
                        float w = prjLT[(pb+i)*16+t];
                        const float4* ul = (const float4*)&prjULT[(pb+i)*16];
                        fma4(a0,w,ul[0]); fma4(a1,w,ul[1]); fma4(a2,w,ul[2]); fma4(a3,w,ul[3]);
                    }
                } else {
#pragma unroll
                    for (int i=0;i<8;i++){
                        float w = prjLT[(pb+i)*16+t];
                        const float4* ul = (const float4*)&prjULT[(pb+i)*16];
                        fma4(a0,w,ul[0]); fma4(a1,w,ul[1]); fma4(a2,w,ul[2]); fma4(a3,w,ul[3]);
                    }
                }
                int col = ng*16 + t;
                Bsc[ 0*240+col]=a0.x;            Bsc[ 1*240+col]=(1<=t)?a0.y:0.f;
                Bsc[ 2*240+col]=(2<=t)?a0.z:0.f; Bsc[ 3*240+col]=(3<=t)?a0.w:0.f;
                Bsc[ 4*240+col]=(4<=t)?a1.x:0.f; Bsc[ 5*240+col]=(5<=t)?a1.y:0.f;
                Bsc[ 6*240+col]=(6<=t)?a1.z:0.f; Bsc[ 7*240+col]=(7<=t)?a1.w:0.f;
                Bsc[ 8*240+col]=(8<=t)?a2.x:0.f; Bsc[ 9*240+col]=(9<=t)?a2.y:0.f;
                Bsc[10*240+col]=(10<=t)?a2.z:0.f; Bsc[11*240+col]=(11<=t)?a2.w:0.f;
                Bsc[12*240+col]=(12<=t)?a3.x:0.f; Bsc[13*240+col]=(13<=t)?a3.y:0.f;
                Bsc[14*240+col]=(14<=t)?a3.z:0.f; Bsc[15*240+col]=(15<=t)?a3.w:0.f;
            } else if (j < 736){
                int jj = j-480;
                int n = jj>>4, t = jj&15;
                float4 qv = *(const float4*)&s_q[t*KPAD+4*n];
                float cvals[16];
#pragma unroll
                for (int s=0;s<16;s++){
                    float val = dot4v(*(const float4*)&s_v[s*KPAD+4*n], qv);
                    cvals[s] = (s<=t)? val : 0.f;
                }
                float acc0 = dot4v(*(const float4*)&s_leaf[(4*n+0)*4], qv);
                float acc1 = dot4v(*(const float4*)&s_leaf[(4*n+1)*4], qv);
                float acc2 = dot4v(*(const float4*)&s_leaf[(4*n+2)*4], qv);
                float acc3 = dot4v(*(const float4*)&s_leaf[(4*n+3)*4], qv);
#pragma unroll
                for (int s=0;s<16;s++){
                    float4 kv = *(const float4*)&s_k[s*KPAD+4*n];
                    float cs = cvals[s];
                    acc0 = fmaf(kv.x, cs, acc0);
                    acc1 = fmaf(kv.y, cs, acc1);
                    acc2 = fmaf(kv.z, cs, acc2);
                    acc3 = fmaf(kv.w, cs, acc3);
                }
                yl[(4*n+0)*17+t] = acc0;
                yl[(4*n+1)*17+t] = acc1;
                yl[(4*n+2)*17+t] = acc2;
                yl[(4*n+3)*17+t] = acc3;
            } else {
                int t = j-736;
                float acc = 0.f;
#pragma unroll
                for (int g=0;g<16;g++)
                    acc += dot4v(*(const float4*)&s_z[4*g], *(const float4*)&s_q[t*KPAD+4*g]);
                for (int s=0;s<=t;s++) acc += Dsc[t*16+s];
                s_den[t] = fmaxf(acc, 1e-6f);
            }
        }
        __syncthreads();

        for (int j=tid; j<2816; j+=NT){
            if (j < 1408){
                int i88 = j>>4, t = j&15;
                int info = lutP[i88]; int pb = info&255, ng=(info>>8)&255;
                float acc = 0.f;
                int wr = lutWT[i88];
                if (i88 < 32){
#pragma unroll
                    for (int u=0;u<4;u++) acc = fmaf(s_Ws[wr+u], prjXT[(pb+u)*16+t], acc);
                } else {
#pragma unroll
                    for (int u=0;u<8;u++) acc = fmaf(s_Ws[wr+u], prjXT[(pb+u)*16+t], acc);
                }
                const float4* uu4 = (const float4*)&prjULT[i88*16];
                float4 u0=uu4[0], u1=uu4[1], u2=uu4[2], u3=uu4[3];
                const int col = ng*16 + t;
                acc = fmaf(u0.x, Asc[ 0*240+col], acc);
                acc = fmaf(u0.y, Asc[ 1*240+col], acc);
                acc = fmaf(u0.z, Asc[ 2*240+col], acc);
                acc = fmaf(u0.w, Asc[ 3*240+col], acc);
                acc = fmaf(u1.x, Asc[ 4*240+col], acc);
                acc = fmaf(u1.y, Asc[ 5*240+col], acc);
                acc = fmaf(u1.z, Asc[ 6*240+col], acc);
                acc = fmaf(u1.w, Asc[ 7*240+col], acc);
                acc = fmaf(u2.x, Asc[ 8*240+col], acc);
                acc = fmaf(u2.y, Asc[ 9*240+col], acc);
                acc = fmaf(u2.z, Asc[10*240+col], acc);
                acc = fmaf(u2.w, Asc[11*240+col], acc);
                acc = fmaf(u3.x, Asc[12*240+col], acc);
                acc = fmaf(u3.y, Asc[13*240+col], acc);
                acc = fmaf(u3.z, Asc[14*240+col], acc);
                acc = fmaf(u3.w, Asc[15*240+col], acc);
                TT[i88*17+t] = acc;
            } else {
                int jj = j-1408;
                int i88 = jj>>4, t = jj&15;
                int info = lutP[i88]; int pb = info&255, ng=(info>>8)&255;
                float acc = 0.f;
                int wc = lutWB[i88];
                if (i88 < 32){
#pragma unroll
                    for (int u=0;u<4;u++) acc = fmaf(s_Ws[wc+u*4], prjLT[(pb+u)*16+t], acc);
                } else {
#pragma unroll
                    for (int u=0;u<8;u++) acc = fmaf(s_Ws[wc+u*8], prjLT[(pb+u)*16+t], acc);
                }
                const float4* vv4 = (const float4*)&prjVRT[i88*16];
                float4 v0=vv4[0], v1=vv4[1], v2=vv4[2], v3=vv4[3];
                const int col = ng*16 + t;
                acc = fmaf(v0.x, Bsc[ 0*240+col], acc);
                acc = fmaf(v0.y, Bsc[ 1*240+col], acc);
                acc = fmaf(v0.z, Bsc[ 2*240+col], acc);
                acc = fmaf(v0.w, Bsc[ 3*240+col], acc);
                acc = fmaf(v1.x, Bsc[ 4*240+col], acc);
                acc = fmaf(v1.y, Bsc[ 5*240+col], acc);
                acc = fmaf(v1.z, Bsc[ 6*240+col], acc);
                acc = fmaf(v1.w, Bsc[ 7*240+col], acc);
                acc = fmaf(v2.x, Bsc[ 8*240+col], acc);
                acc = fmaf(v2.y, Bsc[ 9*240+col], acc);
                acc = fmaf(v2.z, Bsc[10*240+col], acc);
                acc = fmaf(v2.w, Bsc[11*240+col], acc);
                acc = fmaf(v3.x, Bsc[12*240+col], acc);
                acc = fmaf(v3.y, Bsc[13*240+col], acc);
                acc = fmaf(v3.z, Bsc[14*240+col], acc);
                acc = fmaf(v3.w, Bsc[15*240+col], acc);
                TBB[i88*17+t] = acc;
            }
        }
        __syncthreads();

        for (int j=tid; j<1024; j+=NT){
            int d = j&63, t = j>>6;
            float y = yl[d*17+t];
#pragma unroll
            for (int l=0;l<4;l++){
                const int bs = 4<<l;
                const int r  = (l==0)?4:8;
                const int n = d >> (3+l);
                const int loc = d & (2*bs - 1);
                const int pb = Knro(l) + n*r;
                const int bso = Kbso(l);
                if (loc < bs){
                    const float* u = sUL + bso + loc*r;
#pragma unroll
                    for (int i=0;i<8;i++){
                        if (i < r) y = fmaf(u[i], TT[(pb+i)*17+t], y);
                    }
                } else {
                    const float* u = sUR + bso + (loc-bs)*r;
#pragma unroll
                    for (int i=0;i<8;i++){
                        if (i < r) y = fmaf(u[i], TBB[(pb+i)*17+t], y);
                    }
                }
            }
            float o = y / s_den[t];
            __nv_bfloat16 h = __float2bfloat16(o);
            g_oh[(size_t)t*DH + d] = h;
            g_ol[(size_t)t*DH + d] = __float2bfloat16(o - __bfloat162float(h));
        }
    }
}

// ---------------- output GEMM via mma.sync bf16x3 ----------------
#define WA 72
#define WB 136
#define WO_BYTES ((128*WA*2 + 64*WB*2)*2)
__global__ __launch_bounds__(256) void wo_mma_kernel(float* __restrict__ out){
    extern __shared__ __nv_bfloat16 ws[];
    __nv_bfloat16* sAh = ws;
    __nv_bfloat16* sAl = sAh + 128*WA;
    __nv_bfloat16* sBh = sAl + 128*WA;
    __nv_bfloat16* sBl = sBh + 64*WB;

    const int tid = threadIdx.x;
    const int wid = tid >> 5, lane = tid & 31;
    const int wy = wid & 3, wx = wid >> 2;
    const int rb = blockIdx.x * 128, cb = blockIdx.y * 128;

#pragma unroll
    for (int i=0;i<4;i++){
        int idx = tid + i*256;
        int row = idx >> 3, c8 = idx & 7;
        cp_async16(sAh + row*WA + c8*8, g_ah + (size_t)(rb+row)*DH + c8*8);
        cp_async16(sAl + row*WA + c8*8, g_al + (size_t)(rb+row)*DH + c8*8);
    }
#pragma unroll
    for (int i=0;i<4;i++){
        int idx = tid + i*256;
        int k = idx >> 4, c16 = idx & 15;
        cp_async16(sBh + k*WB + c16*8, g_woh + (size_t)k*DM + cb + c16*8);
        cp_async16(sBl + k*WB + c16*8, g_wol + (size_t)k*DM + cb + c16*8);
    }
    asm volatile("cp.async.commit_group;\n");
    asm volatile("cp.async.wait_group 0;\n");
    __syncthreads();

    float acc[2][8][4];
#pragma unroll
    for (int m=0;m<2;m++)
#pragma unroll
        for (int n=0;n<8;n++){ acc[m][n][0]=acc[m][n][1]=acc[m][n][2]=acc[m][n][3]=0.f; }

#pragma unroll
    for (int k0=0;k0<64;k0+=16){
        unsigned ah[2][4], al[2][4];
#pragma unroll
        for (int mt=0;mt<2;mt++){
            const __nv_bfloat16* ap = sAh + (wy*32 + mt*16 + (lane&15))*WA + k0 + (lane>>4)*8;
            ldmx4(ah[mt][0],ah[mt][1],ah[mt][2],ah[mt][3], ap);
            const __nv_bfloat16* ap2 = sAl + (wy*32 + mt*16 + (lane&15))*WA + k0 + (lane>>4)*8;
            ldmx4(al[mt][0],al[mt][1],al[mt][2],al[mt][3], ap2);
        }
#pragma unroll
        for (int nt=0;nt<4;nt++){
            unsigned bh0,bh1,bh2,bh3, bl0,bl1,bl2,bl3;
            const __nv_bfloat16* bp = sBh + (k0 + (lane&15))*WB + wx*64 + nt*16 + (lane>>4)*8;
            ldmx4t(bh0,bh1,bh2,bh3, bp);
            const __nv_bfloat16* bp2 = sBl + (k0 + (lane&15))*WB + wx*64 + nt*16 + (lane>>4)*8;
            ldmx4t(bl0,bl1,bl2,bl3, bp2);
#pragma unroll
            for (int mt=0;mt<2;mt++){
                mma16816(acc[mt][2*nt],   ah[mt][0],ah[mt][1],ah[mt][2],ah[mt][3], bh0,bh1);
                mma16816(acc[mt][2*nt],   ah[mt][0],ah[mt][1],ah[mt][2],ah[mt][3], bl0,bl1);
                mma16816(acc[mt][2*nt],   al[mt][0],al[mt][1],al[mt][2],al[mt][3], bh0,bh1);
                mma16816(acc[mt][2*nt+1], ah[mt][0],ah[mt][1],ah[mt][2],ah[mt][3], bh2,bh3);
                mma16816(acc[mt][2*nt+1], ah[mt][0],ah[mt][1],ah[mt][2],ah[mt][3], bl2,bl3);
                mma16816(acc[mt][2*nt+1], al[mt][0],al[mt][1],al[mt][2],al[mt][3], bh2,bh3);
            }
        }
    }

#pragma unroll
    for (int mt=0;mt<2;mt++){
        int row = rb + wy*32 + mt*16 + (lane>>2);
#pragma unroll
        for (int nt=0;nt<8;nt++){
            int col = cb + wx*64 + nt*8 + (lane&3)*2;
            *(float2*)(out + (size_t)row*DM + col)     = make_float2(acc[mt][nt][0], acc[mt][nt][1]);
            *(float2*)(out + (size_t)(row+8)*DM + col) = make_float2(acc[mt][nt][2], acc[mt][nt][3]);
        }
    }
}

extern "C" void kernel_launch(void* const* d_in, const int* in_sizes, int n_in,
                              void* d_out, int out_size){
    (void)in_sizes; (void)n_in; (void)out_size;
    const float* x  = (const float*)d_in[0];
    const float* Wq = (const float*)d_in[1];
    const float* Wk = (const float*)d_in[2];
    const float* Wv = (const float*)d_in[3];
    const float* Wo = (const float*)d_in[4];
    BasePtrs bp;
    for(int i=0;i<16;i++) bp.p[i] = (const float*)d_in[5+i];
    float* out = (float*)d_out;

    cudaFuncSetAttribute(chunk_sum4_kernel, cudaFuncAttributeMaxDynamicSharedMemorySize, P1_BYTES);
    cudaFuncSetAttribute(chunk_scan_kernel, cudaFuncAttributeMaxDynamicSharedMemorySize, P3_BYTES);
    cudaFuncSetAttribute(wo_mma_kernel,     cudaFuncAttributeMaxDynamicSharedMemorySize, WO_BYTES);

    wprep_kernel<<<(DM*NW + DH*DM)/256, 256>>>(Wq, Wk, Wv, Wo);
    qkv_mma_kernel<<<NTOK/64, 256>>>(x);
    chunk_sum4_kernel<<<BB*NGRP, NT, P1_BYTES>>>(bp);
    midscan_kernel<<<dim3(NST/128, BB), 128>>>();
    chunk_scan_kernel<<<BB*NCH/2, NT, P3_BYTES>>>(bp);
    wo_mma_kernel<<<dim3(NTOK/128, DM/128), 256, WO_BYTES>>>(out);
}